// round 3
// baseline (speedup 1.0000x reference)
#include <cuda_runtime.h>
#include <math.h>

// ---------------- problem constants ----------------
#define NRR 20000
#define NCC 5000
#define ERR 320000
#define ECC 80000
#define DIN 6
#define HID 128
#define KNN 3
#define NEG 0.2f

#define CHUNK 2048
#define NCH 10          // ceil(NRR / CHUNK)
#define CTILES 40       // ceil(NCC / 128)

// ---------------- static scratch (device globals; no allocation) ----------------
__device__ float g_hw_r[NRR * HID];
__device__ float g_h1_r[NRR * HID];
__device__ float g_h2_r[NRR * HID];
__device__ float g_hw_c[NCC * HID];
__device__ float g_h1_c[NCC * HID];
__device__ float g_h2_c[NCC * HID];
__device__ float g_es[NRR];
__device__ float g_ed[NRR];
__device__ float g_mm[NRR];
__device__ float g_dn[NRR];
__device__ int   g_cnt_r[NRR];
__device__ int   g_cur_r[NRR];
__device__ int   g_rp_r[NRR + 1];
__device__ int   g_col_r[ERR + NRR];
__device__ int   g_cnt_c[NCC];
__device__ int   g_cur_c[NCC];
__device__ int   g_rp_c[NCC + 1];
__device__ int   g_col_c[ECC + NCC];
__device__ float g_nr2[NRR];
__device__ float g_pv[NCC * NCH * 3];    // partial top-3 values per chunk
__device__ int   g_pi[NCC * NCH * 3];    // partial top-3 indices per chunk
__device__ int   g_nn[NCC * KNN];
__device__ float g_pool[NRR * HID];
__device__ int   g_pcnt[NRR];

// ---------------- init / zero ----------------
__global__ void k_init() {
    int i = blockIdx.x * blockDim.x + threadIdx.x;
    int st = gridDim.x * blockDim.x;
    for (int t = i; t < NRR * HID; t += st) g_pool[t] = 0.f;
    for (int t = i; t < NRR; t += st) { g_cnt_r[t] = 1; g_cur_r[t] = 0; g_pcnt[t] = 0; }
    for (int t = i; t < NCC; t += st) { g_cnt_c[t] = 1; g_cur_c[t] = 0; }
}

// ---------------- CSR build ----------------
__global__ void k_count(const int* __restrict__ dst, int E, int* __restrict__ cnt) {
    int i = blockIdx.x * blockDim.x + threadIdx.x;
    if (i < E) atomicAdd(&cnt[dst[i]], 1);
}

__global__ void k_scan(const int* __restrict__ cnt, int* __restrict__ rp, int n) {
    __shared__ int part[1024];
    int t = threadIdx.x;
    int chunk = (n + 1023) / 1024;
    int beg = t * chunk;
    int end = min(n, beg + chunk);
    int s = 0;
    for (int i = beg; i < end; i++) s += cnt[i];
    part[t] = s;
    __syncthreads();
    for (int off = 1; off < 1024; off <<= 1) {
        int v = (t >= off) ? part[t - off] : 0;
        __syncthreads();
        part[t] += v;
        __syncthreads();
    }
    int run = part[t] - s;
    for (int i = beg; i < end; i++) { rp[i] = run; run += cnt[i]; }
    if (t == 1023) rp[n] = part[1023];
}

__global__ void k_scatter(const int* __restrict__ src, const int* __restrict__ dst, int E,
                          const int* __restrict__ rp, int* __restrict__ cur,
                          int* __restrict__ colarr) {
    int i = blockIdx.x * blockDim.x + threadIdx.x;
    if (i < E) {
        int d = dst[i];
        int pos = rp[d] + atomicAdd(&cur[d], 1);
        colarr[pos] = src[i];
    }
}

__global__ void k_selfloop(const int* __restrict__ rp, int* __restrict__ colarr, int n) {
    int i = blockIdx.x * blockDim.x + threadIdx.x;
    if (i < n) colarr[rp[i + 1] - 1] = i;
}

// ---------------- GAT linear layers ----------------
__global__ void k_lin1(const float* __restrict__ x, const float* __restrict__ W,
                       const float* __restrict__ as_, const float* __restrict__ ad_,
                       float* __restrict__ h, float* __restrict__ es, float* __restrict__ ed,
                       int n) {
    int w = (blockIdx.x * blockDim.x + threadIdx.x) >> 5;
    int lane = threadIdx.x & 31;
    if (w >= n) return;
    float xv[DIN];
#pragma unroll
    for (int k = 0; k < DIN; k++) xv[k] = x[w * DIN + k];
    float hv[4], ps = 0.f, pd = 0.f;
#pragma unroll
    for (int q = 0; q < 4; q++) {
        int j = lane * 4 + q;
        float a = 0.f;
#pragma unroll
        for (int k = 0; k < DIN; k++) a = fmaf(xv[k], W[k * HID + j], a);
        hv[q] = a;
        ps = fmaf(a, as_[j], ps);
        pd = fmaf(a, ad_[j], pd);
    }
    *(float4*)&h[(size_t)w * HID + lane * 4] = make_float4(hv[0], hv[1], hv[2], hv[3]);
#pragma unroll
    for (int o = 16; o > 0; o >>= 1) {
        ps += __shfl_xor_sync(0xffffffffu, ps, o);
        pd += __shfl_xor_sync(0xffffffffu, pd, o);
    }
    if (lane == 0) { es[w] = ps; ed[w] = pd; }
}

// layer 2 GEMM: C(M x 128) = A(M x 128) @ B(128 x 128)
__global__ void __launch_bounds__(256) k_gemm128(const float* __restrict__ A,
                                                 const float* __restrict__ B,
                                                 float* __restrict__ C, int M) {
    __shared__ float As[16][64];
    __shared__ float Bs[16][128];
    int tid = threadIdx.x;
    int tc = tid & 31;
    int tr = tid >> 5;
    int row0 = blockIdx.x * 64;
    float acc[8][4];
#pragma unroll
    for (int i = 0; i < 8; i++)
#pragma unroll
        for (int j = 0; j < 4; j++) acc[i][j] = 0.f;

    for (int k0 = 0; k0 < HID; k0 += 16) {
        int row_l = tid >> 2, quad = tid & 3;
        int gr = row0 + row_l;
        float4 av = make_float4(0.f, 0.f, 0.f, 0.f);
        if (gr < M) av = *(const float4*)&A[(size_t)gr * HID + k0 + quad * 4];
        As[quad * 4 + 0][row_l] = av.x;
        As[quad * 4 + 1][row_l] = av.y;
        As[quad * 4 + 2][row_l] = av.z;
        As[quad * 4 + 3][row_l] = av.w;
        int kk = tid >> 4, cp = tid & 15;
        float4 bv0 = *(const float4*)&B[(size_t)(k0 + kk) * HID + cp * 8];
        float4 bv1 = *(const float4*)&B[(size_t)(k0 + kk) * HID + cp * 8 + 4];
        *(float4*)&Bs[kk][cp * 8] = bv0;
        *(float4*)&Bs[kk][cp * 8 + 4] = bv1;
        __syncthreads();
#pragma unroll
        for (int k2 = 0; k2 < 16; k2++) {
            float4 a0 = *(float4*)&As[k2][tr * 8];
            float4 a1 = *(float4*)&As[k2][tr * 8 + 4];
            float4 bb = *(float4*)&Bs[k2][tc * 4];
            float a[8] = {a0.x, a0.y, a0.z, a0.w, a1.x, a1.y, a1.z, a1.w};
            float b[4] = {bb.x, bb.y, bb.z, bb.w};
#pragma unroll
            for (int i = 0; i < 8; i++)
#pragma unroll
                for (int j = 0; j < 4; j++) acc[i][j] = fmaf(a[i], b[j], acc[i][j]);
        }
        __syncthreads();
    }
#pragma unroll
    for (int i = 0; i < 8; i++) {
        int r = row0 + tr * 8 + i;
        if (r < M)
            *(float4*)&C[(size_t)r * HID + tc * 4] =
                make_float4(acc[i][0], acc[i][1], acc[i][2], acc[i][3]);
    }
}

__global__ void k_dots(const float* __restrict__ h, const float* __restrict__ as_,
                       const float* __restrict__ ad_, float* __restrict__ es,
                       float* __restrict__ ed, int n) {
    int w = (blockIdx.x * blockDim.x + threadIdx.x) >> 5;
    int lane = threadIdx.x & 31;
    if (w >= n) return;
    const float* hr = &h[(size_t)w * HID];
    float ps = 0.f, pd = 0.f;
#pragma unroll
    for (int t = 0; t < 4; t++) {
        int j = lane + 32 * t;
        float v = hr[j];
        ps = fmaf(v, as_[j], ps);
        pd = fmaf(v, ad_[j], pd);
    }
#pragma unroll
    for (int o = 16; o > 0; o >>= 1) {
        ps += __shfl_xor_sync(0xffffffffu, ps, o);
        pd += __shfl_xor_sync(0xffffffffu, pd, o);
    }
    if (lane == 0) { es[w] = ps; ed[w] = pd; }
}

// ---------------- segment softmax stats ----------------
__global__ void k_stats(const int* __restrict__ rp, const int* __restrict__ col,
                        const float* __restrict__ es, const float* __restrict__ edv,
                        float* __restrict__ mv, float* __restrict__ dnv, int n) {
    int w = (blockIdx.x * blockDim.x + threadIdx.x) >> 5;
    int lane = threadIdx.x & 31;
    if (w >= n) return;
    int beg = rp[w], end = rp[w + 1];
    float ed = edv[w];
    float m = -1e30f, s = 0.f;
    for (int idx = beg + lane; idx < end; idx += 32) {
        float e = es[col[idx]] + ed;
        e = e > 0.f ? e : NEG * e;
        float mn = fmaxf(m, e);
        s = s * __expf(m - mn) + __expf(e - mn);
        m = mn;
    }
#pragma unroll
    for (int o = 16; o > 0; o >>= 1) {
        float m2 = __shfl_xor_sync(0xffffffffu, m, o);
        float s2 = __shfl_xor_sync(0xffffffffu, s, o);
        float mn = fmaxf(m, m2);
        s = s * __expf(m - mn) + s2 * __expf(m2 - mn);
        m = mn;
    }
    if (lane == 0) { mv[w] = m; dnv[w] = s; }
}

// ---------------- attention-weighted aggregation ----------------
__global__ void k_agg(const int* __restrict__ rp, const int* __restrict__ col,
                      const float* __restrict__ hW, const float* __restrict__ es,
                      const float* __restrict__ edv, const float* __restrict__ mv,
                      const float* __restrict__ dnv, const float* __restrict__ bias,
                      float* __restrict__ out, int n) {
    int w = (blockIdx.x * blockDim.x + threadIdx.x) >> 5;
    int lane = threadIdx.x & 31;
    if (w >= n) return;
    int beg = rp[w], end = rp[w + 1];
    float ed = edv[w], md = mv[w];
    float inv = 1.f / fmaxf(dnv[w], 1e-16f);
    float a0 = 0.f, a1 = 0.f, a2 = 0.f, a3 = 0.f;
    for (int idx = beg; idx < end; idx++) {
        int s = col[idx];
        float e = es[s] + ed;
        e = e > 0.f ? e : NEG * e;
        float wgt = __expf(e - md) * inv;
        const float* hr = &hW[(size_t)s * HID];
        a0 = fmaf(wgt, hr[lane], a0);
        a1 = fmaf(wgt, hr[lane + 32], a1);
        a2 = fmaf(wgt, hr[lane + 64], a2);
        a3 = fmaf(wgt, hr[lane + 96], a3);
    }
    out[(size_t)w * HID + lane]      = fmaxf(a0 + bias[lane], 0.f);
    out[(size_t)w * HID + lane + 32] = fmaxf(a1 + bias[lane + 32], 0.f);
    out[(size_t)w * HID + lane + 64] = fmaxf(a2 + bias[lane + 64], 0.f);
    out[(size_t)w * HID + lane + 96] = fmaxf(a3 + bias[lane + 96], 0.f);
}

// ---------------- row norms (resting only) ----------------
__global__ void k_norm(const float* __restrict__ h, float* __restrict__ nrm, int n) {
    int w = (blockIdx.x * blockDim.x + threadIdx.x) >> 5;
    int lane = threadIdx.x & 31;
    if (w >= n) return;
    const float* hr = &h[(size_t)w * HID];
    float s = 0.f;
#pragma unroll
    for (int t = 0; t < 4; t++) { float v = hr[lane + 32 * t]; s = fmaf(v, v, s); }
#pragma unroll
    for (int o = 16; o > 0; o >>= 1) s += __shfl_xor_sync(0xffffffffu, s, o);
    if (lane == 0) nrm[w] = s;
}

// ---------------- top-3 ordering helper (ties -> lower index, = lax.top_k) ----------------
__device__ __forceinline__ bool d2_less(float v1, int i1, float v2, int i2) {
    return (v1 < v2) || (v1 == v2 && i1 < i2);
}

__device__ __forceinline__ void top3_upd(float v, int r, float tv[3], int ti[3]) {
    if (d2_less(v, r, tv[2], ti[2])) {
        tv[2] = v; ti[2] = r;
        if (d2_less(tv[2], ti[2], tv[1], ti[1])) {
            float a = tv[1]; int b = ti[1]; tv[1] = tv[2]; ti[1] = ti[2]; tv[2] = a; ti[2] = b;
        }
        if (d2_less(tv[1], ti[1], tv[0], ti[0])) {
            float a = tv[0]; int b = ti[0]; tv[0] = tv[1]; ti[0] = ti[1]; tv[1] = a; ti[1] = b;
        }
    }
}

// ---------------- fused KNN GEMM (scalar FFMA, R1 core) + per-chunk top-3 ----------------
// rank key = nr2[r] - 2*dot(c,r) (the per-row-constant nc2[c] cannot change the argmin)
// block = 128 colliders (blockIdx.x) x one resting chunk of 2048 (blockIdx.y)
__global__ void __launch_bounds__(256) k_knn_top3(const float* __restrict__ A,   // h2_c
                                                  const float* __restrict__ B,   // h2_r
                                                  const float* __restrict__ nr2) {
    __shared__ __align__(16) union ShU {
        struct { float As[16][128]; float Bs[16][128]; } g;
        struct { float mv[128][48]; int mi[128][48]; } m;
    } sh;
    __shared__ float Nr[128];

    int tid = threadIdx.x;
    int tx = tid & 15, ty = tid >> 4;
    int cb = blockIdx.x * 128;
    int rbeg = blockIdx.y * CHUNK;
    int rend = min(NRR, rbeg + CHUNK);

    float tv[8][3];
    int   ti[8][3];
#pragma unroll
    for (int i = 0; i < 8; i++)
#pragma unroll
        for (int k = 0; k < 3; k++) { tv[i][k] = 1e30f; ti[i][k] = 0x7fffffff; }

    int rl = tid >> 1, kq = tid & 1;
    int gc = cb + rl;

    for (int rt = rbeg; rt < rend; rt += 128) {
        float acc[8][8];
#pragma unroll
        for (int i = 0; i < 8; i++)
#pragma unroll
            for (int j = 0; j < 8; j++) acc[i][j] = 0.f;

        int gr = rt + rl;
#pragma unroll
        for (int k0 = 0; k0 < HID; k0 += 16) {
            // stage collider slice (transposed [k][row])
            float4 v0 = make_float4(0.f, 0.f, 0.f, 0.f), v1 = v0;
            if (gc < NCC) {
                v0 = *(const float4*)&A[(size_t)gc * HID + k0 + kq * 8];
                v1 = *(const float4*)&A[(size_t)gc * HID + k0 + kq * 8 + 4];
            }
            sh.g.As[kq * 8 + 0][rl] = v0.x; sh.g.As[kq * 8 + 1][rl] = v0.y;
            sh.g.As[kq * 8 + 2][rl] = v0.z; sh.g.As[kq * 8 + 3][rl] = v0.w;
            sh.g.As[kq * 8 + 4][rl] = v1.x; sh.g.As[kq * 8 + 5][rl] = v1.y;
            sh.g.As[kq * 8 + 6][rl] = v1.z; sh.g.As[kq * 8 + 7][rl] = v1.w;
            // stage resting slice (transposed [k][row])
            float4 w0 = make_float4(0.f, 0.f, 0.f, 0.f), w1 = w0;
            if (gr < NRR) {
                w0 = *(const float4*)&B[(size_t)gr * HID + k0 + kq * 8];
                w1 = *(const float4*)&B[(size_t)gr * HID + k0 + kq * 8 + 4];
            }
            sh.g.Bs[kq * 8 + 0][rl] = w0.x; sh.g.Bs[kq * 8 + 1][rl] = w0.y;
            sh.g.Bs[kq * 8 + 2][rl] = w0.z; sh.g.Bs[kq * 8 + 3][rl] = w0.w;
            sh.g.Bs[kq * 8 + 4][rl] = w1.x; sh.g.Bs[kq * 8 + 5][rl] = w1.y;
            sh.g.Bs[kq * 8 + 6][rl] = w1.z; sh.g.Bs[kq * 8 + 7][rl] = w1.w;
            if (k0 == 0 && kq == 0) Nr[rl] = (gr < NRR) ? nr2[gr] : 0.f;
            __syncthreads();
#pragma unroll
            for (int kk = 0; kk < 16; kk++) {
                float4 t0 = *(float4*)&sh.g.As[kk][ty * 8];
                float4 t1 = *(float4*)&sh.g.As[kk][ty * 8 + 4];
                float4 u0 = *(float4*)&sh.g.Bs[kk][tx * 8];
                float4 u1 = *(float4*)&sh.g.Bs[kk][tx * 8 + 4];
                float a[8] = {t0.x, t0.y, t0.z, t0.w, t1.x, t1.y, t1.z, t1.w};
                float b[8] = {u0.x, u0.y, u0.z, u0.w, u1.x, u1.y, u1.z, u1.w};
#pragma unroll
                for (int i = 0; i < 8; i++)
#pragma unroll
                    for (int j = 0; j < 8; j++) acc[i][j] = fmaf(a[i], b[j], acc[i][j]);
            }
            __syncthreads();
        }
        // epilogue: fold this resting tile into running top-3
#pragma unroll
        for (int i = 0; i < 8; i++) {
#pragma unroll
            for (int j = 0; j < 8; j++) {
                int rloc = tx * 8 + j;
                int r = rt + rloc;
                if (r < NRR) {
                    float val = Nr[rloc] - 2.f * acc[i][j];
                    top3_upd(val, r, tv[i], ti[i]);
                }
            }
        }
        __syncthreads();  // protect Nr/shared before next tile's stores
    }

    // merge across the 16 tx threads sharing each collider row
#pragma unroll
    for (int i = 0; i < 8; i++) {
        int row = ty * 8 + i;
#pragma unroll
        for (int k = 0; k < 3; k++) {
            sh.m.mv[row][tx * 3 + k] = tv[i][k];
            sh.m.mi[row][tx * 3 + k] = ti[i][k];
        }
    }
    __syncthreads();
    if (tid < 128) {
        int row = tid;
        float f[3] = {1e30f, 1e30f, 1e30f};
        int   j[3] = {0x7fffffff, 0x7fffffff, 0x7fffffff};
        for (int t = 0; t < 48; t++) {
            int r = sh.m.mi[row][t];
            if (r == 0x7fffffff) continue;
            top3_upd(sh.m.mv[row][t], r, f, j);
        }
        int c = cb + row;
        if (c < NCC) {
            int base = (c * NCH + blockIdx.y) * 3;
            g_pv[base + 0] = f[0]; g_pi[base + 0] = j[0];
            g_pv[base + 1] = f[1]; g_pi[base + 1] = j[1];
            g_pv[base + 2] = f[2]; g_pi[base + 2] = j[2];
        }
    }
}

// ---------------- final merge of per-chunk candidates ----------------
__global__ void k_merge() {
    int c = blockIdx.x * blockDim.x + threadIdx.x;
    if (c >= NCC) return;
    float f[3] = {1e30f, 1e30f, 1e30f};
    int   j[3] = {0x7fffffff, 0x7fffffff, 0x7fffffff};
    int base = c * NCH * 3;
    for (int t = 0; t < NCH * 3; t++) {
        int r = g_pi[base + t];
        if (r == 0x7fffffff) continue;
        top3_upd(g_pv[base + t], r, f, j);
    }
    g_nn[c * 3 + 0] = j[0];
    g_nn[c * 3 + 1] = j[1];
    g_nn[c * 3 + 2] = j[2];
}

// ---------------- scatter-mean pooling ----------------
__global__ void k_pool(const float* __restrict__ hc) {
    int w = (blockIdx.x * blockDim.x + threadIdx.x) >> 5;
    int lane = threadIdx.x & 31;
    if (w >= NCC) return;
    const float* hr = &hc[(size_t)w * HID];
    float v0 = hr[lane], v1 = hr[lane + 32], v2 = hr[lane + 64], v3 = hr[lane + 96];
#pragma unroll
    for (int k = 0; k < KNN; k++) {
        int nn = g_nn[w * 3 + k];
        atomicAdd(&g_pool[(size_t)nn * HID + lane], v0);
        atomicAdd(&g_pool[(size_t)nn * HID + lane + 32], v1);
        atomicAdd(&g_pool[(size_t)nn * HID + lane + 64], v2);
        atomicAdd(&g_pool[(size_t)nn * HID + lane + 96], v3);
        if (lane == 0) atomicAdd(&g_pcnt[nn], 1);
    }
}

// ---------------- decoder ----------------
__global__ void k_dec(const float* __restrict__ hr, const float* __restrict__ Wd,
                      const float* __restrict__ bd, float* __restrict__ out) {
    int w = (blockIdx.x * blockDim.x + threadIdx.x) >> 5;
    int lane = threadIdx.x & 31;
    if (w >= NRR) return;
    float inv = 1.f / fmaxf((float)g_pcnt[w], 1.f);
    float a0 = 0.f, a1 = 0.f, a2 = 0.f;
#pragma unroll
    for (int t = 0; t < 4; t++) {
        int j = lane + 32 * t;
        float hv = hr[(size_t)w * HID + j];
        float pv = g_pool[(size_t)w * HID + j] * inv;
        a0 = fmaf(hv, Wd[j * 3 + 0], a0); a0 = fmaf(pv, Wd[(HID + j) * 3 + 0], a0);
        a1 = fmaf(hv, Wd[j * 3 + 1], a1); a1 = fmaf(pv, Wd[(HID + j) * 3 + 1], a1);
        a2 = fmaf(hv, Wd[j * 3 + 2], a2); a2 = fmaf(pv, Wd[(HID + j) * 3 + 2], a2);
    }
#pragma unroll
    for (int o = 16; o > 0; o >>= 1) {
        a0 += __shfl_xor_sync(0xffffffffu, a0, o);
        a1 += __shfl_xor_sync(0xffffffffu, a1, o);
        a2 += __shfl_xor_sync(0xffffffffu, a2, o);
    }
    if (lane == 0) {
        out[w * 3 + 0] = a0 + bd[0];
        out[w * 3 + 1] = a1 + bd[1];
        out[w * 3 + 2] = a2 + bd[2];
    }
}

// ---------------- host launcher ----------------
extern "C" void kernel_launch(void* const* d_in, const int* in_sizes, int n_in,
                              void* d_out, int out_size) {
    const float* x_r  = (const float*)d_in[0];
    const float* x_c  = (const float*)d_in[1];
    const int*   ei_r = (const int*)d_in[2];
    const int*   ei_c = (const int*)d_in[3];
    const float* W_r1  = (const float*)d_in[5];
    const float* as_r1 = (const float*)d_in[6];
    const float* ad_r1 = (const float*)d_in[7];
    const float* b_r1  = (const float*)d_in[8];
    const float* W_r2  = (const float*)d_in[9];
    const float* as_r2 = (const float*)d_in[10];
    const float* ad_r2 = (const float*)d_in[11];
    const float* b_r2  = (const float*)d_in[12];
    const float* W_c1  = (const float*)d_in[13];
    const float* as_c1 = (const float*)d_in[14];
    const float* ad_c1 = (const float*)d_in[15];
    const float* b_c1  = (const float*)d_in[16];
    const float* W_c2  = (const float*)d_in[17];
    const float* as_c2 = (const float*)d_in[18];
    const float* ad_c2 = (const float*)d_in[19];
    const float* b_c2  = (const float*)d_in[20];
    const float* W_dec = (const float*)d_in[21];
    const float* b_dec = (const float*)d_in[22];
    float* out = (float*)d_out;

    float *hw_r, *h1_r, *h2_r, *hw_c, *h1_c, *h2_c, *es, *ed, *mv, *dn, *nr2;
    int *cnt_r, *cur_r, *rp_r, *col_r, *cnt_c, *cur_c, *rp_c, *col_c;
    cudaGetSymbolAddress((void**)&hw_r, g_hw_r);
    cudaGetSymbolAddress((void**)&h1_r, g_h1_r);
    cudaGetSymbolAddress((void**)&h2_r, g_h2_r);
    cudaGetSymbolAddress((void**)&hw_c, g_hw_c);
    cudaGetSymbolAddress((void**)&h1_c, g_h1_c);
    cudaGetSymbolAddress((void**)&h2_c, g_h2_c);
    cudaGetSymbolAddress((void**)&es, g_es);
    cudaGetSymbolAddress((void**)&ed, g_ed);
    cudaGetSymbolAddress((void**)&mv, g_mm);
    cudaGetSymbolAddress((void**)&dn, g_dn);
    cudaGetSymbolAddress((void**)&nr2, g_nr2);
    cudaGetSymbolAddress((void**)&cnt_r, g_cnt_r);
    cudaGetSymbolAddress((void**)&cur_r, g_cur_r);
    cudaGetSymbolAddress((void**)&rp_r, g_rp_r);
    cudaGetSymbolAddress((void**)&col_r, g_col_r);
    cudaGetSymbolAddress((void**)&cnt_c, g_cnt_c);
    cudaGetSymbolAddress((void**)&cur_c, g_cur_c);
    cudaGetSymbolAddress((void**)&rp_c, g_rp_c);
    cudaGetSymbolAddress((void**)&col_c, g_col_c);

    k_init<<<1024, 256>>>();

    k_count<<<(ERR + 255) / 256, 256>>>(ei_r + ERR, ERR, cnt_r);
    k_count<<<(ECC + 255) / 256, 256>>>(ei_c + ECC, ECC, cnt_c);
    k_scan<<<1, 1024>>>(cnt_r, rp_r, NRR);
    k_scan<<<1, 1024>>>(cnt_c, rp_c, NCC);
    k_scatter<<<(ERR + 255) / 256, 256>>>(ei_r, ei_r + ERR, ERR, rp_r, cur_r, col_r);
    k_scatter<<<(ECC + 255) / 256, 256>>>(ei_c, ei_c + ECC, ECC, rp_c, cur_c, col_c);
    k_selfloop<<<(NRR + 255) / 256, 256>>>(rp_r, col_r, NRR);
    k_selfloop<<<(NCC + 255) / 256, 256>>>(rp_c, col_c, NCC);

    const int WGR = (NRR + 7) / 8;
    const int WGC = (NCC + 7) / 8;

    // resting branch
    k_lin1<<<WGR, 256>>>(x_r, W_r1, as_r1, ad_r1, hw_r, es, ed, NRR);
    k_stats<<<WGR, 256>>>(rp_r, col_r, es, ed, mv, dn, NRR);
    k_agg<<<WGR, 256>>>(rp_r, col_r, hw_r, es, ed, mv, dn, b_r1, h1_r, NRR);
    k_gemm128<<<(NRR + 63) / 64, 256>>>(h1_r, W_r2, hw_r, NRR);
    k_dots<<<WGR, 256>>>(hw_r, as_r2, ad_r2, es, ed, NRR);
    k_stats<<<WGR, 256>>>(rp_r, col_r, es, ed, mv, dn, NRR);
    k_agg<<<WGR, 256>>>(rp_r, col_r, hw_r, es, ed, mv, dn, b_r2, h2_r, NRR);

    // collider branch
    k_lin1<<<WGC, 256>>>(x_c, W_c1, as_c1, ad_c1, hw_c, es, ed, NCC);
    k_stats<<<WGC, 256>>>(rp_c, col_c, es, ed, mv, dn, NCC);
    k_agg<<<WGC, 256>>>(rp_c, col_c, hw_c, es, ed, mv, dn, b_c1, h1_c, NCC);
    k_gemm128<<<(NCC + 63) / 64, 256>>>(h1_c, W_c2, hw_c, NCC);
    k_dots<<<WGC, 256>>>(hw_c, as_c2, ad_c2, es, ed, NCC);
    k_stats<<<WGC, 256>>>(rp_c, col_c, es, ed, mv, dn, NCC);
    k_agg<<<WGC, 256>>>(rp_c, col_c, hw_c, es, ed, mv, dn, b_c2, h2_c, NCC);

    // fused KNN + top-3 + pooling + decode
    k_norm<<<WGR, 256>>>(h2_r, nr2, NRR);
    dim3 kg(CTILES, NCH);
    k_knn_top3<<<kg, 256>>>(h2_c, h2_r, nr2);
    k_merge<<<(NCC + 255) / 256, 256>>>();
    k_pool<<<WGC, 256>>>(h2_c);
    k_dec<<<WGR, 256>>>(h2_r, W_dec, b_dec, out);
}

// round 4
// speedup vs baseline: 1.5705x; 1.5705x over previous
#include <cuda_runtime.h>
#include <math.h>

// ---------------- problem constants ----------------
#define NRR 20000
#define NCC 5000
#define ERR 320000
#define ECC 80000
#define DIN 6
#define HID 128
#define KNN 3
#define NEG 0.2f

#define NRT 157         // ceil(NRR / 128) resting tiles
#define CTILES 40       // ceil(NCC / 128) collider tiles

// ---------------- static scratch (device globals; no allocation) ----------------
__device__ float g_hw_r[NRR * HID];
__device__ float g_h1_r[NRR * HID];
__device__ float g_h2_r[NRR * HID];
__device__ float g_hw_c[NCC * HID];
__device__ float g_h1_c[NCC * HID];
__device__ float g_h2_c[NCC * HID];
__device__ float g_es[NRR];
__device__ float g_ed[NRR];
__device__ float g_mm[NRR];
__device__ float g_dn[NRR];
__device__ int   g_cnt_r[NRR];
__device__ int   g_cur_r[NRR];
__device__ int   g_rp_r[NRR + 1];
__device__ int   g_col_r[ERR + NRR];
__device__ int   g_cnt_c[NCC];
__device__ int   g_cur_c[NCC];
__device__ int   g_rp_c[NCC + 1];
__device__ int   g_col_c[ECC + NCC];
__device__ float g_nr2[NRR];
__device__ float g_pv[NRT * NCC * 3];    // partial top-3 values, [rtile][collider][3]
__device__ int   g_pi[NRT * NCC * 3];    // partial top-3 indices
__device__ int   g_nn[NCC * KNN];
__device__ float g_pool[NRR * HID];
__device__ int   g_pcnt[NRR];

// ---------------- init / zero ----------------
__global__ void k_init() {
    int i = blockIdx.x * blockDim.x + threadIdx.x;
    int st = gridDim.x * blockDim.x;
    for (int t = i; t < NRR * HID; t += st) g_pool[t] = 0.f;
    for (int t = i; t < NRR; t += st) { g_cnt_r[t] = 1; g_cur_r[t] = 0; g_pcnt[t] = 0; }
    for (int t = i; t < NCC; t += st) { g_cnt_c[t] = 1; g_cur_c[t] = 0; }
}

// ---------------- CSR build ----------------
__global__ void k_count(const int* __restrict__ dst, int E, int* __restrict__ cnt) {
    int i = blockIdx.x * blockDim.x + threadIdx.x;
    if (i < E) atomicAdd(&cnt[dst[i]], 1);
}

__global__ void k_scan(const int* __restrict__ cnt, int* __restrict__ rp, int n) {
    __shared__ int part[1024];
    int t = threadIdx.x;
    int chunk = (n + 1023) / 1024;
    int beg = t * chunk;
    int end = min(n, beg + chunk);
    int s = 0;
    for (int i = beg; i < end; i++) s += cnt[i];
    part[t] = s;
    __syncthreads();
    for (int off = 1; off < 1024; off <<= 1) {
        int v = (t >= off) ? part[t - off] : 0;
        __syncthreads();
        part[t] += v;
        __syncthreads();
    }
    int run = part[t] - s;
    for (int i = beg; i < end; i++) { rp[i] = run; run += cnt[i]; }
    if (t == 1023) rp[n] = part[1023];
}

__global__ void k_scatter(const int* __restrict__ src, const int* __restrict__ dst, int E,
                          const int* __restrict__ rp, int* __restrict__ cur,
                          int* __restrict__ colarr) {
    int i = blockIdx.x * blockDim.x + threadIdx.x;
    if (i < E) {
        int d = dst[i];
        int pos = rp[d] + atomicAdd(&cur[d], 1);
        colarr[pos] = src[i];
    }
}

__global__ void k_selfloop(const int* __restrict__ rp, int* __restrict__ colarr, int n) {
    int i = blockIdx.x * blockDim.x + threadIdx.x;
    if (i < n) colarr[rp[i + 1] - 1] = i;
}

// ---------------- GAT linear layers ----------------
__global__ void k_lin1(const float* __restrict__ x, const float* __restrict__ W,
                       const float* __restrict__ as_, const float* __restrict__ ad_,
                       float* __restrict__ h, float* __restrict__ es, float* __restrict__ ed,
                       int n) {
    int w = (blockIdx.x * blockDim.x + threadIdx.x) >> 5;
    int lane = threadIdx.x & 31;
    if (w >= n) return;
    float xv[DIN];
#pragma unroll
    for (int k = 0; k < DIN; k++) xv[k] = x[w * DIN + k];
    float hv[4], ps = 0.f, pd = 0.f;
#pragma unroll
    for (int q = 0; q < 4; q++) {
        int j = lane * 4 + q;
        float a = 0.f;
#pragma unroll
        for (int k = 0; k < DIN; k++) a = fmaf(xv[k], W[k * HID + j], a);
        hv[q] = a;
        ps = fmaf(a, as_[j], ps);
        pd = fmaf(a, ad_[j], pd);
    }
    *(float4*)&h[(size_t)w * HID + lane * 4] = make_float4(hv[0], hv[1], hv[2], hv[3]);
#pragma unroll
    for (int o = 16; o > 0; o >>= 1) {
        ps += __shfl_xor_sync(0xffffffffu, ps, o);
        pd += __shfl_xor_sync(0xffffffffu, pd, o);
    }
    if (lane == 0) { es[w] = ps; ed[w] = pd; }
}

// layer 2 GEMM: C(M x 128) = A(M x 128) @ B(128 x 128)
__global__ void __launch_bounds__(256) k_gemm128(const float* __restrict__ A,
                                                 const float* __restrict__ B,
                                                 float* __restrict__ C, int M) {
    __shared__ float As[16][64];
    __shared__ float Bs[16][128];
    int tid = threadIdx.x;
    int tc = tid & 31;
    int tr = tid >> 5;
    int row0 = blockIdx.x * 64;
    float acc[8][4];
#pragma unroll
    for (int i = 0; i < 8; i++)
#pragma unroll
        for (int j = 0; j < 4; j++) acc[i][j] = 0.f;

    for (int k0 = 0; k0 < HID; k0 += 16) {
        int row_l = tid >> 2, quad = tid & 3;
        int gr = row0 + row_l;
        float4 av = make_float4(0.f, 0.f, 0.f, 0.f);
        if (gr < M) av = *(const float4*)&A[(size_t)gr * HID + k0 + quad * 4];
        As[quad * 4 + 0][row_l] = av.x;
        As[quad * 4 + 1][row_l] = av.y;
        As[quad * 4 + 2][row_l] = av.z;
        As[quad * 4 + 3][row_l] = av.w;
        int kk = tid >> 4, cp = tid & 15;
        float4 bv0 = *(const float4*)&B[(size_t)(k0 + kk) * HID + cp * 8];
        float4 bv1 = *(const float4*)&B[(size_t)(k0 + kk) * HID + cp * 8 + 4];
        *(float4*)&Bs[kk][cp * 8] = bv0;
        *(float4*)&Bs[kk][cp * 8 + 4] = bv1;
        __syncthreads();
#pragma unroll
        for (int k2 = 0; k2 < 16; k2++) {
            float4 a0 = *(float4*)&As[k2][tr * 8];
            float4 a1 = *(float4*)&As[k2][tr * 8 + 4];
            float4 bb = *(float4*)&Bs[k2][tc * 4];
            float a[8] = {a0.x, a0.y, a0.z, a0.w, a1.x, a1.y, a1.z, a1.w};
            float b[4] = {bb.x, bb.y, bb.z, bb.w};
#pragma unroll
            for (int i = 0; i < 8; i++)
#pragma unroll
                for (int j = 0; j < 4; j++) acc[i][j] = fmaf(a[i], b[j], acc[i][j]);
        }
        __syncthreads();
    }
#pragma unroll
    for (int i = 0; i < 8; i++) {
        int r = row0 + tr * 8 + i;
        if (r < M)
            *(float4*)&C[(size_t)r * HID + tc * 4] =
                make_float4(acc[i][0], acc[i][1], acc[i][2], acc[i][3]);
    }
}

__global__ void k_dots(const float* __restrict__ h, const float* __restrict__ as_,
                       const float* __restrict__ ad_, float* __restrict__ es,
                       float* __restrict__ ed, int n) {
    int w = (blockIdx.x * blockDim.x + threadIdx.x) >> 5;
    int lane = threadIdx.x & 31;
    if (w >= n) return;
    const float* hr = &h[(size_t)w * HID];
    float ps = 0.f, pd = 0.f;
#pragma unroll
    for (int t = 0; t < 4; t++) {
        int j = lane + 32 * t;
        float v = hr[j];
        ps = fmaf(v, as_[j], ps);
        pd = fmaf(v, ad_[j], pd);
    }
#pragma unroll
    for (int o = 16; o > 0; o >>= 1) {
        ps += __shfl_xor_sync(0xffffffffu, ps, o);
        pd += __shfl_xor_sync(0xffffffffu, pd, o);
    }
    if (lane == 0) { es[w] = ps; ed[w] = pd; }
}

// ---------------- segment softmax stats ----------------
__global__ void k_stats(const int* __restrict__ rp, const int* __restrict__ col,
                        const float* __restrict__ es, const float* __restrict__ edv,
                        float* __restrict__ mv, float* __restrict__ dnv, int n) {
    int w = (blockIdx.x * blockDim.x + threadIdx.x) >> 5;
    int lane = threadIdx.x & 31;
    if (w >= n) return;
    int beg = rp[w], end = rp[w + 1];
    float ed = edv[w];
    float m = -1e30f, s = 0.f;
    for (int idx = beg + lane; idx < end; idx += 32) {
        float e = es[col[idx]] + ed;
        e = e > 0.f ? e : NEG * e;
        float mn = fmaxf(m, e);
        s = s * __expf(m - mn) + __expf(e - mn);
        m = mn;
    }
#pragma unroll
    for (int o = 16; o > 0; o >>= 1) {
        float m2 = __shfl_xor_sync(0xffffffffu, m, o);
        float s2 = __shfl_xor_sync(0xffffffffu, s, o);
        float mn = fmaxf(m, m2);
        s = s * __expf(m - mn) + s2 * __expf(m2 - mn);
        m = mn;
    }
    if (lane == 0) { mv[w] = m; dnv[w] = s; }
}

// ---------------- attention-weighted aggregation ----------------
__global__ void k_agg(const int* __restrict__ rp, const int* __restrict__ col,
                      const float* __restrict__ hW, const float* __restrict__ es,
                      const float* __restrict__ edv, const float* __restrict__ mv,
                      const float* __restrict__ dnv, const float* __restrict__ bias,
                      float* __restrict__ out, int n) {
    int w = (blockIdx.x * blockDim.x + threadIdx.x) >> 5;
    int lane = threadIdx.x & 31;
    if (w >= n) return;
    int beg = rp[w], end = rp[w + 1];
    float ed = edv[w], md = mv[w];
    float inv = 1.f / fmaxf(dnv[w], 1e-16f);
    float a0 = 0.f, a1 = 0.f, a2 = 0.f, a3 = 0.f;
    for (int idx = beg; idx < end; idx++) {
        int s = col[idx];
        float e = es[s] + ed;
        e = e > 0.f ? e : NEG * e;
        float wgt = __expf(e - md) * inv;
        const float* hr = &hW[(size_t)s * HID];
        a0 = fmaf(wgt, hr[lane], a0);
        a1 = fmaf(wgt, hr[lane + 32], a1);
        a2 = fmaf(wgt, hr[lane + 64], a2);
        a3 = fmaf(wgt, hr[lane + 96], a3);
    }
    out[(size_t)w * HID + lane]      = fmaxf(a0 + bias[lane], 0.f);
    out[(size_t)w * HID + lane + 32] = fmaxf(a1 + bias[lane + 32], 0.f);
    out[(size_t)w * HID + lane + 64] = fmaxf(a2 + bias[lane + 64], 0.f);
    out[(size_t)w * HID + lane + 96] = fmaxf(a3 + bias[lane + 96], 0.f);
}

// ---------------- row norms (resting only) ----------------
__global__ void k_norm(const float* __restrict__ h, float* __restrict__ nrm, int n) {
    int w = (blockIdx.x * blockDim.x + threadIdx.x) >> 5;
    int lane = threadIdx.x & 31;
    if (w >= n) return;
    const float* hr = &h[(size_t)w * HID];
    float s = 0.f;
#pragma unroll
    for (int t = 0; t < 4; t++) { float v = hr[lane + 32 * t]; s = fmaf(v, v, s); }
#pragma unroll
    for (int o = 16; o > 0; o >>= 1) s += __shfl_xor_sync(0xffffffffu, s, o);
    if (lane == 0) nrm[w] = s;
}

// ---------------- top-3 ordering helper (ties -> lower index, = lax.top_k) ----------------
__device__ __forceinline__ bool d2_less(float v1, int i1, float v2, int i2) {
    return (v1 < v2) || (v1 == v2 && i1 < i2);
}

__device__ __forceinline__ void top3_upd(float v, int r, float tv[3], int ti[3]) {
    if (d2_less(v, r, tv[2], ti[2])) {
        tv[2] = v; ti[2] = r;
        if (d2_less(tv[2], ti[2], tv[1], ti[1])) {
            float a = tv[1]; int b = ti[1]; tv[1] = tv[2]; ti[1] = ti[2]; tv[2] = a; ti[2] = b;
        }
        if (d2_less(tv[1], ti[1], tv[0], ti[0])) {
            float a = tv[0]; int b = ti[0]; tv[0] = tv[1]; ti[0] = ti[1]; tv[1] = a; ti[1] = b;
        }
    }
}

// ---------------- KNN GEMM (R1 hot loop verbatim) + in-block top-3 epilogue ----------------
// rank key = nr2[r] - 2*dot(c,r); per-row-constant nc2 dropped (argmin invariant).
// grid (NRT, CTILES): one 128x128 tile per block, exactly like R1's k_knn.
__global__ void __launch_bounds__(256) k_knn_top3(const float* __restrict__ A,   // h2_c
                                                  const float* __restrict__ B,   // h2_r
                                                  const float* __restrict__ nr2) {
    __shared__ __align__(16) union ShU {
        struct { float As[16][128]; float Bs[16][128]; } g;
        struct { float mv[128][48]; int mi[128][48]; } m;
    } sh;
    int tid = threadIdx.x;
    int tx = tid & 15, ty = tid >> 4;
    int rb = blockIdx.x * 128;  // resting tile
    int cb = blockIdx.y * 128;  // collider tile
    float acc[8][8];
#pragma unroll
    for (int i = 0; i < 8; i++)
#pragma unroll
        for (int j = 0; j < 8; j++) acc[i][j] = 0.f;

    int rl = tid >> 1, kq = tid & 1;
    for (int k0 = 0; k0 < HID; k0 += 16) {
        {
            int gc = cb + rl;
            float4 v0 = make_float4(0.f, 0.f, 0.f, 0.f), v1 = v0;
            if (gc < NCC) {
                v0 = *(const float4*)&A[(size_t)gc * HID + k0 + kq * 8];
                v1 = *(const float4*)&A[(size_t)gc * HID + k0 + kq * 8 + 4];
            }
            sh.g.As[kq * 8 + 0][rl] = v0.x; sh.g.As[kq * 8 + 1][rl] = v0.y;
            sh.g.As[kq * 8 + 2][rl] = v0.z; sh.g.As[kq * 8 + 3][rl] = v0.w;
            sh.g.As[kq * 8 + 4][rl] = v1.x; sh.g.As[kq * 8 + 5][rl] = v1.y;
            sh.g.As[kq * 8 + 6][rl] = v1.z; sh.g.As[kq * 8 + 7][rl] = v1.w;
        }
        {
            int gr = rb + rl;
            float4 v0 = make_float4(0.f, 0.f, 0.f, 0.f), v1 = v0;
            if (gr < NRR) {
                v0 = *(const float4*)&B[(size_t)gr * HID + k0 + kq * 8];
                v1 = *(const float4*)&B[(size_t)gr * HID + k0 + kq * 8 + 4];
            }
            sh.g.Bs[kq * 8 + 0][rl] = v0.x; sh.g.Bs[kq * 8 + 1][rl] = v0.y;
            sh.g.Bs[kq * 8 + 2][rl] = v0.z; sh.g.Bs[kq * 8 + 3][rl] = v0.w;
            sh.g.Bs[kq * 8 + 4][rl] = v1.x; sh.g.Bs[kq * 8 + 5][rl] = v1.y;
            sh.g.Bs[kq * 8 + 6][rl] = v1.z; sh.g.Bs[kq * 8 + 7][rl] = v1.w;
        }
        __syncthreads();
#pragma unroll
        for (int kk = 0; kk < 16; kk++) {
            float4 t0 = *(float4*)&sh.g.As[kk][ty * 8];
            float4 t1 = *(float4*)&sh.g.As[kk][ty * 8 + 4];
            float4 u0 = *(float4*)&sh.g.Bs[kk][tx * 8];
            float4 u1 = *(float4*)&sh.g.Bs[kk][tx * 8 + 4];
            float a[8] = {t0.x, t0.y, t0.z, t0.w, t1.x, t1.y, t1.z, t1.w};
            float b[8] = {u0.x, u0.y, u0.z, u0.w, u1.x, u1.y, u1.z, u1.w};
#pragma unroll
            for (int i = 0; i < 8; i++)
#pragma unroll
                for (int j = 0; j < 8; j++) acc[i][j] = fmaf(a[i], b[j], acc[i][j]);
        }
        __syncthreads();
    }

    // ---- epilogue (post-loop; tv/ti live range starts here) ----
    int r0 = rb + tx * 8;
    float nrv[8];
#pragma unroll
    for (int j = 0; j < 8; j++) nrv[j] = (r0 + j < NRR) ? nr2[r0 + j] : 1e30f;

#pragma unroll
    for (int i = 0; i < 8; i++) {
        float tv[3] = {1e30f, 1e30f, 1e30f};
        int   ti[3] = {0x7fffffff, 0x7fffffff, 0x7fffffff};
#pragma unroll
        for (int j = 0; j < 8; j++) {
            int r = r0 + j;
            if (r < NRR) {
                float val = nrv[j] - 2.f * acc[i][j];
                top3_upd(val, r, tv, ti);
            }
        }
        int row = ty * 8 + i;
#pragma unroll
        for (int k = 0; k < 3; k++) {
            sh.m.mv[row][tx * 3 + k] = tv[k];
            sh.m.mi[row][tx * 3 + k] = ti[k];
        }
    }
    __syncthreads();
    if (tid < 128) {
        int row = tid;
        float f[3] = {1e30f, 1e30f, 1e30f};
        int   j[3] = {0x7fffffff, 0x7fffffff, 0x7fffffff};
        for (int t = 0; t < 48; t++) {
            int r = sh.m.mi[row][t];
            if (r == 0x7fffffff) continue;
            top3_upd(sh.m.mv[row][t], r, f, j);
        }
        int c = cb + row;
        if (c < NCC) {
            // layout [rtile][collider][3] for coalesced merge reads
            size_t base = ((size_t)blockIdx.x * NCC + c) * 3;
            g_pv[base + 0] = f[0]; g_pi[base + 0] = j[0];
            g_pv[base + 1] = f[1]; g_pi[base + 1] = j[1];
            g_pv[base + 2] = f[2]; g_pi[base + 2] = j[2];
        }
    }
}

// ---------------- final merge of per-rtile candidates ----------------
__global__ void k_merge() {
    int c = blockIdx.x * blockDim.x + threadIdx.x;
    if (c >= NCC) return;
    float f[3] = {1e30f, 1e30f, 1e30f};
    int   j[3] = {0x7fffffff, 0x7fffffff, 0x7fffffff};
    for (int t = 0; t < NRT; t++) {
        size_t base = ((size_t)t * NCC + c) * 3;
#pragma unroll
        for (int k = 0; k < 3; k++) {
            int r = g_pi[base + k];
            if (r == 0x7fffffff) continue;
            top3_upd(g_pv[base + k], r, f, j);
        }
    }
    g_nn[c * 3 + 0] = j[0];
    g_nn[c * 3 + 1] = j[1];
    g_nn[c * 3 + 2] = j[2];
}

// ---------------- scatter-mean pooling ----------------
__global__ void k_pool(const float* __restrict__ hc) {
    int w = (blockIdx.x * blockDim.x + threadIdx.x) >> 5;
    int lane = threadIdx.x & 31;
    if (w >= NCC) return;
    const float* hr = &hc[(size_t)w * HID];
    float v0 = hr[lane], v1 = hr[lane + 32], v2 = hr[lane + 64], v3 = hr[lane + 96];
#pragma unroll
    for (int k = 0; k < KNN; k++) {
        int nn = g_nn[w * 3 + k];
        atomicAdd(&g_pool[(size_t)nn * HID + lane], v0);
        atomicAdd(&g_pool[(size_t)nn * HID + lane + 32], v1);
        atomicAdd(&g_pool[(size_t)nn * HID + lane + 64], v2);
        atomicAdd(&g_pool[(size_t)nn * HID + lane + 96], v3);
        if (lane == 0) atomicAdd(&g_pcnt[nn], 1);
    }
}

// ---------------- decoder ----------------
__global__ void k_dec(const float* __restrict__ hr, const float* __restrict__ Wd,
                      const float* __restrict__ bd, float* __restrict__ out) {
    int w = (blockIdx.x * blockDim.x + threadIdx.x) >> 5;
    int lane = threadIdx.x & 31;
    if (w >= NRR) return;
    float inv = 1.f / fmaxf((float)g_pcnt[w], 1.f);
    float a0 = 0.f, a1 = 0.f, a2 = 0.f;
#pragma unroll
    for (int t = 0; t < 4; t++) {
        int j = lane + 32 * t;
        float hv = hr[(size_t)w * HID + j];
        float pv = g_pool[(size_t)w * HID + j] * inv;
        a0 = fmaf(hv, Wd[j * 3 + 0], a0); a0 = fmaf(pv, Wd[(HID + j) * 3 + 0], a0);
        a1 = fmaf(hv, Wd[j * 3 + 1], a1); a1 = fmaf(pv, Wd[(HID + j) * 3 + 1], a1);
        a2 = fmaf(hv, Wd[j * 3 + 2], a2); a2 = fmaf(pv, Wd[(HID + j) * 3 + 2], a2);
    }
#pragma unroll
    for (int o = 16; o > 0; o >>= 1) {
        a0 += __shfl_xor_sync(0xffffffffu, a0, o);
        a1 += __shfl_xor_sync(0xffffffffu, a1, o);
        a2 += __shfl_xor_sync(0xffffffffu, a2, o);
    }
    if (lane == 0) {
        out[w * 3 + 0] = a0 + bd[0];
        out[w * 3 + 1] = a1 + bd[1];
        out[w * 3 + 2] = a2 + bd[2];
    }
}

// ---------------- host launcher ----------------
extern "C" void kernel_launch(void* const* d_in, const int* in_sizes, int n_in,
                              void* d_out, int out_size) {
    const float* x_r  = (const float*)d_in[0];
    const float* x_c  = (const float*)d_in[1];
    const int*   ei_r = (const int*)d_in[2];
    const int*   ei_c = (const int*)d_in[3];
    const float* W_r1  = (const float*)d_in[5];
    const float* as_r1 = (const float*)d_in[6];
    const float* ad_r1 = (const float*)d_in[7];
    const float* b_r1  = (const float*)d_in[8];
    const float* W_r2  = (const float*)d_in[9];
    const float* as_r2 = (const float*)d_in[10];
    const float* ad_r2 = (const float*)d_in[11];
    const float* b_r2  = (const float*)d_in[12];
    const float* W_c1  = (const float*)d_in[13];
    const float* as_c1 = (const float*)d_in[14];
    const float* ad_c1 = (const float*)d_in[15];
    const float* b_c1  = (const float*)d_in[16];
    const float* W_c2  = (const float*)d_in[17];
    const float* as_c2 = (const float*)d_in[18];
    const float* ad_c2 = (const float*)d_in[19];
    const float* b_c2  = (const float*)d_in[20];
    const float* W_dec = (const float*)d_in[21];
    const float* b_dec = (const float*)d_in[22];
    float* out = (float*)d_out;

    float *hw_r, *h1_r, *h2_r, *hw_c, *h1_c, *h2_c, *es, *ed, *mv, *dn, *nr2;
    int *cnt_r, *cur_r, *rp_r, *col_r, *cnt_c, *cur_c, *rp_c, *col_c;
    cudaGetSymbolAddress((void**)&hw_r, g_hw_r);
    cudaGetSymbolAddress((void**)&h1_r, g_h1_r);
    cudaGetSymbolAddress((void**)&h2_r, g_h2_r);
    cudaGetSymbolAddress((void**)&hw_c, g_hw_c);
    cudaGetSymbolAddress((void**)&h1_c, g_h1_c);
    cudaGetSymbolAddress((void**)&h2_c, g_h2_c);
    cudaGetSymbolAddress((void**)&es, g_es);
    cudaGetSymbolAddress((void**)&ed, g_ed);
    cudaGetSymbolAddress((void**)&mv, g_mm);
    cudaGetSymbolAddress((void**)&dn, g_dn);
    cudaGetSymbolAddress((void**)&nr2, g_nr2);
    cudaGetSymbolAddress((void**)&cnt_r, g_cnt_r);
    cudaGetSymbolAddress((void**)&cur_r, g_cur_r);
    cudaGetSymbolAddress((void**)&rp_r, g_rp_r);
    cudaGetSymbolAddress((void**)&col_r, g_col_r);
    cudaGetSymbolAddress((void**)&cnt_c, g_cnt_c);
    cudaGetSymbolAddress((void**)&cur_c, g_cur_c);
    cudaGetSymbolAddress((void**)&rp_c, g_rp_c);
    cudaGetSymbolAddress((void**)&col_c, g_col_c);

    k_init<<<1024, 256>>>();

    k_count<<<(ERR + 255) / 256, 256>>>(ei_r + ERR, ERR, cnt_r);
    k_count<<<(ECC + 255) / 256, 256>>>(ei_c + ECC, ECC, cnt_c);
    k_scan<<<1, 1024>>>(cnt_r, rp_r, NRR);
    k_scan<<<1, 1024>>>(cnt_c, rp_c, NCC);
    k_scatter<<<(ERR + 255) / 256, 256>>>(ei_r, ei_r + ERR, ERR, rp_r, cur_r, col_r);
    k_scatter<<<(ECC + 255) / 256, 256>>>(ei_c, ei_c + ECC, ECC, rp_c, cur_c, col_c);
    k_selfloop<<<(NRR + 255) / 256, 256>>>(rp_r, col_r, NRR);
    k_selfloop<<<(NCC + 255) / 256, 256>>>(rp_c, col_c, NCC);

    const int WGR = (NRR + 7) / 8;
    const int WGC = (NCC + 7) / 8;

    // resting branch
    k_lin1<<<WGR, 256>>>(x_r, W_r1, as_r1, ad_r1, hw_r, es, ed, NRR);
    k_stats<<<WGR, 256>>>(rp_r, col_r, es, ed, mv, dn, NRR);
    k_agg<<<WGR, 256>>>(rp_r, col_r, hw_r, es, ed, mv, dn, b_r1, h1_r, NRR);
    k_gemm128<<<(NRR + 63) / 64, 256>>>(h1_r, W_r2, hw_r, NRR);
    k_dots<<<WGR, 256>>>(hw_r, as_r2, ad_r2, es, ed, NRR);
    k_stats<<<WGR, 256>>>(rp_r, col_r, es, ed, mv, dn, NRR);
    k_agg<<<WGR, 256>>>(rp_r, col_r, hw_r, es, ed, mv, dn, b_r2, h2_r, NRR);

    // collider branch
    k_lin1<<<WGC, 256>>>(x_c, W_c1, as_c1, ad_c1, hw_c, es, ed, NCC);
    k_stats<<<WGC, 256>>>(rp_c, col_c, es, ed, mv, dn, NCC);
    k_agg<<<WGC, 256>>>(rp_c, col_c, hw_c, es, ed, mv, dn, b_c1, h1_c, NCC);
    k_gemm128<<<(NCC + 63) / 64, 256>>>(h1_c, W_c2, hw_c, NCC);
    k_dots<<<WGC, 256>>>(hw_c, as_c2, ad_c2, es, ed, NCC);
    k_stats<<<WGC, 256>>>(rp_c, col_c, es, ed, mv, dn, NCC);
    k_agg<<<WGC, 256>>>(rp_c, col_c, hw_c, es, ed, mv, dn, b_c2, h2_c, NCC);

    // fused KNN + top-3 + pooling + decode
    k_norm<<<WGR, 256>>>(h2_r, nr2, NRR);
    dim3 kg(NRT, CTILES);
    k_knn_top3<<<kg, 256>>>(h2_c, h2_r, nr2);
    k_merge<<<(NCC + 255) / 256, 256>>>();
    k_pool<<<WGC, 256>>>(h2_c);
    k_dec<<<WGR, 256>>>(h2_r, W_dec, b_dec, out);
}

// round 6
// speedup vs baseline: 2.2991x; 1.4639x over previous
#include <cuda_runtime.h>
#include <cuda_bf16.h>
#include <math.h>
#include <cstdint>

// ---------------- problem constants ----------------
#define NRR 20000
#define NCC 5000
#define ERR 320000
#define ECC 80000
#define DIN 6
#define HID 128
#define KNN 3
#define NEG 0.2f

#define CTILES 40        // ceil(NCC/128)
#define RSPLIT 8
#define RROWS 2500       // NRR / RSPLIT (exact)
#define NCAND 16         // candidates per (split, collider): 4 quad threads x top-4

// ---------------- mma.sync m16n8k16 bf16 (baseline PTX, compiles at compute_103) ----------------
#define MMA16816(c, a, b0, b1) \
    asm volatile("mma.sync.aligned.m16n8k16.row.col.f32.bf16.bf16.f32 " \
        "{%0,%1,%2,%3}, {%4,%5,%6,%7}, {%8,%9}, {%0,%1,%2,%3};" \
        : "+f"((c)[0]), "+f"((c)[1]), "+f"((c)[2]), "+f"((c)[3]) \
        : "r"((a)[0]), "r"((a)[1]), "r"((a)[2]), "r"((a)[3]), "r"(b0), "r"(b1))

// ---------------- static scratch ----------------
__device__ float g_hw_r[NRR * HID];
__device__ float g_h1_r[NRR * HID];
__device__ float g_h2_r[NRR * HID];
__device__ float g_hw_c[NCC * HID];
__device__ float g_h1_c[NCC * HID];
__device__ float g_h2_c[NCC * HID];
__device__ float g_es[NRR];
__device__ float g_ed[NRR];
__device__ float g_mm[NRR];
__device__ float g_dn[NRR];
__device__ int   g_cnt_r[NRR];
__device__ int   g_cur_r[NRR];
__device__ int   g_rp_r[NRR + 1];
__device__ int   g_col_r[ERR + NRR];
__device__ int   g_cnt_c[NCC];
__device__ int   g_cur_c[NCC];
__device__ int   g_rp_c[NCC + 1];
__device__ int   g_col_c[ECC + NCC];
__device__ float g_nr2[NRR];
__device__ __nv_bfloat16 g_bch[NCC * HID];   // collider hi
__device__ __nv_bfloat16 g_bcl[NCC * HID];   // collider lo
__device__ __nv_bfloat16 g_brh[NRR * HID];   // resting hi
__device__ __nv_bfloat16 g_brl[NRR * HID];   // resting lo
__device__ int   g_ci[RSPLIT * NCC * NCAND]; // candidate indices
__device__ int   g_nn[NCC * KNN];
__device__ float g_pool[NRR * HID];
__device__ int   g_pcnt[NRR];

// ---------------- init ----------------
__global__ void k_init() {
    int i = blockIdx.x * blockDim.x + threadIdx.x;
    int st = gridDim.x * blockDim.x;
    for (int t = i; t < NRR * HID; t += st) g_pool[t] = 0.f;
    for (int t = i; t < NRR; t += st) { g_cnt_r[t] = 1; g_cur_r[t] = 0; g_pcnt[t] = 0; }
    for (int t = i; t < NCC; t += st) { g_cnt_c[t] = 1; g_cur_c[t] = 0; }
}

// ---------------- CSR build ----------------
__global__ void k_count(const int* __restrict__ dst, int E, int* __restrict__ cnt) {
    int i = blockIdx.x * blockDim.x + threadIdx.x;
    if (i < E) atomicAdd(&cnt[dst[i]], 1);
}
__global__ void k_scan(const int* __restrict__ cnt, int* __restrict__ rp, int n) {
    __shared__ int part[1024];
    int t = threadIdx.x;
    int chunk = (n + 1023) / 1024;
    int beg = t * chunk, end = min(n, beg + chunk);
    int s = 0;
    for (int i = beg; i < end; i++) s += cnt[i];
    part[t] = s;
    __syncthreads();
    for (int off = 1; off < 1024; off <<= 1) {
        int v = (t >= off) ? part[t - off] : 0;
        __syncthreads();
        part[t] += v;
        __syncthreads();
    }
    int run = part[t] - s;
    for (int i = beg; i < end; i++) { rp[i] = run; run += cnt[i]; }
    if (t == 1023) rp[n] = part[1023];
}
__global__ void k_scatter(const int* __restrict__ src, const int* __restrict__ dst, int E,
                          const int* __restrict__ rp, int* __restrict__ cur, int* __restrict__ colarr) {
    int i = blockIdx.x * blockDim.x + threadIdx.x;
    if (i < E) {
        int d = dst[i];
        int pos = rp[d] + atomicAdd(&cur[d], 1);
        colarr[pos] = src[i];
    }
}
__global__ void k_selfloop(const int* __restrict__ rp, int* __restrict__ colarr, int n) {
    int i = blockIdx.x * blockDim.x + threadIdx.x;
    if (i < n) colarr[rp[i + 1] - 1] = i;
}

// ---------------- GAT stages (R1-proven) ----------------
__global__ void k_lin1(const float* __restrict__ x, const float* __restrict__ W,
                       const float* __restrict__ as_, const float* __restrict__ ad_,
                       float* __restrict__ h, float* __restrict__ es, float* __restrict__ ed, int n) {
    int w = (blockIdx.x * blockDim.x + threadIdx.x) >> 5;
    int lane = threadIdx.x & 31;
    if (w >= n) return;
    float xv[DIN];
#pragma unroll
    for (int k = 0; k < DIN; k++) xv[k] = x[w * DIN + k];
    float hv[4], ps = 0.f, pd = 0.f;
#pragma unroll
    for (int q = 0; q < 4; q++) {
        int j = lane * 4 + q;
        float a = 0.f;
#pragma unroll
        for (int k = 0; k < DIN; k++) a = fmaf(xv[k], W[k * HID + j], a);
        hv[q] = a;
        ps = fmaf(a, as_[j], ps);
        pd = fmaf(a, ad_[j], pd);
    }
    *(float4*)&h[(size_t)w * HID + lane * 4] = make_float4(hv[0], hv[1], hv[2], hv[3]);
#pragma unroll
    for (int o = 16; o > 0; o >>= 1) {
        ps += __shfl_xor_sync(0xffffffffu, ps, o);
        pd += __shfl_xor_sync(0xffffffffu, pd, o);
    }
    if (lane == 0) { es[w] = ps; ed[w] = pd; }
}

__global__ void __launch_bounds__(256) k_gemm128(const float* __restrict__ A,
                                                 const float* __restrict__ B,
                                                 float* __restrict__ C, int M) {
    __shared__ float As[16][64];
    __shared__ float Bs[16][128];
    int tid = threadIdx.x;
    int tc = tid & 31, tr = tid >> 5;
    int row0 = blockIdx.x * 64;
    float acc[8][4];
#pragma unroll
    for (int i = 0; i < 8; i++)
#pragma unroll
        for (int j = 0; j < 4; j++) acc[i][j] = 0.f;
    for (int k0 = 0; k0 < HID; k0 += 16) {
        int row_l = tid >> 2, quad = tid & 3;
        int gr = row0 + row_l;
        float4 av = make_float4(0.f, 0.f, 0.f, 0.f);
        if (gr < M) av = *(const float4*)&A[(size_t)gr * HID + k0 + quad * 4];
        As[quad * 4 + 0][row_l] = av.x;
        As[quad * 4 + 1][row_l] = av.y;
        As[quad * 4 + 2][row_l] = av.z;
        As[quad * 4 + 3][row_l] = av.w;
        int kk = tid >> 4, cp = tid & 15;
        float4 bv0 = *(const float4*)&B[(size_t)(k0 + kk) * HID + cp * 8];
        float4 bv1 = *(const float4*)&B[(size_t)(k0 + kk) * HID + cp * 8 + 4];
        *(float4*)&Bs[kk][cp * 8] = bv0;
        *(float4*)&Bs[kk][cp * 8 + 4] = bv1;
        __syncthreads();
#pragma unroll
        for (int k2 = 0; k2 < 16; k2++) {
            float4 a0 = *(float4*)&As[k2][tr * 8];
            float4 a1 = *(float4*)&As[k2][tr * 8 + 4];
            float4 bb = *(float4*)&Bs[k2][tc * 4];
            float a[8] = {a0.x, a0.y, a0.z, a0.w, a1.x, a1.y, a1.z, a1.w};
            float b[4] = {bb.x, bb.y, bb.z, bb.w};
#pragma unroll
            for (int i = 0; i < 8; i++)
#pragma unroll
                for (int j = 0; j < 4; j++) acc[i][j] = fmaf(a[i], b[j], acc[i][j]);
        }
        __syncthreads();
    }
#pragma unroll
    for (int i = 0; i < 8; i++) {
        int r = row0 + tr * 8 + i;
        if (r < M)
            *(float4*)&C[(size_t)r * HID + tc * 4] =
                make_float4(acc[i][0], acc[i][1], acc[i][2], acc[i][3]);
    }
}

__global__ void k_dots(const float* __restrict__ h, const float* __restrict__ as_,
                       const float* __restrict__ ad_, float* __restrict__ es,
                       float* __restrict__ ed, int n) {
    int w = (blockIdx.x * blockDim.x + threadIdx.x) >> 5;
    int lane = threadIdx.x & 31;
    if (w >= n) return;
    const float* hr = &h[(size_t)w * HID];
    float ps = 0.f, pd = 0.f;
#pragma unroll
    for (int t = 0; t < 4; t++) {
        int j = lane + 32 * t;
        float v = hr[j];
        ps = fmaf(v, as_[j], ps);
        pd = fmaf(v, ad_[j], pd);
    }
#pragma unroll
    for (int o = 16; o > 0; o >>= 1) {
        ps += __shfl_xor_sync(0xffffffffu, ps, o);
        pd += __shfl_xor_sync(0xffffffffu, pd, o);
    }
    if (lane == 0) { es[w] = ps; ed[w] = pd; }
}

__global__ void k_stats(const int* __restrict__ rp, const int* __restrict__ col,
                        const float* __restrict__ es, const float* __restrict__ edv,
                        float* __restrict__ mv, float* __restrict__ dnv, int n) {
    int w = (blockIdx.x * blockDim.x + threadIdx.x) >> 5;
    int lane = threadIdx.x & 31;
    if (w >= n) return;
    int beg = rp[w], end = rp[w + 1];
    float ed = edv[w];
    float m = -1e30f, s = 0.f;
    for (int idx = beg + lane; idx < end; idx += 32) {
        float e = es[col[idx]] + ed;
        e = e > 0.f ? e : NEG * e;
        float mn = fmaxf(m, e);
        s = s * __expf(m - mn) + __expf(e - mn);
        m = mn;
    }
#pragma unroll
    for (int o = 16; o > 0; o >>= 1) {
        float m2 = __shfl_xor_sync(0xffffffffu, m, o);
        float s2 = __shfl_xor_sync(0xffffffffu, s, o);
        float mn = fmaxf(m, m2);
        s = s * __expf(m - mn) + s2 * __expf(m2 - mn);
        m = mn;
    }
    if (lane == 0) { mv[w] = m; dnv[w] = s; }
}

__global__ void k_agg(const int* __restrict__ rp, const int* __restrict__ col,
                      const float* __restrict__ hW, const float* __restrict__ es,
                      const float* __restrict__ edv, const float* __restrict__ mv,
                      const float* __restrict__ dnv, const float* __restrict__ bias,
                      float* __restrict__ out, int n) {
    int w = (blockIdx.x * blockDim.x + threadIdx.x) >> 5;
    int lane = threadIdx.x & 31;
    if (w >= n) return;
    int beg = rp[w], end = rp[w + 1];
    float ed = edv[w], md = mv[w];
    float inv = 1.f / fmaxf(dnv[w], 1e-16f);
    float a0 = 0.f, a1 = 0.f, a2 = 0.f, a3 = 0.f;
    for (int idx = beg; idx < end; idx++) {
        int s = col[idx];
        float e = es[s] + ed;
        e = e > 0.f ? e : NEG * e;
        float wgt = __expf(e - md) * inv;
        const float* hr = &hW[(size_t)s * HID];
        a0 = fmaf(wgt, hr[lane], a0);
        a1 = fmaf(wgt, hr[lane + 32], a1);
        a2 = fmaf(wgt, hr[lane + 64], a2);
        a3 = fmaf(wgt, hr[lane + 96], a3);
    }
    out[(size_t)w * HID + lane]      = fmaxf(a0 + bias[lane], 0.f);
    out[(size_t)w * HID + lane + 32] = fmaxf(a1 + bias[lane + 32], 0.f);
    out[(size_t)w * HID + lane + 64] = fmaxf(a2 + bias[lane + 64], 0.f);
    out[(size_t)w * HID + lane + 96] = fmaxf(a3 + bias[lane + 96], 0.f);
}

__global__ void k_norm(const float* __restrict__ h, float* __restrict__ nrm, int n) {
    int w = (blockIdx.x * blockDim.x + threadIdx.x) >> 5;
    int lane = threadIdx.x & 31;
    if (w >= n) return;
    const float* hr = &h[(size_t)w * HID];
    float s = 0.f;
#pragma unroll
    for (int t = 0; t < 4; t++) { float v = hr[lane + 32 * t]; s = fmaf(v, v, s); }
#pragma unroll
    for (int o = 16; o > 0; o >>= 1) s += __shfl_xor_sync(0xffffffffu, s, o);
    if (lane == 0) nrm[w] = s;
}

// ---------------- bf16 hi/lo split ----------------
__global__ void k_split(const float* __restrict__ h, __nv_bfloat16* __restrict__ hi,
                        __nv_bfloat16* __restrict__ lo, int n) {
    int i = blockIdx.x * blockDim.x + threadIdx.x;
    if (i < n) {
        float x = h[i];
        __nv_bfloat16 a = __float2bfloat16(x);
        hi[i] = a;
        lo[i] = __float2bfloat16(x - __bfloat162float(a));
    }
}

// ---------------- comparators ----------------
__device__ __forceinline__ bool d2_less(float v1, int i1, float v2, int i2) {
    return (v1 < v2) || (v1 == v2 && i1 < i2);
}
__device__ __forceinline__ void top3_upd(float v, int r, float tv[3], int ti[3]) {
    if (d2_less(v, r, tv[2], ti[2])) {
        tv[2] = v; ti[2] = r;
        if (d2_less(tv[2], ti[2], tv[1], ti[1])) {
            float a = tv[1]; int b = ti[1]; tv[1] = tv[2]; ti[1] = ti[2]; tv[2] = a; ti[2] = b;
        }
        if (d2_less(tv[1], ti[1], tv[0], ti[0])) {
            float a = tv[0]; int b = ti[0]; tv[0] = tv[1]; ti[0] = ti[1]; tv[1] = a; ti[1] = b;
        }
    }
}
__device__ __forceinline__ void top4_upd(float v, int r, float tv[4], int ti[4]) {
    if (d2_less(v, r, tv[3], ti[3])) {
        tv[3] = v; ti[3] = r;
#pragma unroll
        for (int k = 3; k > 0; k--) {
            if (d2_less(tv[k], ti[k], tv[k - 1], ti[k - 1])) {
                float a = tv[k - 1]; int b = ti[k - 1];
                tv[k - 1] = tv[k]; ti[k - 1] = ti[k];
                tv[k] = a; ti[k] = b;
            }
        }
    }
}

// ---------------- HMMA KNN candidate kernel ----------------
// grid (CTILES, RSPLIT), 256 threads (8 warps). Warp w owns collider rows
// [cb + w*16, cb + w*16 + 16). 3xbf16-split dot: AhiBhi + AhiBlo + AloBhi.
// Each thread keeps top-4 per owned collider row (2 rows) over its col subset.
#define BPITCH 136
__global__ void __launch_bounds__(256, 1) k_knn_mma(const float* __restrict__ nr2) {
    __shared__ __align__(16) __nv_bfloat16 BsH[64][BPITCH];
    __shared__ __align__(16) __nv_bfloat16 BsL[64][BPITCH];
    __shared__ float NrS[64];

    int tid = threadIdx.x;
    int l = tid & 31, w = tid >> 5;
    int cb = blockIdx.x * 128;
    int rbeg = blockIdx.y * RROWS;
    int rend = rbeg + RROWS;           // NRR divisible by RSPLIT

    // ---- A fragments (hi+lo) held in registers for whole CTA lifetime ----
    int m0 = cb + w * 16 + (l >> 2);
    int aR0 = min(m0, NCC - 1);        // clamp (stores guarded later)
    int aR1 = min(m0 + 8, NCC - 1);
    int kc = (l & 3) * 2;
    uint32_t Ah[8][4], Al[8][4];
#pragma unroll
    for (int ks = 0; ks < 8; ks++) {
        int k0 = ks * 16 + kc;
        Ah[ks][0] = *(const uint32_t*)&g_bch[(size_t)aR0 * HID + k0];
        Ah[ks][1] = *(const uint32_t*)&g_bch[(size_t)aR1 * HID + k0];
        Ah[ks][2] = *(const uint32_t*)&g_bch[(size_t)aR0 * HID + k0 + 8];
        Ah[ks][3] = *(const uint32_t*)&g_bch[(size_t)aR1 * HID + k0 + 8];
        Al[ks][0] = *(const uint32_t*)&g_bcl[(size_t)aR0 * HID + k0];
        Al[ks][1] = *(const uint32_t*)&g_bcl[(size_t)aR1 * HID + k0];
        Al[ks][2] = *(const uint32_t*)&g_bcl[(size_t)aR0 * HID + k0 + 8];
        Al[ks][3] = *(const uint32_t*)&g_bcl[(size_t)aR1 * HID + k0 + 8];
    }

    float tvA[4] = {1e30f, 1e30f, 1e30f, 1e30f};
    float tvB[4] = {1e30f, 1e30f, 1e30f, 1e30f};
    int tiA[4] = {0x7fffffff, 0x7fffffff, 0x7fffffff, 0x7fffffff};
    int tiB[4] = {0x7fffffff, 0x7fffffff, 0x7fffffff, 0x7fffffff};

    for (int rt = rbeg; rt < rend; rt += 64) {
        // ---- stage B tile (64 resting rows, hi+lo) ----
        {
            int row = tid >> 2, q = tid & 3;
            int gr = rt + row;
            bool ok = (gr < rend);
#pragma unroll
            for (int i = 0; i < 2; i++) {
                int col = q * 32 + i * 16;
                uint4 vh = make_uint4(0, 0, 0, 0), vl = vh;
                if (ok) {
                    vh = *(const uint4*)&g_brh[(size_t)gr * HID + col];
                    vl = *(const uint4*)&g_brl[(size_t)gr * HID + col];
                }
                *(uint4*)&BsH[row][col] = vh;
                *(uint4*)&BsL[row][col] = vl;
                uint4 vh2 = make_uint4(0, 0, 0, 0), vl2 = vh2;
                if (ok) {
                    vh2 = *(const uint4*)&g_brh[(size_t)gr * HID + col + 8];
                    vl2 = *(const uint4*)&g_brl[(size_t)gr * HID + col + 8];
                }
                *(uint4*)&BsH[row][col + 8] = vh2;
                *(uint4*)&BsL[row][col + 8] = vl2;
            }
            if (tid < 64) NrS[tid] = (rt + tid < rend) ? nr2[rt + tid] : 1e30f;
        }
        __syncthreads();

        // ---- mma: acc[n8][0..3] = dot for (2 rows) x (2 cols) per n8 ----
        float acc[8][4];
#pragma unroll
        for (int i = 0; i < 8; i++)
#pragma unroll
            for (int j = 0; j < 4; j++) acc[i][j] = 0.f;

#pragma unroll
        for (int ks = 0; ks < 8; ks++) {
            int kb = ks * 16 + kc;
#pragma unroll
            for (int n8 = 0; n8 < 8; n8++) {
                int n = n8 * 8 + (l >> 2);
                uint32_t bh0 = *(const uint32_t*)&BsH[n][kb];
                uint32_t bh1 = *(const uint32_t*)&BsH[n][kb + 8];
                uint32_t bl0 = *(const uint32_t*)&BsL[n][kb];
                uint32_t bl1 = *(const uint32_t*)&BsL[n][kb + 8];
                MMA16816(acc[n8], Ah[ks], bh0, bh1);
                MMA16816(acc[n8], Ah[ks], bl0, bl1);
                MMA16816(acc[n8], Al[ks], bh0, bh1);
            }
        }

        // ---- epilogue: key = nr2[r] - 2*dot, per-row top-4 ----
#pragma unroll
        for (int n8 = 0; n8 < 8; n8++) {
            int c0 = n8 * 8 + (l & 3) * 2;
            int r = rt + c0;
            float n0 = NrS[c0], n1 = NrS[c0 + 1];
            top4_upd(n0 - 2.f * acc[n8][0], r, tvA, tiA);
            top4_upd(n1 - 2.f * acc[n8][1], r + 1, tvA, tiA);
            top4_upd(n0 - 2.f * acc[n8][2], r, tvB, tiB);
            top4_upd(n1 - 2.f * acc[n8][3], r + 1, tvB, tiB);
        }
        __syncthreads();
    }

    // ---- store candidates: 16 per (split, collider) ----
    int cA = cb + w * 16 + (l >> 2);
    int cB = cA + 8;
    if (cA < NCC) {
        size_t base = ((size_t)blockIdx.y * NCC + cA) * NCAND + (l & 3) * 4;
#pragma unroll
        for (int k = 0; k < 4; k++) g_ci[base + k] = tiA[k];
    }
    if (cB < NCC) {
        size_t base = ((size_t)blockIdx.y * NCC + cB) * NCAND + (l & 3) * 4;
#pragma unroll
        for (int k = 0; k < 4; k++) g_ci[base + k] = tiB[k];
    }
}

// ---------------- exact fp32 rescore of 128 candidates, top-3 ----------------
__global__ void k_rescore(const float* __restrict__ hc, const float* __restrict__ hr,
                          const float* __restrict__ nr2) {
    int w = (blockIdx.x * blockDim.x + threadIdx.x) >> 5;
    int lane = threadIdx.x & 31;
    if (w >= NCC) return;
    float c0 = hc[(size_t)w * HID + lane];
    float c1 = hc[(size_t)w * HID + lane + 32];
    float c2 = hc[(size_t)w * HID + lane + 64];
    float c3 = hc[(size_t)w * HID + lane + 96];
    float f[3] = {1e30f, 1e30f, 1e30f};
    int   j[3] = {0x7fffffff, 0x7fffffff, 0x7fffffff};
    for (int s = 0; s < RSPLIT; s++) {
        size_t base = ((size_t)s * NCC + w) * NCAND;
        for (int k = 0; k < NCAND; k++) {
            int r = g_ci[base + k];
            if ((unsigned)r >= (unsigned)NRR) continue;
            const float* hrr = &hr[(size_t)r * HID];
            float p = 0.f;
            p = fmaf(c0, hrr[lane], p);
            p = fmaf(c1, hrr[lane + 32], p);
            p = fmaf(c2, hrr[lane + 64], p);
            p = fmaf(c3, hrr[lane + 96], p);
#pragma unroll
            for (int o = 16; o > 0; o >>= 1) p += __shfl_xor_sync(0xffffffffu, p, o);
            if (lane == 0) {
                float key = nr2[r] - 2.f * p;
                top3_upd(key, r, f, j);
            }
        }
    }
    if (lane == 0) {
        g_nn[w * 3 + 0] = j[0];
        g_nn[w * 3 + 1] = j[1];
        g_nn[w * 3 + 2] = j[2];
    }
}

// ---------------- scatter-mean pooling ----------------
__global__ void k_pool(const float* __restrict__ hc) {
    int w = (blockIdx.x * blockDim.x + threadIdx.x) >> 5;
    int lane = threadIdx.x & 31;
    if (w >= NCC) return;
    const float* hr = &hc[(size_t)w * HID];
    float v0 = hr[lane], v1 = hr[lane + 32], v2 = hr[lane + 64], v3 = hr[lane + 96];
#pragma unroll
    for (int k = 0; k < KNN; k++) {
        int nn = g_nn[w * 3 + k];
        atomicAdd(&g_pool[(size_t)nn * HID + lane], v0);
        atomicAdd(&g_pool[(size_t)nn * HID + lane + 32], v1);
        atomicAdd(&g_pool[(size_t)nn * HID + lane + 64], v2);
        atomicAdd(&g_pool[(size_t)nn * HID + lane + 96], v3);
        if (lane == 0) atomicAdd(&g_pcnt[nn], 1);
    }
}

// ---------------- decoder ----------------
__global__ void k_dec(const float* __restrict__ hr, const float* __restrict__ Wd,
                      const float* __restrict__ bd, float* __restrict__ out) {
    int w = (blockIdx.x * blockDim.x + threadIdx.x) >> 5;
    int lane = threadIdx.x & 31;
    if (w >= NRR) return;
    float inv = 1.f / fmaxf((float)g_pcnt[w], 1.f);
    float a0 = 0.f, a1 = 0.f, a2 = 0.f;
#pragma unroll
    for (int t = 0; t < 4; t++) {
        int j = lane + 32 * t;
        float hv = hr[(size_t)w * HID + j];
        float pv = g_pool[(size_t)w * HID + j] * inv;
        a0 = fmaf(hv, Wd[j * 3 + 0], a0); a0 = fmaf(pv, Wd[(HID + j) * 3 + 0], a0);
        a1 = fmaf(hv, Wd[j * 3 + 1], a1); a1 = fmaf(pv, Wd[(HID + j) * 3 + 1], a1);
        a2 = fmaf(hv, Wd[j * 3 + 2], a2); a2 = fmaf(pv, Wd[(HID + j) * 3 + 2], a2);
    }
#pragma unroll
    for (int o = 16; o > 0; o >>= 1) {
        a0 += __shfl_xor_sync(0xffffffffu, a0, o);
        a1 += __shfl_xor_sync(0xffffffffu, a1, o);
        a2 += __shfl_xor_sync(0xffffffffu, a2, o);
    }
    if (lane == 0) {
        out[w * 3 + 0] = a0 + bd[0];
        out[w * 3 + 1] = a1 + bd[1];
        out[w * 3 + 2] = a2 + bd[2];
    }
}

// ---------------- host launcher ----------------
extern "C" void kernel_launch(void* const* d_in, const int* in_sizes, int n_in,
                              void* d_out, int out_size) {
    const float* x_r  = (const float*)d_in[0];
    const float* x_c  = (const float*)d_in[1];
    const int*   ei_r = (const int*)d_in[2];
    const int*   ei_c = (const int*)d_in[3];
    const float* W_r1  = (const float*)d_in[5];
    const float* as_r1 = (const float*)d_in[6];
    const float* ad_r1 = (const float*)d_in[7];
    const float* b_r1  = (const float*)d_in[8];
    const float* W_r2  = (const float*)d_in[9];
    const float* as_r2 = (const float*)d_in[10];
    const float* ad_r2 = (const float*)d_in[11];
    const float* b_r2  = (const float*)d_in[12];
    const float* W_c1  = (const float*)d_in[13];
    const float* as_c1 = (const float*)d_in[14];
    const float* ad_c1 = (const float*)d_in[15];
    const float* b_c1  = (const float*)d_in[16];
    const float* W_c2  = (const float*)d_in[17];
    const float* as_c2 = (const float*)d_in[18];
    const float* ad_c2 = (const float*)d_in[19];
    const float* b_c2  = (const float*)d_in[20];
    const float* W_dec = (const float*)d_in[21];
    const float* b_dec = (const float*)d_in[22];
    float* out = (float*)d_out;

    float *hw_r, *h1_r, *h2_r, *hw_c, *h1_c, *h2_c, *es, *ed, *mv, *dn, *nr2;
    int *cnt_r, *cur_r, *rp_r, *col_r, *cnt_c, *cur_c, *rp_c, *col_c;
    __nv_bfloat16 *bch, *bcl, *brh, *brl;
    cudaGetSymbolAddress((void**)&hw_r, g_hw_r);
    cudaGetSymbolAddress((void**)&h1_r, g_h1_r);
    cudaGetSymbolAddress((void**)&h2_r, g_h2_r);
    cudaGetSymbolAddress((void**)&hw_c, g_hw_c);
    cudaGetSymbolAddress((void**)&h1_c, g_h1_c);
    cudaGetSymbolAddress((void**)&h2_c, g_h2_c);
    cudaGetSymbolAddress((void**)&es, g_es);
    cudaGetSymbolAddress((void**)&ed, g_ed);
    cudaGetSymbolAddress((void**)&mv, g_mm);
    cudaGetSymbolAddress((void**)&dn, g_dn);
    cudaGetSymbolAddress((void**)&nr2, g_nr2);
    cudaGetSymbolAddress((void**)&cnt_r, g_cnt_r);
    cudaGetSymbolAddress((void**)&cur_r, g_cur_r);
    cudaGetSymbolAddress((void**)&rp_r, g_rp_r);
    cudaGetSymbolAddress((void**)&col_r, g_col_r);
    cudaGetSymbolAddress((void**)&cnt_c, g_cnt_c);
    cudaGetSymbolAddress((void**)&cur_c, g_cur_c);
    cudaGetSymbolAddress((void**)&rp_c, g_rp_c);
    cudaGetSymbolAddress((void**)&col_c, g_col_c);
    cudaGetSymbolAddress((void**)&bch, g_bch);
    cudaGetSymbolAddress((void**)&bcl, g_bcl);
    cudaGetSymbolAddress((void**)&brh, g_brh);
    cudaGetSymbolAddress((void**)&brl, g_brl);

    k_init<<<1024, 256>>>();

    k_count<<<(ERR + 255) / 256, 256>>>(ei_r + ERR, ERR, cnt_r);
    k_count<<<(ECC + 255) / 256, 256>>>(ei_c + ECC, ECC, cnt_c);
    k_scan<<<1, 1024>>>(cnt_r, rp_r, NRR);
    k_scan<<<1, 1024>>>(cnt_c, rp_c, NCC);
    k_scatter<<<(ERR + 255) / 256, 256>>>(ei_r, ei_r + ERR, ERR, rp_r, cur_r, col_r);
    k_scatter<<<(ECC + 255) / 256, 256>>>(ei_c, ei_c + ECC, ECC, rp_c, cur_c, col_c);
    k_selfloop<<<(NRR + 255) / 256, 256>>>(rp_r, col_r, NRR);
    k_selfloop<<<(NCC + 255) / 256, 256>>>(rp_c, col_c, NCC);

    const int WGR = (NRR + 7) / 8;
    const int WGC = (NCC + 7) / 8;

    // resting branch
    k_lin1<<<WGR, 256>>>(x_r, W_r1, as_r1, ad_r1, hw_r, es, ed, NRR);
    k_stats<<<WGR, 256>>>(rp_r, col_r, es, ed, mv, dn, NRR);
    k_agg<<<WGR, 256>>>(rp_r, col_r, hw_r, es, ed, mv, dn, b_r1, h1_r, NRR);
    k_gemm128<<<(NRR + 63) / 64, 256>>>(h1_r, W_r2, hw_r, NRR);
    k_dots<<<WGR, 256>>>(hw_r, as_r2, ad_r2, es, ed, NRR);
    k_stats<<<WGR, 256>>>(rp_r, col_r, es, ed, mv, dn, NRR);
    k_agg<<<WGR, 256>>>(rp_r, col_r, hw_r, es, ed, mv, dn, b_r2, h2_r, NRR);

    // collider branch
    k_lin1<<<WGC, 256>>>(x_c, W_c1, as_c1, ad_c1, hw_c, es, ed, NCC);
    k_stats<<<WGC, 256>>>(rp_c, col_c, es, ed, mv, dn, NCC);
    k_agg<<<WGC, 256>>>(rp_c, col_c, hw_c, es, ed, mv, dn, b_c1, h1_c, NCC);
    k_gemm128<<<(NCC + 63) / 64, 256>>>(h1_c, W_c2, hw_c, NCC);
    k_dots<<<WGC, 256>>>(hw_c, as_c2, ad_c2, es, ed, NCC);
    k_stats<<<WGC, 256>>>(rp_c, col_c, es, ed, mv, dn, NCC);
    k_agg<<<WGC, 256>>>(rp_c, col_c, hw_c, es, ed, mv, dn, b_c2, h2_c, NCC);

    // KNN: bf16 split -> HMMA candidates -> exact fp32 rescore
    k_norm<<<WGR, 256>>>(h2_r, nr2, NRR);
    k_split<<<(NRR * HID + 255) / 256, 256>>>(h2_r, brh, brl, NRR * HID);
    k_split<<<(NCC * HID + 255) / 256, 256>>>(h2_c, bch, bcl, NCC * HID);
    dim3 kg(CTILES, RSPLIT);
    k_knn_mma<<<kg, 256>>>(nr2);
    k_rescore<<<(NCC * 32 + 255) / 256, 256>>>(h2_c, h2_r, nr2);
    k_pool<<<WGC, 256>>>(h2_c);
    k_dec<<<WGR, 256>>>(h2_r, W_dec, b_dec, out);
}

// round 7
// speedup vs baseline: 2.7381x; 1.1910x over previous
#include <cuda_runtime.h>
#include <cuda_bf16.h>
#include <math.h>
#include <cstdint>

// ---------------- problem constants ----------------
#define NRR 20000
#define NCC 5000
#define ERR 320000
#define ECC 80000
#define DIN 6
#define HID 128
#define KNN 3
#define NEG 0.2f

#define CTILES 40        // ceil(NCC/128)
#define RSPLIT 8
#define RROWS 2500       // NRR / RSPLIT (exact)
#define NCAND 16         // candidates per (split, collider): 4 quad threads x top-4

// ---------------- mma.sync m16n8k16 bf16 ----------------
#define MMA16816(c, a, b0, b1) \
    asm volatile("mma.sync.aligned.m16n8k16.row.col.f32.bf16.bf16.f32 " \
        "{%0,%1,%2,%3}, {%4,%5,%6,%7}, {%8,%9}, {%0,%1,%2,%3};" \
        : "+f"((c)[0]), "+f"((c)[1]), "+f"((c)[2]), "+f"((c)[3]) \
        : "r"((a)[0]), "r"((a)[1]), "r"((a)[2]), "r"((a)[3]), "r"(b0), "r"(b1))

// ---------------- static scratch ----------------
__device__ float g_hw_r[NRR * HID];
__device__ float g_h1_r[NRR * HID];
__device__ float g_h2_r[NRR * HID];
__device__ float g_hw_c[NCC * HID];
__device__ float g_h1_c[NCC * HID];
__device__ float g_h2_c[NCC * HID];
__device__ float g_es[NRR];
__device__ float g_ed[NRR];
__device__ float g_mm[NRR];
__device__ float g_dn[NRR];
__device__ int   g_cnt_r[NRR];
__device__ int   g_cur_r[NRR];
__device__ int   g_rp_r[NRR + 1];
__device__ int   g_col_r[ERR + NRR];
__device__ int   g_cnt_c[NCC];
__device__ int   g_cur_c[NCC];
__device__ int   g_rp_c[NCC + 1];
__device__ int   g_col_c[ECC + NCC];
__device__ float g_nr2[NRR];
__device__ __nv_bfloat16 g_bch[NCC * HID];
__device__ __nv_bfloat16 g_bcl[NCC * HID];
__device__ __nv_bfloat16 g_brh[NRR * HID];
__device__ __nv_bfloat16 g_brl[NRR * HID];
__device__ int   g_ci[RSPLIT * NCC * NCAND];
__device__ int   g_nn[NCC * KNN];
__device__ float g_pool[NRR * HID];
__device__ int   g_pcnt[NRR];

// ---------------- init ----------------
__global__ void k_init() {
    int i = blockIdx.x * blockDim.x + threadIdx.x;
    int st = gridDim.x * blockDim.x;
    for (int t = i; t < NRR * HID; t += st) g_pool[t] = 0.f;
    for (int t = i; t < NRR; t += st) { g_cnt_r[t] = 1; g_cur_r[t] = 0; g_pcnt[t] = 0; }
    for (int t = i; t < NCC; t += st) { g_cnt_c[t] = 1; g_cur_c[t] = 0; }
}

// ---------------- CSR build ----------------
__global__ void k_count(const int* __restrict__ dst, int E, int* __restrict__ cnt) {
    int i = blockIdx.x * blockDim.x + threadIdx.x;
    if (i < E) atomicAdd(&cnt[dst[i]], 1);
}
__global__ void k_scan(const int* __restrict__ cnt, int* __restrict__ rp, int n) {
    __shared__ int part[1024];
    int t = threadIdx.x;
    int chunk = (n + 1023) / 1024;
    int beg = t * chunk, end = min(n, beg + chunk);
    int s = 0;
    for (int i = beg; i < end; i++) s += cnt[i];
    part[t] = s;
    __syncthreads();
    for (int off = 1; off < 1024; off <<= 1) {
        int v = (t >= off) ? part[t - off] : 0;
        __syncthreads();
        part[t] += v;
        __syncthreads();
    }
    int run = part[t] - s;
    for (int i = beg; i < end; i++) { rp[i] = run; run += cnt[i]; }
    if (t == 1023) rp[n] = part[1023];
}
__global__ void k_scatter(const int* __restrict__ src, const int* __restrict__ dst, int E,
                          const int* __restrict__ rp, int* __restrict__ cur, int* __restrict__ colarr) {
    int i = blockIdx.x * blockDim.x + threadIdx.x;
    if (i < E) {
        int d = dst[i];
        int pos = rp[d] + atomicAdd(&cur[d], 1);
        colarr[pos] = src[i];
    }
}
__global__ void k_selfloop(const int* __restrict__ rp, int* __restrict__ colarr, int n) {
    int i = blockIdx.x * blockDim.x + threadIdx.x;
    if (i < n) colarr[rp[i + 1] - 1] = i;
}

// ---------------- GAT stages (R1-proven) ----------------
__global__ void k_lin1(const float* __restrict__ x, const float* __restrict__ W,
                       const float* __restrict__ as_, const float* __restrict__ ad_,
                       float* __restrict__ h, float* __restrict__ es, float* __restrict__ ed, int n) {
    int w = (blockIdx.x * blockDim.x + threadIdx.x) >> 5;
    int lane = threadIdx.x & 31;
    if (w >= n) return;
    float xv[DIN];
#pragma unroll
    for (int k = 0; k < DIN; k++) xv[k] = x[w * DIN + k];
    float hv[4], ps = 0.f, pd = 0.f;
#pragma unroll
    for (int q = 0; q < 4; q++) {
        int j = lane * 4 + q;
        float a = 0.f;
#pragma unroll
        for (int k = 0; k < DIN; k++) a = fmaf(xv[k], W[k * HID + j], a);
        hv[q] = a;
        ps = fmaf(a, as_[j], ps);
        pd = fmaf(a, ad_[j], pd);
    }
    *(float4*)&h[(size_t)w * HID + lane * 4] = make_float4(hv[0], hv[1], hv[2], hv[3]);
#pragma unroll
    for (int o = 16; o > 0; o >>= 1) {
        ps += __shfl_xor_sync(0xffffffffu, ps, o);
        pd += __shfl_xor_sync(0xffffffffu, pd, o);
    }
    if (lane == 0) { es[w] = ps; ed[w] = pd; }
}

__global__ void __launch_bounds__(256) k_gemm128(const float* __restrict__ A,
                                                 const float* __restrict__ B,
                                                 float* __restrict__ C, int M) {
    __shared__ float As[16][64];
    __shared__ float Bs[16][128];
    int tid = threadIdx.x;
    int tc = tid & 31, tr = tid >> 5;
    int row0 = blockIdx.x * 64;
    float acc[8][4];
#pragma unroll
    for (int i = 0; i < 8; i++)
#pragma unroll
        for (int j = 0; j < 4; j++) acc[i][j] = 0.f;
    for (int k0 = 0; k0 < HID; k0 += 16) {
        int row_l = tid >> 2, quad = tid & 3;
        int gr = row0 + row_l;
        float4 av = make_float4(0.f, 0.f, 0.f, 0.f);
        if (gr < M) av = *(const float4*)&A[(size_t)gr * HID + k0 + quad * 4];
        As[quad * 4 + 0][row_l] = av.x;
        As[quad * 4 + 1][row_l] = av.y;
        As[quad * 4 + 2][row_l] = av.z;
        As[quad * 4 + 3][row_l] = av.w;
        int kk = tid >> 4, cp = tid & 15;
        float4 bv0 = *(const float4*)&B[(size_t)(k0 + kk) * HID + cp * 8];
        float4 bv1 = *(const float4*)&B[(size_t)(k0 + kk) * HID + cp * 8 + 4];
        *(float4*)&Bs[kk][cp * 8] = bv0;
        *(float4*)&Bs[kk][cp * 8 + 4] = bv1;
        __syncthreads();
#pragma unroll
        for (int k2 = 0; k2 < 16; k2++) {
            float4 a0 = *(float4*)&As[k2][tr * 8];
            float4 a1 = *(float4*)&As[k2][tr * 8 + 4];
            float4 bb = *(float4*)&Bs[k2][tc * 4];
            float a[8] = {a0.x, a0.y, a0.z, a0.w, a1.x, a1.y, a1.z, a1.w};
            float b[4] = {bb.x, bb.y, bb.z, bb.w};
#pragma unroll
            for (int i = 0; i < 8; i++)
#pragma unroll
                for (int j = 0; j < 4; j++) acc[i][j] = fmaf(a[i], b[j], acc[i][j]);
        }
        __syncthreads();
    }
#pragma unroll
    for (int i = 0; i < 8; i++) {
        int r = row0 + tr * 8 + i;
        if (r < M)
            *(float4*)&C[(size_t)r * HID + tc * 4] =
                make_float4(acc[i][0], acc[i][1], acc[i][2], acc[i][3]);
    }
}

__global__ void k_dots(const float* __restrict__ h, const float* __restrict__ as_,
                       const float* __restrict__ ad_, float* __restrict__ es,
                       float* __restrict__ ed, int n) {
    int w = (blockIdx.x * blockDim.x + threadIdx.x) >> 5;
    int lane = threadIdx.x & 31;
    if (w >= n) return;
    const float* hr = &h[(size_t)w * HID];
    float ps = 0.f, pd = 0.f;
#pragma unroll
    for (int t = 0; t < 4; t++) {
        int j = lane + 32 * t;
        float v = hr[j];
        ps = fmaf(v, as_[j], ps);
        pd = fmaf(v, ad_[j], pd);
    }
#pragma unroll
    for (int o = 16; o > 0; o >>= 1) {
        ps += __shfl_xor_sync(0xffffffffu, ps, o);
        pd += __shfl_xor_sync(0xffffffffu, pd, o);
    }
    if (lane == 0) { es[w] = ps; ed[w] = pd; }
}

__global__ void k_stats(const int* __restrict__ rp, const int* __restrict__ col,
                        const float* __restrict__ es, const float* __restrict__ edv,
                        float* __restrict__ mv, float* __restrict__ dnv, int n) {
    int w = (blockIdx.x * blockDim.x + threadIdx.x) >> 5;
    int lane = threadIdx.x & 31;
    if (w >= n) return;
    int beg = rp[w], end = rp[w + 1];
    float ed = edv[w];
    float m = -1e30f, s = 0.f;
    for (int idx = beg + lane; idx < end; idx += 32) {
        float e = es[col[idx]] + ed;
        e = e > 0.f ? e : NEG * e;
        float mn = fmaxf(m, e);
        s = s * __expf(m - mn) + __expf(e - mn);
        m = mn;
    }
#pragma unroll
    for (int o = 16; o > 0; o >>= 1) {
        float m2 = __shfl_xor_sync(0xffffffffu, m, o);
        float s2 = __shfl_xor_sync(0xffffffffu, s, o);
        float mn = fmaxf(m, m2);
        s = s * __expf(m - mn) + s2 * __expf(m2 - mn);
        m = mn;
    }
    if (lane == 0) { mv[w] = m; dnv[w] = s; }
}

__global__ void k_agg(const int* __restrict__ rp, const int* __restrict__ col,
                      const float* __restrict__ hW, const float* __restrict__ es,
                      const float* __restrict__ edv, const float* __restrict__ mv,
                      const float* __restrict__ dnv, const float* __restrict__ bias,
                      float* __restrict__ out, int n) {
    int w = (blockIdx.x * blockDim.x + threadIdx.x) >> 5;
    int lane = threadIdx.x & 31;
    if (w >= n) return;
    int beg = rp[w], end = rp[w + 1];
    float ed = edv[w], md = mv[w];
    float inv = 1.f / fmaxf(dnv[w], 1e-16f);
    float a0 = 0.f, a1 = 0.f, a2 = 0.f, a3 = 0.f;
    for (int idx = beg; idx < end; idx++) {
        int s = col[idx];
        float e = es[s] + ed;
        e = e > 0.f ? e : NEG * e;
        float wgt = __expf(e - md) * inv;
        const float* hr = &hW[(size_t)s * HID];
        a0 = fmaf(wgt, hr[lane], a0);
        a1 = fmaf(wgt, hr[lane + 32], a1);
        a2 = fmaf(wgt, hr[lane + 64], a2);
        a3 = fmaf(wgt, hr[lane + 96], a3);
    }
    out[(size_t)w * HID + lane]      = fmaxf(a0 + bias[lane], 0.f);
    out[(size_t)w * HID + lane + 32] = fmaxf(a1 + bias[lane + 32], 0.f);
    out[(size_t)w * HID + lane + 64] = fmaxf(a2 + bias[lane + 64], 0.f);
    out[(size_t)w * HID + lane + 96] = fmaxf(a3 + bias[lane + 96], 0.f);
}

__global__ void k_norm(const float* __restrict__ h, float* __restrict__ nrm, int n) {
    int w = (blockIdx.x * blockDim.x + threadIdx.x) >> 5;
    int lane = threadIdx.x & 31;
    if (w >= n) return;
    const float* hr = &h[(size_t)w * HID];
    float s = 0.f;
#pragma unroll
    for (int t = 0; t < 4; t++) { float v = hr[lane + 32 * t]; s = fmaf(v, v, s); }
#pragma unroll
    for (int o = 16; o > 0; o >>= 1) s += __shfl_xor_sync(0xffffffffu, s, o);
    if (lane == 0) nrm[w] = s;
}

// ---------------- bf16 hi/lo split ----------------
__global__ void k_split(const float* __restrict__ h, __nv_bfloat16* __restrict__ hi,
                        __nv_bfloat16* __restrict__ lo, int n) {
    int i = blockIdx.x * blockDim.x + threadIdx.x;
    if (i < n) {
        float x = h[i];
        __nv_bfloat16 a = __float2bfloat16(x);
        hi[i] = a;
        lo[i] = __float2bfloat16(x - __bfloat162float(a));
    }
}

// ---------------- comparators ----------------
__device__ __forceinline__ bool d2_less(float v1, int i1, float v2, int i2) {
    return (v1 < v2) || (v1 == v2 && i1 < i2);
}
__device__ __forceinline__ void top3_upd(float v, int r, float tv[3], int ti[3]) {
    if (d2_less(v, r, tv[2], ti[2])) {
        tv[2] = v; ti[2] = r;
        if (d2_less(tv[2], ti[2], tv[1], ti[1])) {
            float a = tv[1]; int b = ti[1]; tv[1] = tv[2]; ti[1] = ti[2]; tv[2] = a; ti[2] = b;
        }
        if (d2_less(tv[1], ti[1], tv[0], ti[0])) {
            float a = tv[0]; int b = ti[0]; tv[0] = tv[1]; ti[0] = ti[1]; tv[1] = a; ti[1] = b;
        }
    }
}
__device__ __forceinline__ void top4_upd(float v, int r, float tv[4], int ti[4]) {
    if (d2_less(v, r, tv[3], ti[3])) {
        tv[3] = v; ti[3] = r;
#pragma unroll
        for (int k = 3; k > 0; k--) {
            if (d2_less(tv[k], ti[k], tv[k - 1], ti[k - 1])) {
                float a = tv[k - 1]; int b = ti[k - 1];
                tv[k - 1] = tv[k]; ti[k - 1] = ti[k];
                tv[k] = a; ti[k] = b;
            }
        }
    }
}

// ---------------- HMMA KNN candidate kernel (occ-2 variant) ----------------
// grid (CTILES, RSPLIT), 256 threads (8 warps). Warp w owns collider rows
// [cb + w*16, cb + w*16 + 16). 3xbf16-split dot: AhiBhi + AhiBlo + AloBhi.
// n8-pair-outer / ks-inner: only 8 accumulator regs live -> 2 CTAs/SM.
#define BPITCH 136
__global__ void __launch_bounds__(256, 2) k_knn_mma(const float* __restrict__ nr2) {
    __shared__ __align__(16) __nv_bfloat16 BsH[64][BPITCH];
    __shared__ __align__(16) __nv_bfloat16 BsL[64][BPITCH];
    __shared__ float NrS[64];

    int tid = threadIdx.x;
    int l = tid & 31, w = tid >> 5;
    int cb = blockIdx.x * 128;
    int rbeg = blockIdx.y * RROWS;
    int rend = rbeg + RROWS;           // NRR divisible by RSPLIT

    // ---- A fragments (hi+lo) held in registers for whole CTA lifetime ----
    int m0 = cb + w * 16 + (l >> 2);
    int aR0 = min(m0, NCC - 1);
    int aR1 = min(m0 + 8, NCC - 1);
    int kc = (l & 3) * 2;
    uint32_t Ah[8][4], Al[8][4];
#pragma unroll
    for (int ks = 0; ks < 8; ks++) {
        int k0 = ks * 16 + kc;
        Ah[ks][0] = *(const uint32_t*)&g_bch[(size_t)aR0 * HID + k0];
        Ah[ks][1] = *(const uint32_t*)&g_bch[(size_t)aR1 * HID + k0];
        Ah[ks][2] = *(const uint32_t*)&g_bch[(size_t)aR0 * HID + k0 + 8];
        Ah[ks][3] = *(const uint32_t*)&g_bch[(size_t)aR1 * HID + k0 + 8];
        Al[ks][0] = *(const uint32_t*)&g_bcl[(size_t)aR0 * HID + k0];
        Al[ks][1] = *(const uint32_t*)&g_bcl[(size_t)aR1 * HID + k0];
        Al[ks][2] = *(const uint32_t*)&g_bcl[(size_t)aR0 * HID + k0 + 8];
        Al[ks][3] = *(const uint32_t*)&g_bcl[(size_t)aR1 * HID + k0 + 8];
    }

    float tvA[4] = {1e30f, 1e30f, 1e30f, 1e30f};
    float tvB[4] = {1e30f, 1e30f, 1e30f, 1e30f};
    int tiA[4] = {0x7fffffff, 0x7fffffff, 0x7fffffff, 0x7fffffff};
    int tiB[4] = {0x7fffffff, 0x7fffffff, 0x7fffffff, 0x7fffffff};

    for (int rt = rbeg; rt < rend; rt += 64) {
        // ---- stage B tile (64 resting rows, hi+lo) ----
        {
            int row = tid >> 2, q = tid & 3;
            int gr = rt + row;
            bool ok = (gr < rend);
#pragma unroll
            for (int i = 0; i < 2; i++) {
                int col = q * 32 + i * 16;
                uint4 vh = make_uint4(0, 0, 0, 0), vl = vh;
                if (ok) {
                    vh = *(const uint4*)&g_brh[(size_t)gr * HID + col];
                    vl = *(const uint4*)&g_brl[(size_t)gr * HID + col];
                }
                *(uint4*)&BsH[row][col] = vh;
                *(uint4*)&BsL[row][col] = vl;
                uint4 vh2 = make_uint4(0, 0, 0, 0), vl2 = vh2;
                if (ok) {
                    vh2 = *(const uint4*)&g_brh[(size_t)gr * HID + col + 8];
                    vl2 = *(const uint4*)&g_brl[(size_t)gr * HID + col + 8];
                }
                *(uint4*)&BsH[row][col + 8] = vh2;
                *(uint4*)&BsL[row][col + 8] = vl2;
            }
            if (tid < 64) NrS[tid] = (rt + tid < rend) ? nr2[rt + tid] : 1e30f;
        }
        __syncthreads();

        // ---- mma: n8-pair outer, ks inner; two independent chains/thread ----
#pragma unroll
        for (int np = 0; np < 4; np++) {
            int nA = (np * 2) * 8 + (l >> 2);
            int nB = (np * 2 + 1) * 8 + (l >> 2);
            float acc0[4] = {0.f, 0.f, 0.f, 0.f};
            float acc1[4] = {0.f, 0.f, 0.f, 0.f};
#pragma unroll
            for (int ks = 0; ks < 8; ks++) {
                int kb = ks * 16 + kc;
                uint32_t bh0a = *(const uint32_t*)&BsH[nA][kb];
                uint32_t bh1a = *(const uint32_t*)&BsH[nA][kb + 8];
                uint32_t bl0a = *(const uint32_t*)&BsL[nA][kb];
                uint32_t bl1a = *(const uint32_t*)&BsL[nA][kb + 8];
                uint32_t bh0b = *(const uint32_t*)&BsH[nB][kb];
                uint32_t bh1b = *(const uint32_t*)&BsH[nB][kb + 8];
                uint32_t bl0b = *(const uint32_t*)&BsL[nB][kb];
                uint32_t bl1b = *(const uint32_t*)&BsL[nB][kb + 8];
                MMA16816(acc0, Ah[ks], bh0a, bh1a);
                MMA16816(acc1, Ah[ks], bh0b, bh1b);
                MMA16816(acc0, Ah[ks], bl0a, bl1a);
                MMA16816(acc1, Ah[ks], bl0b, bl1b);
                MMA16816(acc0, Al[ks], bh0a, bh1a);
                MMA16816(acc1, Al[ks], bh0b, bh1b);
            }
            // ---- epilogue for these two n8 groups ----
            int c0a = (np * 2) * 8 + (l & 3) * 2;
            int c0b = (np * 2 + 1) * 8 + (l & 3) * 2;
            int ra = rt + c0a, rb2 = rt + c0b;
            float na0 = NrS[c0a], na1 = NrS[c0a + 1];
            float nb0 = NrS[c0b], nb1 = NrS[c0b + 1];
            top4_upd(na0 - 2.f * acc0[0], ra, tvA, tiA);
            top4_upd(na1 - 2.f * acc0[1], ra + 1, tvA, tiA);
            top4_upd(na0 - 2.f * acc0[2], ra, tvB, tiB);
            top4_upd(na1 - 2.f * acc0[3], ra + 1, tvB, tiB);
            top4_upd(nb0 - 2.f * acc1[0], rb2, tvA, tiA);
            top4_upd(nb1 - 2.f * acc1[1], rb2 + 1, tvA, tiA);
            top4_upd(nb0 - 2.f * acc1[2], rb2, tvB, tiB);
            top4_upd(nb1 - 2.f * acc1[3], rb2 + 1, tvB, tiB);
        }
        __syncthreads();
    }

    // ---- store candidates: 16 per (split, collider) ----
    int cA = cb + w * 16 + (l >> 2);
    int cB = cA + 8;
    if (cA < NCC) {
        size_t base = ((size_t)blockIdx.y * NCC + cA) * NCAND + (l & 3) * 4;
#pragma unroll
        for (int k = 0; k < 4; k++) g_ci[base + k] = tiA[k];
    }
    if (cB < NCC) {
        size_t base = ((size_t)blockIdx.y * NCC + cB) * NCAND + (l & 3) * 4;
#pragma unroll
        for (int k = 0; k < 4; k++) g_ci[base + k] = tiB[k];
    }
}

// ---------------- exact fp32 rescore of 128 candidates, top-3 ----------------
__global__ void k_rescore(const float* __restrict__ hc, const float* __restrict__ hr,
                          const float* __restrict__ nr2) {
    int w = (blockIdx.x * blockDim.x + threadIdx.x) >> 5;
    int lane = threadIdx.x & 31;
    if (w >= NCC) return;
    float c0 = hc[(size_t)w * HID + lane];
    float c1 = hc[(size_t)w * HID + lane + 32];
    float c2 = hc[(size_t)w * HID + lane + 64];
    float c3 = hc[(size_t)w * HID + lane + 96];
    float f[3] = {1e30f, 1e30f, 1e30f};
    int   j[3] = {0x7fffffff, 0x7fffffff, 0x7fffffff};
    for (int s = 0; s < RSPLIT; s++) {
        size_t base = ((size_t)s * NCC + w) * NCAND;
        for (int k = 0; k < NCAND; k++) {
            int r = g_ci[base + k];
            if ((unsigned)r >= (unsigned)NRR) continue;
            const float* hrr = &hr[(size_t)r * HID];
            float p = 0.f;
            p = fmaf(c0, hrr[lane], p);
            p = fmaf(c1, hrr[lane + 32], p);
            p = fmaf(c2, hrr[lane + 64], p);
            p = fmaf(c3, hrr[lane + 96], p);
#pragma unroll
            for (int o = 16; o > 0; o >>= 1) p += __shfl_xor_sync(0xffffffffu, p, o);
            if (lane == 0) {
                float key = nr2[r] - 2.f * p;
                top3_upd(key, r, f, j);
            }
        }
    }
    if (lane == 0) {
        g_nn[w * 3 + 0] = j[0];
        g_nn[w * 3 + 1] = j[1];
        g_nn[w * 3 + 2] = j[2];
    }
}

// ---------------- scatter-mean pooling ----------------
__global__ void k_pool(const float* __restrict__ hc) {
    int w = (blockIdx.x * blockDim.x + threadIdx.x) >> 5;
    int lane = threadIdx.x & 31;
    if (w >= NCC) return;
    const float* hr = &hc[(size_t)w * HID];
    float v0 = hr[lane], v1 = hr[lane + 32], v2 = hr[lane + 64], v3 = hr[lane + 96];
#pragma unroll
    for (int k = 0; k < KNN; k++) {
        int nn = g_nn[w * 3 + k];
        atomicAdd(&g_pool[(size_t)nn * HID + lane], v0);
        atomicAdd(&g_pool[(size_t)nn * HID + lane + 32], v1);
        atomicAdd(&g_pool[(size_t)nn * HID + lane + 64], v2);
        atomicAdd(&g_pool[(size_t)nn * HID + lane + 96], v3);
        if (lane == 0) atomicAdd(&g_pcnt[nn], 1);
    }
}

// ---------------- decoder ----------------
__global__ void k_dec(const float* __restrict__ hr, const float* __restrict__ Wd,
                      const float* __restrict__ bd, float* __restrict__ out) {
    int w = (blockIdx.x * blockDim.x + threadIdx.x) >> 5;
    int lane = threadIdx.x & 31;
    if (w >= NRR) return;
    float inv = 1.f / fmaxf((float)g_pcnt[w], 1.f);
    float a0 = 0.f, a1 = 0.f, a2 = 0.f;
#pragma unroll
    for (int t = 0; t < 4; t++) {
        int j = lane + 32 * t;
        float hv = hr[(size_t)w * HID + j];
        float pv = g_pool[(size_t)w * HID + j] * inv;
        a0 = fmaf(hv, Wd[j * 3 + 0], a0); a0 = fmaf(pv, Wd[(HID + j) * 3 + 0], a0);
        a1 = fmaf(hv, Wd[j * 3 + 1], a1); a1 = fmaf(pv, Wd[(HID + j) * 3 + 1], a1);
        a2 = fmaf(hv, Wd[j * 3 + 2], a2); a2 = fmaf(pv, Wd[(HID + j) * 3 + 2], a2);
    }
#pragma unroll
    for (int o = 16; o > 0; o >>= 1) {
        a0 += __shfl_xor_sync(0xffffffffu, a0, o);
        a1 += __shfl_xor_sync(0xffffffffu, a1, o);
        a2 += __shfl_xor_sync(0xffffffffu, a2, o);
    }
    if (lane == 0) {
        out[w * 3 + 0] = a0 + bd[0];
        out[w * 3 + 1] = a1 + bd[1];
        out[w * 3 + 2] = a2 + bd[2];
    }
}

// ---------------- host launcher ----------------
extern "C" void kernel_launch(void* const* d_in, const int* in_sizes, int n_in,
                              void* d_out, int out_size) {
    const float* x_r  = (const float*)d_in[0];
    const float* x_c  = (const float*)d_in[1];
    const int*   ei_r = (const int*)d_in[2];
    const int*   ei_c = (const int*)d_in[3];
    const float* W_r1  = (const float*)d_in[5];
    const float* as_r1 = (const float*)d_in[6];
    const float* ad_r1 = (const float*)d_in[7];
    const float* b_r1  = (const float*)d_in[8];
    const float* W_r2  = (const float*)d_in[9];
    const float* as_r2 = (const float*)d_in[10];
    const float* ad_r2 = (const float*)d_in[11];
    const float* b_r2  = (const float*)d_in[12];
    const float* W_c1  = (const float*)d_in[13];
    const float* as_c1 = (const float*)d_in[14];
    const float* ad_c1 = (const float*)d_in[15];
    const float* b_c1  = (const float*)d_in[16];
    const float* W_c2  = (const float*)d_in[17];
    const float* as_c2 = (const float*)d_in[18];
    const float* ad_c2 = (const float*)d_in[19];
    const float* b_c2  = (const float*)d_in[20];
    const float* W_dec = (const float*)d_in[21];
    const float* b_dec = (const float*)d_in[22];
    float* out = (float*)d_out;

    float *hw_r, *h1_r, *h2_r, *hw_c, *h1_c, *h2_c, *es, *ed, *mv, *dn, *nr2;
    int *cnt_r, *cur_r, *rp_r, *col_r, *cnt_c, *cur_c, *rp_c, *col_c;
    __nv_bfloat16 *bch, *bcl, *brh, *brl;
    cudaGetSymbolAddress((void**)&hw_r, g_hw_r);
    cudaGetSymbolAddress((void**)&h1_r, g_h1_r);
    cudaGetSymbolAddress((void**)&h2_r, g_h2_r);
    cudaGetSymbolAddress((void**)&hw_c, g_hw_c);
    cudaGetSymbolAddress((void**)&h1_c, g_h1_c);
    cudaGetSymbolAddress((void**)&h2_c, g_h2_c);
    cudaGetSymbolAddress((void**)&es, g_es);
    cudaGetSymbolAddress((void**)&ed, g_ed);
    cudaGetSymbolAddress((void**)&mv, g_mm);
    cudaGetSymbolAddress((void**)&dn, g_dn);
    cudaGetSymbolAddress((void**)&nr2, g_nr2);
    cudaGetSymbolAddress((void**)&cnt_r, g_cnt_r);
    cudaGetSymbolAddress((void**)&cur_r, g_cur_r);
    cudaGetSymbolAddress((void**)&rp_r, g_rp_r);
    cudaGetSymbolAddress((void**)&col_r, g_col_r);
    cudaGetSymbolAddress((void**)&cnt_c, g_cnt_c);
    cudaGetSymbolAddress((void**)&cur_c, g_cur_c);
    cudaGetSymbolAddress((void**)&rp_c, g_rp_c);
    cudaGetSymbolAddress((void**)&col_c, g_col_c);
    cudaGetSymbolAddress((void**)&bch, g_bch);
    cudaGetSymbolAddress((void**)&bcl, g_bcl);
    cudaGetSymbolAddress((void**)&brh, g_brh);
    cudaGetSymbolAddress((void**)&brl, g_brl);

    k_init<<<1024, 256>>>();

    k_count<<<(ERR + 255) / 256, 256>>>(ei_r + ERR, ERR, cnt_r);
    k_count<<<(ECC + 255) / 256, 256>>>(ei_c + ECC, ECC, cnt_c);
    k_scan<<<1, 1024>>>(cnt_r, rp_r, NRR);
    k_scan<<<1, 1024>>>(cnt_c, rp_c, NCC);
    k_scatter<<<(ERR + 255) / 256, 256>>>(ei_r, ei_r + ERR, ERR, rp_r, cur_r, col_r);
    k_scatter<<<(ECC + 255) / 256, 256>>>(ei_c, ei_c + ECC, ECC, rp_c, cur_c, col_c);
    k_selfloop<<<(NRR + 255) / 256, 256>>>(rp_r, col_r, NRR);
    k_selfloop<<<(NCC + 255) / 256, 256>>>(rp_c, col_c, NCC);

    const int WGR = (NRR + 7) / 8;
    const int WGC = (NCC + 7) / 8;

    // resting branch
    k_lin1<<<WGR, 256>>>(x_r, W_r1, as_r1, ad_r1, hw_r, es, ed, NRR);
    k_stats<<<WGR, 256>>>(rp_r, col_r, es, ed, mv, dn, NRR);
    k_agg<<<WGR, 256>>>(rp_r, col_r, hw_r, es, ed, mv, dn, b_r1, h1_r, NRR);
    k_gemm128<<<(NRR + 63) / 64, 256>>>(h1_r, W_r2, hw_r, NRR);
    k_dots<<<WGR, 256>>>(hw_r, as_r2, ad_r2, es, ed, NRR);
    k_stats<<<WGR, 256>>>(rp_r, col_r, es, ed, mv, dn, NRR);
    k_agg<<<WGR, 256>>>(rp_r, col_r, hw_r, es, ed, mv, dn, b_r2, h2_r, NRR);

    // collider branch
    k_lin1<<<WGC, 256>>>(x_c, W_c1, as_c1, ad_c1, hw_c, es, ed, NCC);
    k_stats<<<WGC, 256>>>(rp_c, col_c, es, ed, mv, dn, NCC);
    k_agg<<<WGC, 256>>>(rp_c, col_c, hw_c, es, ed, mv, dn, b_c1, h1_c, NCC);
    k_gemm128<<<(NCC + 63) / 64, 256>>>(h1_c, W_c2, hw_c, NCC);
    k_dots<<<WGC, 256>>>(hw_c, as_c2, ad_c2, es, ed, NCC);
    k_stats<<<WGC, 256>>>(rp_c, col_c, es, ed, mv, dn, NCC);
    k_agg<<<WGC, 256>>>(rp_c, col_c, hw_c, es, ed, mv, dn, b_c2, h2_c, NCC);

    // KNN: bf16 split -> HMMA candidates -> exact fp32 rescore
    k_norm<<<WGR, 256>>>(h2_r, nr2, NRR);
    k_split<<<(NRR * HID + 255) / 256, 256>>>(h2_r, brh, brl, NRR * HID);
    k_split<<<(NCC * HID + 255) / 256, 256>>>(h2_c, bch, bcl, NCC * HID);
    dim3 kg(CTILES, RSPLIT);
    k_knn_mma<<<kg, 256>>>(nr2);
    k_rescore<<<(NCC * 32 + 255) / 256, 256>>>(h2_c, h2_r, nr2);
    k_pool<<<WGC, 256>>>(h2_c);
    k_dec<<<WGR, 256>>>(h2_r, W_dec, b_dec, out);
}

// round 8
// speedup vs baseline: 3.1371x; 1.1457x over previous
#include <cuda_runtime.h>
#include <cuda_bf16.h>
#include <math.h>
#include <cstdint>

// ---------------- problem constants ----------------
#define NRR 20000
#define NCC 5000
#define ERR 320000
#define ECC 80000
#define DIN 6
#define HID 128
#define KNN 3
#define NEG 0.2f

#define CTILES 40        // ceil(NCC/128)
#define RSPLIT 8
#define RROWS 2500       // NRR / RSPLIT (exact)
#define NCAND 16         // candidates per (split, collider)

#define WGR 2500         // NRR/8 warps-per-node blocks
#define WGC 625          // NCC/8
#define GBR 313          // ceil(NRR/64) gemm blocks
#define GBC 79           // ceil(NCC/64)

// ---------------- mma.sync m16n8k16 bf16 ----------------
#define MMA16816(c, a, b0, b1) \
    asm volatile("mma.sync.aligned.m16n8k16.row.col.f32.bf16.bf16.f32 " \
        "{%0,%1,%2,%3}, {%4,%5,%6,%7}, {%8,%9}, {%0,%1,%2,%3};" \
        : "+f"((c)[0]), "+f"((c)[1]), "+f"((c)[2]), "+f"((c)[3]) \
        : "r"((a)[0]), "r"((a)[1]), "r"((a)[2]), "r"((a)[3]), "r"(b0), "r"(b1))

// ---------------- static scratch ----------------
__device__ float g_hw_r[NRR * HID];
__device__ float g_h1_r[NRR * HID];
__device__ float g_h2_r[NRR * HID];
__device__ float g_hw_c[NCC * HID];
__device__ float g_h1_c[NCC * HID];
__device__ float g_h2_c[NCC * HID];
__device__ float g_es[NRR];
__device__ float g_ed[NRR];
__device__ float g_mm[NRR];
__device__ float g_dn[NRR];
__device__ float g_es_c[NCC];
__device__ float g_ed_c[NCC];
__device__ float g_mm_c[NCC];
__device__ float g_dn_c[NCC];
__device__ int   g_cnt_r[NRR];
__device__ int   g_cur_r[NRR];
__device__ int   g_rp_r[NRR + 1];
__device__ int   g_col_r[ERR + NRR];
__device__ int   g_cnt_c[NCC];
__device__ int   g_cur_c[NCC];
__device__ int   g_rp_c[NCC + 1];
__device__ int   g_col_c[ECC + NCC];
__device__ float g_nr2[NRR];
__device__ __nv_bfloat16 g_bch[NCC * HID];   // collider hi (A fragments)
__device__ __nv_bfloat16 g_bcl[NCC * HID];   // collider lo
__device__ uint4 g_brq[NRR * 32];            // resting hi/lo in fragment-quad layout
__device__ int   g_ci[RSPLIT * NCC * NCAND];
__device__ int   g_nn[NCC * KNN];
__device__ float g_pool[NRR * HID];
__device__ int   g_pcnt[NRR];

// ---------------- init ----------------
__global__ void k_init() {
    int i = blockIdx.x * blockDim.x + threadIdx.x;
    int st = gridDim.x * blockDim.x;
    for (int t = i; t < NRR * HID; t += st) g_pool[t] = 0.f;
    for (int t = i; t < NRR; t += st) { g_cnt_r[t] = 1; g_cur_r[t] = 0; g_pcnt[t] = 0; }
    for (int t = i; t < NCC; t += st) { g_cnt_c[t] = 1; g_cur_c[t] = 0; }
}

// ---------------- CSR build (branch-merged) ----------------
__global__ void k_count_both(const int* __restrict__ dst_r, const int* __restrict__ dst_c) {
    int i = blockIdx.x * blockDim.x + threadIdx.x;
    if (i < ERR) atomicAdd(&g_cnt_r[dst_r[i]], 1);
    else if (i - ERR < ECC) atomicAdd(&g_cnt_c[dst_c[i - ERR]], 1);
}

__device__ __forceinline__ void scan_body(const int* cnt, int* rp, int n) {
    __shared__ int part[1024];
    int t = threadIdx.x;
    int chunk = (n + 1023) / 1024;
    int beg = t * chunk, end = min(n, beg + chunk);
    int s = 0;
    for (int i = beg; i < end; i++) s += cnt[i];
    part[t] = s;
    __syncthreads();
    for (int off = 1; off < 1024; off <<= 1) {
        int v = (t >= off) ? part[t - off] : 0;
        __syncthreads();
        part[t] += v;
        __syncthreads();
    }
    int run = part[t] - s;
    for (int i = beg; i < end; i++) { rp[i] = run; run += cnt[i]; }
    if (t == 1023) rp[n] = part[1023];
}
__global__ void k_scan_both() {
    if (blockIdx.x == 0) scan_body(g_cnt_r, g_rp_r, NRR);
    else scan_body(g_cnt_c, g_rp_c, NCC);
}

__global__ void k_scatter_both(const int* __restrict__ ei_r, const int* __restrict__ ei_c) {
    int i = blockIdx.x * blockDim.x + threadIdx.x;
    if (i < ERR) {
        int d = ei_r[ERR + i];
        int pos = g_rp_r[d] + atomicAdd(&g_cur_r[d], 1);
        g_col_r[pos] = ei_r[i];
    } else if (i - ERR < ECC) {
        int j = i - ERR;
        int d = ei_c[ECC + j];
        int pos = g_rp_c[d] + atomicAdd(&g_cur_c[d], 1);
        g_col_c[pos] = ei_c[j];
    }
}

__global__ void k_selfloop_both() {
    int i = blockIdx.x * blockDim.x + threadIdx.x;
    if (i < NRR) g_col_r[g_rp_r[i + 1] - 1] = i;
    else if (i - NRR < NCC) { int j = i - NRR; g_col_c[g_rp_c[j + 1] - 1] = j; }
}

// ---------------- GAT stage bodies ----------------
__device__ __forceinline__ void lin1_body(int w, int lane, const float* __restrict__ x,
                                          const float* __restrict__ W, const float* __restrict__ as_,
                                          const float* __restrict__ ad_, float* __restrict__ h,
                                          float* __restrict__ es, float* __restrict__ ed) {
    float xv[DIN];
#pragma unroll
    for (int k = 0; k < DIN; k++) xv[k] = x[w * DIN + k];
    float hv[4], ps = 0.f, pd = 0.f;
#pragma unroll
    for (int q = 0; q < 4; q++) {
        int j = lane * 4 + q;
        float a = 0.f;
#pragma unroll
        for (int k = 0; k < DIN; k++) a = fmaf(xv[k], W[k * HID + j], a);
        hv[q] = a;
        ps = fmaf(a, as_[j], ps);
        pd = fmaf(a, ad_[j], pd);
    }
    *(float4*)&h[(size_t)w * HID + lane * 4] = make_float4(hv[0], hv[1], hv[2], hv[3]);
#pragma unroll
    for (int o = 16; o > 0; o >>= 1) {
        ps += __shfl_xor_sync(0xffffffffu, ps, o);
        pd += __shfl_xor_sync(0xffffffffu, pd, o);
    }
    if (lane == 0) { es[w] = ps; ed[w] = pd; }
}

__global__ void k_lin1_both(const float* xr, const float* Wr, const float* asr, const float* adr,
                            const float* xc, const float* Wc, const float* asc, const float* adc,
                            float* hr, float* hc) {
    int gw = (blockIdx.x * blockDim.x + threadIdx.x) >> 5;
    int lane = threadIdx.x & 31;
    if (blockIdx.x < WGR) {
        if (gw < NRR) lin1_body(gw, lane, xr, Wr, asr, adr, hr, g_es, g_ed);
    } else {
        int w = gw - WGR * 8;
        if (w < NCC) lin1_body(w, lane, xc, Wc, asc, adc, hc, g_es_c, g_ed_c);
    }
}

__device__ __forceinline__ void stats_body(int w, int lane, const int* __restrict__ rp,
                                           const int* __restrict__ col, const float* __restrict__ es,
                                           const float* __restrict__ edv, float* __restrict__ mv,
                                           float* __restrict__ dnv) {
    int beg = rp[w], end = rp[w + 1];
    float ed = edv[w];
    float m = -1e30f, s = 0.f;
    for (int idx = beg + lane; idx < end; idx += 32) {
        float e = es[col[idx]] + ed;
        e = e > 0.f ? e : NEG * e;
        float mn = fmaxf(m, e);
        s = s * __expf(m - mn) + __expf(e - mn);
        m = mn;
    }
#pragma unroll
    for (int o = 16; o > 0; o >>= 1) {
        float m2 = __shfl_xor_sync(0xffffffffu, m, o);
        float s2 = __shfl_xor_sync(0xffffffffu, s, o);
        float mn = fmaxf(m, m2);
        s = s * __expf(m - mn) + s2 * __expf(m2 - mn);
        m = mn;
    }
    if (lane == 0) { mv[w] = m; dnv[w] = s; }
}

__global__ void k_stats_both() {
    int gw = (blockIdx.x * blockDim.x + threadIdx.x) >> 5;
    int lane = threadIdx.x & 31;
    if (blockIdx.x < WGR) {
        if (gw < NRR) stats_body(gw, lane, g_rp_r, g_col_r, g_es, g_ed, g_mm, g_dn);
    } else {
        int w = gw - WGR * 8;
        if (w < NCC) stats_body(w, lane, g_rp_c, g_col_c, g_es_c, g_ed_c, g_mm_c, g_dn_c);
    }
}

__device__ __forceinline__ void agg_body(int w, int lane, const int* __restrict__ rp,
                                         const int* __restrict__ col, const float* __restrict__ hW,
                                         const float* __restrict__ es, const float* __restrict__ edv,
                                         const float* __restrict__ mv, const float* __restrict__ dnv,
                                         const float* __restrict__ bias, float* __restrict__ out) {
    int beg = rp[w], end = rp[w + 1];
    float ed = edv[w], md = mv[w];
    float inv = 1.f / fmaxf(dnv[w], 1e-16f);
    float a0 = 0.f, a1 = 0.f, a2 = 0.f, a3 = 0.f;
    for (int idx = beg; idx < end; idx++) {
        int s = col[idx];
        float e = es[s] + ed;
        e = e > 0.f ? e : NEG * e;
        float wgt = __expf(e - md) * inv;
        const float* hr = &hW[(size_t)s * HID];
        a0 = fmaf(wgt, hr[lane], a0);
        a1 = fmaf(wgt, hr[lane + 32], a1);
        a2 = fmaf(wgt, hr[lane + 64], a2);
        a3 = fmaf(wgt, hr[lane + 96], a3);
    }
    out[(size_t)w * HID + lane]      = fmaxf(a0 + bias[lane], 0.f);
    out[(size_t)w * HID + lane + 32] = fmaxf(a1 + bias[lane + 32], 0.f);
    out[(size_t)w * HID + lane + 64] = fmaxf(a2 + bias[lane + 64], 0.f);
    out[(size_t)w * HID + lane + 96] = fmaxf(a3 + bias[lane + 96], 0.f);
}

__global__ void k_agg_both(const float* hWr, const float* br, float* outr,
                           const float* hWc, const float* bc, float* outc) {
    int gw = (blockIdx.x * blockDim.x + threadIdx.x) >> 5;
    int lane = threadIdx.x & 31;
    if (blockIdx.x < WGR) {
        if (gw < NRR) agg_body(gw, lane, g_rp_r, g_col_r, hWr, g_es, g_ed, g_mm, g_dn, br, outr);
    } else {
        int w = gw - WGR * 8;
        if (w < NCC) agg_body(w, lane, g_rp_c, g_col_c, hWc, g_es_c, g_ed_c, g_mm_c, g_dn_c, bc, outc);
    }
}

__device__ __forceinline__ void gemm_body(int row0, int M, const float* __restrict__ A,
                                          const float* __restrict__ B, float* __restrict__ C) {
    __shared__ float As[16][64];
    __shared__ float Bs[16][128];
    int tid = threadIdx.x;
    int tc = tid & 31, tr = tid >> 5;
    float acc[8][4];
#pragma unroll
    for (int i = 0; i < 8; i++)
#pragma unroll
        for (int j = 0; j < 4; j++) acc[i][j] = 0.f;
    for (int k0 = 0; k0 < HID; k0 += 16) {
        int row_l = tid >> 2, quad = tid & 3;
        int gr = row0 + row_l;
        float4 av = make_float4(0.f, 0.f, 0.f, 0.f);
        if (gr < M) av = *(const float4*)&A[(size_t)gr * HID + k0 + quad * 4];
        As[quad * 4 + 0][row_l] = av.x;
        As[quad * 4 + 1][row_l] = av.y;
        As[quad * 4 + 2][row_l] = av.z;
        As[quad * 4 + 3][row_l] = av.w;
        int kk = tid >> 4, cp = tid & 15;
        float4 bv0 = *(const float4*)&B[(size_t)(k0 + kk) * HID + cp * 8];
        float4 bv1 = *(const float4*)&B[(size_t)(k0 + kk) * HID + cp * 8 + 4];
        *(float4*)&Bs[kk][cp * 8] = bv0;
        *(float4*)&Bs[kk][cp * 8 + 4] = bv1;
        __syncthreads();
#pragma unroll
        for (int k2 = 0; k2 < 16; k2++) {
            float4 a0 = *(float4*)&As[k2][tr * 8];
            float4 a1 = *(float4*)&As[k2][tr * 8 + 4];
            float4 bb = *(float4*)&Bs[k2][tc * 4];
            float a[8] = {a0.x, a0.y, a0.z, a0.w, a1.x, a1.y, a1.z, a1.w};
            float b[4] = {bb.x, bb.y, bb.z, bb.w};
#pragma unroll
            for (int i = 0; i < 8; i++)
#pragma unroll
                for (int j = 0; j < 4; j++) acc[i][j] = fmaf(a[i], b[j], acc[i][j]);
        }
        __syncthreads();
    }
#pragma unroll
    for (int i = 0; i < 8; i++) {
        int r = row0 + tr * 8 + i;
        if (r < M)
            *(float4*)&C[(size_t)r * HID + tc * 4] =
                make_float4(acc[i][0], acc[i][1], acc[i][2], acc[i][3]);
    }
}

__global__ void __launch_bounds__(256) k_gemm_both(const float* Ar, const float* Br, float* Cr,
                                                   const float* Ac, const float* Bc, float* Cc) {
    if (blockIdx.x < GBR) gemm_body(blockIdx.x * 64, NRR, Ar, Br, Cr);
    else gemm_body((blockIdx.x - GBR) * 64, NCC, Ac, Bc, Cc);
}

__device__ __forceinline__ void dots_body(int w, int lane, const float* __restrict__ h,
                                          const float* __restrict__ as_, const float* __restrict__ ad_,
                                          float* __restrict__ es, float* __restrict__ ed) {
    const float* hr = &h[(size_t)w * HID];
    float ps = 0.f, pd = 0.f;
#pragma unroll
    for (int t = 0; t < 4; t++) {
        int j = lane + 32 * t;
        float v = hr[j];
        ps = fmaf(v, as_[j], ps);
        pd = fmaf(v, ad_[j], pd);
    }
#pragma unroll
    for (int o = 16; o > 0; o >>= 1) {
        ps += __shfl_xor_sync(0xffffffffu, ps, o);
        pd += __shfl_xor_sync(0xffffffffu, pd, o);
    }
    if (lane == 0) { es[w] = ps; ed[w] = pd; }
}

__global__ void k_dots_both(const float* hr, const float* asr, const float* adr,
                            const float* hc, const float* asc, const float* adc) {
    int gw = (blockIdx.x * blockDim.x + threadIdx.x) >> 5;
    int lane = threadIdx.x & 31;
    if (blockIdx.x < WGR) {
        if (gw < NRR) dots_body(gw, lane, hr, asr, adr, g_es, g_ed);
    } else {
        int w = gw - WGR * 8;
        if (w < NCC) dots_body(w, lane, hc, asc, adc, g_es_c, g_ed_c);
    }
}

__global__ void k_norm(const float* __restrict__ h, float* __restrict__ nrm, int n) {
    int w = (blockIdx.x * blockDim.x + threadIdx.x) >> 5;
    int lane = threadIdx.x & 31;
    if (w >= n) return;
    const float* hr = &h[(size_t)w * HID];
    float s = 0.f;
#pragma unroll
    for (int t = 0; t < 4; t++) { float v = hr[lane + 32 * t]; s = fmaf(v, v, s); }
#pragma unroll
    for (int o = 16; o > 0; o >>= 1) s += __shfl_xor_sync(0xffffffffu, s, o);
    if (lane == 0) nrm[w] = s;
}

// ---------------- bf16 hi/lo splits ----------------
// collider: plain hi/lo arrays (A fragments read 32-bit pairs)
__global__ void k_split(const float* __restrict__ h, __nv_bfloat16* __restrict__ hi,
                        __nv_bfloat16* __restrict__ lo, int n) {
    int i = blockIdx.x * blockDim.x + threadIdx.x;
    if (i < n) {
        float x = h[i];
        __nv_bfloat16 a = __float2bfloat16(x);
        hi[i] = a;
        lo[i] = __float2bfloat16(x - __bfloat162float(a));
    }
}
// resting: fragment-quad layout. 16B group g=(node*8+ks)*4+kcg holds
// [Hi(kb,kb+1) Hi(kb+8,kb+9) Lo(kb,kb+1) Lo(kb+8,kb+9)], kb=16*ks+2*kcg.
__global__ void k_splitq(const float* __restrict__ h) {
    int i = blockIdx.x * blockDim.x + threadIdx.x;
    if (i < NRR * HID) {
        int node = i >> 7, k = i & 127;
        float x = h[i];
        __nv_bfloat16 hi = __float2bfloat16(x);
        __nv_bfloat16 lo = __float2bfloat16(x - __bfloat162float(hi));
        int j = k & 15;
        int g = (node * 8 + (k >> 4)) * 4 + ((j >> 1) & 3);
        int slot = ((j >> 3) << 1) | (j & 1);
        __nv_bfloat16* base = (__nv_bfloat16*)g_brq + (size_t)g * 8;
        base[slot] = hi;
        base[4 + slot] = lo;
    }
}

// ---------------- comparators ----------------
__device__ __forceinline__ bool d2_less(float v1, int i1, float v2, int i2) {
    return (v1 < v2) || (v1 == v2 && i1 < i2);
}
__device__ __forceinline__ void top3_upd(float v, int r, float tv[3], int ti[3]) {
    if (d2_less(v, r, tv[2], ti[2])) {
        tv[2] = v; ti[2] = r;
        if (d2_less(tv[2], ti[2], tv[1], ti[1])) {
            float a = tv[1]; int b = ti[1]; tv[1] = tv[2]; ti[1] = ti[2]; tv[2] = a; ti[2] = b;
        }
        if (d2_less(tv[1], ti[1], tv[0], ti[0])) {
            float a = tv[0]; int b = ti[0]; tv[0] = tv[1]; ti[0] = ti[1]; tv[1] = a; ti[1] = b;
        }
    }
}
__device__ __forceinline__ void top4_upd(float v, int r, float tv[4], int ti[4]) {
    if (d2_less(v, r, tv[3], ti[3])) {
        tv[3] = v; ti[3] = r;
#pragma unroll
        for (int k = 3; k > 0; k--) {
            if (d2_less(tv[k], ti[k], tv[k - 1], ti[k - 1])) {
                float a = tv[k - 1]; int b = ti[k - 1];
                tv[k - 1] = tv[k]; ti[k - 1] = ti[k];
                tv[k] = a; ti[k] = b;
            }
        }
    }
}

// ---------------- HMMA KNN candidate kernel (LDS.128 B loads) ----------------
// grid (CTILES, RSPLIT), 256 threads. Same math as R7; B fragments now come
// from the quad layout: one LDS.128 = all 4 operands for one (n, ks).
#define BROW 36   // uint4 per row in smem (32 data + 4 pad; stride 576B kills phase conflicts)
__global__ void __launch_bounds__(256, 2) k_knn_mma(const float* __restrict__ nr2) {
    __shared__ __align__(16) uint4 Bs[64 * BROW];
    __shared__ float NrS[64];

    int tid = threadIdx.x;
    int l = tid & 31, w = tid >> 5;
    int cb = blockIdx.x * 128;
    int rbeg = blockIdx.y * RROWS;
    int rend = rbeg + RROWS;

    // ---- A fragments (hi+lo) in registers ----
    int m0 = cb + w * 16 + (l >> 2);
    int aR0 = min(m0, NCC - 1);
    int aR1 = min(m0 + 8, NCC - 1);
    int kc = (l & 3) * 2;
    uint32_t Ah[8][4], Al[8][4];
#pragma unroll
    for (int ks = 0; ks < 8; ks++) {
        int k0 = ks * 16 + kc;
        Ah[ks][0] = *(const uint32_t*)&g_bch[(size_t)aR0 * HID + k0];
        Ah[ks][1] = *(const uint32_t*)&g_bch[(size_t)aR1 * HID + k0];
        Ah[ks][2] = *(const uint32_t*)&g_bch[(size_t)aR0 * HID + k0 + 8];
        Ah[ks][3] = *(const uint32_t*)&g_bch[(size_t)aR1 * HID + k0 + 8];
        Al[ks][0] = *(const uint32_t*)&g_bcl[(size_t)aR0 * HID + k0];
        Al[ks][1] = *(const uint32_t*)&g_bcl[(size_t)aR1 * HID + k0];
        Al[ks][2] = *(const uint32_t*)&g_bcl[(size_t)aR0 * HID + k0 + 8];
        Al[ks][3] = *(const uint32_t*)&g_bcl[(size_t)aR1 * HID + k0 + 8];
    }

    float tvA[4] = {1e30f, 1e30f, 1e30f, 1e30f};
    float tvB[4] = {1e30f, 1e30f, 1e30f, 1e30f};
    int tiA[4] = {0x7fffffff, 0x7fffffff, 0x7fffffff, 0x7fffffff};
    int tiB[4] = {0x7fffffff, 0x7fffffff, 0x7fffffff, 0x7fffffff};

    int kcg = l & 3;

    for (int rt = rbeg; rt < rend; rt += 64) {
        // ---- stage quad tile: 64 rows x 32 uint4 (coalesced copy) ----
        for (int idx = tid; idx < 2048; idx += 256) {
            int row = idx >> 5, i = idx & 31;
            int gr = rt + row;
            uint4 v = make_uint4(0, 0, 0, 0);
            if (gr < rend) v = g_brq[(size_t)gr * 32 + i];
            Bs[row * BROW + i] = v;
        }
        if (tid < 64) NrS[tid] = (rt + tid < rend) ? nr2[rt + tid] : 1e30f;
        __syncthreads();

        // ---- mma: n8-pair outer, ks inner ----
#pragma unroll
        for (int np = 0; np < 4; np++) {
            int nA = (np * 2) * 8 + (l >> 2);
            int nB = (np * 2 + 1) * 8 + (l >> 2);
            float acc0[4] = {0.f, 0.f, 0.f, 0.f};
            float acc1[4] = {0.f, 0.f, 0.f, 0.f};
#pragma unroll
            for (int ks = 0; ks < 8; ks++) {
                uint4 va = Bs[nA * BROW + ks * 4 + kcg];
                uint4 vb = Bs[nB * BROW + ks * 4 + kcg];
                MMA16816(acc0, Ah[ks], va.x, va.y);
                MMA16816(acc1, Ah[ks], vb.x, vb.y);
                MMA16816(acc0, Ah[ks], va.z, va.w);
                MMA16816(acc1, Ah[ks], vb.z, vb.w);
                MMA16816(acc0, Al[ks], va.x, va.y);
                MMA16816(acc1, Al[ks], vb.x, vb.y);
            }
            int c0a = (np * 2) * 8 + (l & 3) * 2;
            int c0b = (np * 2 + 1) * 8 + (l & 3) * 2;
            int ra = rt + c0a, rb2 = rt + c0b;
            float na0 = NrS[c0a], na1 = NrS[c0a + 1];
            float nb0 = NrS[c0b], nb1 = NrS[c0b + 1];
            top4_upd(na0 - 2.f * acc0[0], ra, tvA, tiA);
            top4_upd(na1 - 2.f * acc0[1], ra + 1, tvA, tiA);
            top4_upd(na0 - 2.f * acc0[2], ra, tvB, tiB);
            top4_upd(na1 - 2.f * acc0[3], ra + 1, tvB, tiB);
            top4_upd(nb0 - 2.f * acc1[0], rb2, tvA, tiA);
            top4_upd(nb1 - 2.f * acc1[1], rb2 + 1, tvA, tiA);
            top4_upd(nb0 - 2.f * acc1[2], rb2, tvB, tiB);
            top4_upd(nb1 - 2.f * acc1[3], rb2 + 1, tvB, tiB);
        }
        __syncthreads();
    }

    int cA = cb + w * 16 + (l >> 2);
    int cB = cA + 8;
    if (cA < NCC) {
        size_t base = ((size_t)blockIdx.y * NCC + cA) * NCAND + (l & 3) * 4;
#pragma unroll
        for (int k = 0; k < 4; k++) g_ci[base + k] = tiA[k];
    }
    if (cB < NCC) {
        size_t base = ((size_t)blockIdx.y * NCC + cB) * NCAND + (l & 3) * 4;
#pragma unroll
        for (int k = 0; k < 4; k++) g_ci[base + k] = tiB[k];
    }
}

// ---------------- exact fp32 rescore of 128 candidates, top-3 ----------------
__global__ void k_rescore(const float* __restrict__ hc, const float* __restrict__ hr,
                          const float* __restrict__ nr2) {
    int w = (blockIdx.x * blockDim.x + threadIdx.x) >> 5;
    int lane = threadIdx.x & 31;
    if (w >= NCC) return;
    float c0 = hc[(size_t)w * HID + lane];
    float c1 = hc[(size_t)w * HID + lane + 32];
    float c2 = hc[(size_t)w * HID + lane + 64];
    float c3 = hc[(size_t)w * HID + lane + 96];
    float f[3] = {1e30f, 1e30f, 1e30f};
    int   j[3] = {0x7fffffff, 0x7fffffff, 0x7fffffff};
    for (int s = 0; s < RSPLIT; s++) {
        size_t base = ((size_t)s * NCC + w) * NCAND;
        for (int k = 0; k < NCAND; k++) {
            int r = g_ci[base + k];
            if ((unsigned)r >= (unsigned)NRR) continue;
            const float* hrr = &hr[(size_t)r * HID];
            float p = 0.f;
            p = fmaf(c0, hrr[lane], p);
            p = fmaf(c1, hrr[lane + 32], p);
            p = fmaf(c2, hrr[lane + 64], p);
            p = fmaf(c3, hrr[lane + 96], p);
#pragma unroll
            for (int o = 16; o > 0; o >>= 1) p += __shfl_xor_sync(0xffffffffu, p, o);
            if (lane == 0) {
                float key = nr2[r] - 2.f * p;
                top3_upd(key, r, f, j);
            }
        }
    }
    if (lane == 0) {
        g_nn[w * 3 + 0] = j[0];
        g_nn[w * 3 + 1] = j[1];
        g_nn[w * 3 + 2] = j[2];
    }
}

// ---------------- scatter-mean pooling ----------------
__global__ void k_pool(const float* __restrict__ hc) {
    int w = (blockIdx.x * blockDim.x + threadIdx.x) >> 5;
    int lane = threadIdx.x & 31;
    if (w >= NCC) return;
    const float* hr = &hc[(size_t)w * HID];
    float v0 = hr[lane], v1 = hr[lane + 32], v2 = hr[lane + 64], v3 = hr[lane + 96];
#pragma unroll
    for (int k = 0; k < KNN; k++) {
        int nn = g_nn[w * 3 + k];
        atomicAdd(&g_pool[(size_t)nn * HID + lane], v0);
        atomicAdd(&g_pool[(size_t)nn * HID + lane + 32], v1);
        atomicAdd(&g_pool[(size_t)nn * HID + lane + 64], v2);
        atomicAdd(&g_pool[(size_t)nn * HID + lane + 96], v3);
        if (lane == 0) atomicAdd(&g_pcnt[nn], 1);
    }
}

// ---------------- decoder ----------------
__global__ void k_dec(const float* __restrict__ hr, const float* __restrict__ Wd,
                      const float* __restrict__ bd, float* __restrict__ out) {
    int w = (blockIdx.x * blockDim.x + threadIdx.x) >> 5;
    int lane = threadIdx.x & 31;
    if (w >= NRR) return;
    float inv = 1.f / fmaxf((float)g_pcnt[w], 1.f);
    float a0 = 0.f, a1 = 0.f, a2 = 0.f;
#pragma unroll
    for (int t = 0; t < 4; t++) {
        int j = lane + 32 * t;
        float hv = hr[(size_t)w * HID + j];
        float pv = g_pool[(size_t)w * HID + j] * inv;
        a0 = fmaf(hv, Wd[j * 3 + 0], a0); a0 = fmaf(pv, Wd[(HID + j) * 3 + 0], a0);
        a1 = fmaf(hv, Wd[j * 3 + 1], a1); a1 = fmaf(pv, Wd[(HID + j) * 3 + 1], a1);
        a2 = fmaf(hv, Wd[j * 3 + 2], a2); a2 = fmaf(pv, Wd[(HID + j) * 3 + 2], a2);
    }
#pragma unroll
    for (int o = 16; o > 0; o >>= 1) {
        a0 += __shfl_xor_sync(0xffffffffu, a0, o);
        a1 += __shfl_xor_sync(0xffffffffu, a1, o);
        a2 += __shfl_xor_sync(0xffffffffu, a2, o);
    }
    if (lane == 0) {
        out[w * 3 + 0] = a0 + bd[0];
        out[w * 3 + 1] = a1 + bd[1];
        out[w * 3 + 2] = a2 + bd[2];
    }
}

// ---------------- host launcher ----------------
extern "C" void kernel_launch(void* const* d_in, const int* in_sizes, int n_in,
                              void* d_out, int out_size) {
    const float* x_r  = (const float*)d_in[0];
    const float* x_c  = (const float*)d_in[1];
    const int*   ei_r = (const int*)d_in[2];
    const int*   ei_c = (const int*)d_in[3];
    const float* W_r1  = (const float*)d_in[5];
    const float* as_r1 = (const float*)d_in[6];
    const float* ad_r1 = (const float*)d_in[7];
    const float* b_r1  = (const float*)d_in[8];
    const float* W_r2  = (const float*)d_in[9];
    const float* as_r2 = (const float*)d_in[10];
    const float* ad_r2 = (const float*)d_in[11];
    const float* b_r2  = (const float*)d_in[12];
    const float* W_c1  = (const float*)d_in[13];
    const float* as_c1 = (const float*)d_in[14];
    const float* ad_c1 = (const float*)d_in[15];
    const float* b_c1  = (const float*)d_in[16];
    const float* W_c2  = (const float*)d_in[17];
    const float* as_c2 = (const float*)d_in[18];
    const float* ad_c2 = (const float*)d_in[19];
    const float* b_c2  = (const float*)d_in[20];
    const float* W_dec = (const float*)d_in[21];
    const float* b_dec = (const float*)d_in[22];
    float* out = (float*)d_out;

    float *hw_r, *h1_r, *h2_r, *hw_c, *h1_c, *h2_c, *nr2;
    __nv_bfloat16 *bch, *bcl;
    cudaGetSymbolAddress((void**)&hw_r, g_hw_r);
    cudaGetSymbolAddress((void**)&h1_r, g_h1_r);
    cudaGetSymbolAddress((void**)&h2_r, g_h2_r);
    cudaGetSymbolAddress((void**)&hw_c, g_hw_c);
    cudaGetSymbolAddress((void**)&h1_c, g_h1_c);
    cudaGetSymbolAddress((void**)&h2_c, g_h2_c);
    cudaGetSymbolAddress((void**)&nr2, g_nr2);
    cudaGetSymbolAddress((void**)&bch, g_bch);
    cudaGetSymbolAddress((void**)&bcl, g_bcl);

    k_init<<<1024, 256>>>();

    // CSR (branch-merged)
    k_count_both<<<(ERR + ECC + 255) / 256, 256>>>(ei_r + ERR, ei_c + ECC);
    k_scan_both<<<2, 1024>>>();
    k_scatter_both<<<(ERR + ECC + 255) / 256, 256>>>(ei_r, ei_c);
    k_selfloop_both<<<(NRR + NCC + 255) / 256, 256>>>();

    const int WB = WGR + WGC;   // merged warp-per-node grid

    // layer 1 (both branches in one launch each)
    k_lin1_both<<<WB, 256>>>(x_r, W_r1, as_r1, ad_r1, x_c, W_c1, as_c1, ad_c1, hw_r, hw_c);
    k_stats_both<<<WB, 256>>>();
    k_agg_both<<<WB, 256>>>(hw_r, b_r1, h1_r, hw_c, b_c1, h1_c);
    // layer 2
    k_gemm_both<<<GBR + GBC, 256>>>(h1_r, W_r2, hw_r, h1_c, W_c2, hw_c);
    k_dots_both<<<WB, 256>>>(hw_r, as_r2, ad_r2, hw_c, as_c2, ad_c2);
    k_stats_both<<<WB, 256>>>();
    k_agg_both<<<WB, 256>>>(hw_r, b_r2, h2_r, hw_c, b_c2, h2_c);

    // KNN: bf16 split -> HMMA candidates -> exact fp32 rescore
    k_norm<<<WGR, 256>>>(h2_r, nr2, NRR);
    k_splitq<<<(NRR * HID + 255) / 256, 256>>>(h2_r);
    k_split<<<(NCC * HID + 255) / 256, 256>>>(h2_c, bch, bcl, NCC * HID);
    dim3 kg(CTILES, RSPLIT);
    k_knn_mma<<<kg, 256>>>(nr2);
    k_rescore<<<(NCC * 32 + 255) / 256, 256>>>(h2_c, h2_r, nr2);
    k_pool<<<WGC, 256>>>(h2_c);
    k_dec<<<WGR, 256>>>(h2_r, W_dec, b_dec, out);
}

// round 9
// speedup vs baseline: 3.5863x; 1.1432x over previous
#include <cuda_runtime.h>
#include <cuda_fp16.h>
#include <math.h>
#include <cstdint>

// ---------------- problem constants ----------------
#define NRR 20000
#define NCC 5000
#define ERR 320000
#define ECC 80000
#define DIN 6
#define HID 128
#define KNN 3
#define NEG 0.2f

#define CTILES 40        // ceil(NCC/128)
#define RSPLIT 8
#define RROWS 2500       // NRR / RSPLIT (exact)
#define NCAND 16         // candidates per (split, collider)

#define WGR 2500         // NRR/8 warp-per-node blocks
#define WGC 625          // NCC/8
#define GBR 313          // ceil(NRR/64) gemm blocks
#define GBC 79           // ceil(NCC/64)

// ---------------- mma.sync m16n8k16 fp16 ----------------
#define MMA16816(c, a, b0, b1) \
    asm volatile("mma.sync.aligned.m16n8k16.row.col.f32.f16.f16.f32 " \
        "{%0,%1,%2,%3}, {%4,%5,%6,%7}, {%8,%9}, {%0,%1,%2,%3};" \
        : "+f"((c)[0]), "+f"((c)[1]), "+f"((c)[2]), "+f"((c)[3]) \
        : "r"((a)[0]), "r"((a)[1]), "r"((a)[2]), "r"((a)[3]), "r"(b0), "r"(b1))

// ---------------- static scratch ----------------
__device__ float g_hw_r[NRR * HID];
__device__ float g_h1_r[NRR * HID];
__device__ float g_h2_r[NRR * HID];
__device__ float g_hw_c[NCC * HID];
__device__ float g_h1_c[NCC * HID];
__device__ float g_h2_c[NCC * HID];
__device__ float g_es[NRR];
__device__ float g_ed[NRR];
__device__ float g_mm[NRR];
__device__ float g_dn[NRR];
__device__ float g_es_c[NCC];
__device__ float g_ed_c[NCC];
__device__ float g_mm_c[NCC];
__device__ float g_dn_c[NCC];
__device__ int   g_cnt_r[NRR];
__device__ int   g_cur_r[NRR];
__device__ int   g_rp_r[NRR + 1];
__device__ int   g_col_r[ERR + NRR];
__device__ int   g_cnt_c[NCC];
__device__ int   g_cur_c[NCC];
__device__ int   g_rp_c[NCC + 1];
__device__ int   g_col_c[ECC + NCC];
__device__ float g_nr2[NRR];
__device__ __half g_ach[NCC * HID];          // collider hi (A fragments, fp16)
__device__ uint4  g_brq[NRR * 32];           // resting hi/lo fp16 fragment-quad layout
__device__ int   g_ci[RSPLIT * NCC * NCAND];
__device__ int   g_nn[NCC * KNN];
__device__ float g_pool[NRR * HID];
__device__ int   g_pcnt[NRR];

// ---------------- init ----------------
__global__ void k_init() {
    int i = blockIdx.x * blockDim.x + threadIdx.x;
    int st = gridDim.x * blockDim.x;
    for (int t = i; t < NRR * HID; t += st) g_pool[t] = 0.f;
    for (int t = i; t < NRR; t += st) { g_cnt_r[t] = 1; g_cur_r[t] = 0; g_pcnt[t] = 0; }
    for (int t = i; t < NCC; t += st) { g_cnt_c[t] = 1; g_cur_c[t] = 0; }
}

// ---------------- CSR build (branch-merged) ----------------
__global__ void k_count_both(const int* __restrict__ dst_r, const int* __restrict__ dst_c) {
    int i = blockIdx.x * blockDim.x + threadIdx.x;
    if (i < ERR) atomicAdd(&g_cnt_r[dst_r[i]], 1);
    else if (i - ERR < ECC) atomicAdd(&g_cnt_c[dst_c[i - ERR]], 1);
}

__device__ __forceinline__ void scan_body(const int* cnt, int* rp, int n) {
    __shared__ int part[1024];
    int t = threadIdx.x;
    int chunk = (n + 1023) / 1024;
    int beg = t * chunk, end = min(n, beg + chunk);
    int s = 0;
    for (int i = beg; i < end; i++) s += cnt[i];
    part[t] = s;
    __syncthreads();
    for (int off = 1; off < 1024; off <<= 1) {
        int v = (t >= off) ? part[t - off] : 0;
        __syncthreads();
        part[t] += v;
        __syncthreads();
    }
    int run = part[t] - s;
    for (int i = beg; i < end; i++) { rp[i] = run; run += cnt[i]; }
    if (t == 1023) rp[n] = part[1023];
}
__global__ void k_scan_both() {
    if (blockIdx.x == 0) scan_body(g_cnt_r, g_rp_r, NRR);
    else scan_body(g_cnt_c, g_rp_c, NCC);
}

__global__ void k_scatter_both(const int* __restrict__ ei_r, const int* __restrict__ ei_c) {
    int i = blockIdx.x * blockDim.x + threadIdx.x;
    if (i < ERR) {
        int d = ei_r[ERR + i];
        int pos = g_rp_r[d] + atomicAdd(&g_cur_r[d], 1);
        g_col_r[pos] = ei_r[i];
    } else if (i - ERR < ECC) {
        int j = i - ERR;
        int d = ei_c[ECC + j];
        int pos = g_rp_c[d] + atomicAdd(&g_cur_c[d], 1);
        g_col_c[pos] = ei_c[j];
    }
}

__global__ void k_selfloop_both() {
    int i = blockIdx.x * blockDim.x + threadIdx.x;
    if (i < NRR) g_col_r[g_rp_r[i + 1] - 1] = i;
    else if (i - NRR < NCC) { int j = i - NRR; g_col_c[g_rp_c[j + 1] - 1] = j; }
}

// ---------------- GAT stage bodies ----------------
__device__ __forceinline__ void lin1_body(int w, int lane, const float* __restrict__ x,
                                          const float* __restrict__ W, const float* __restrict__ as_,
                                          const float* __restrict__ ad_, float* __restrict__ h,
                                          float* __restrict__ es, float* __restrict__ ed) {
    float xv[DIN];
#pragma unroll
    for (int k = 0; k < DIN; k++) xv[k] = x[w * DIN + k];
    float hv[4], ps = 0.f, pd = 0.f;
#pragma unroll
    for (int q = 0; q < 4; q++) {
        int j = lane * 4 + q;
        float a = 0.f;
#pragma unroll
        for (int k = 0; k < DIN; k++) a = fmaf(xv[k], W[k * HID + j], a);
        hv[q] = a;
        ps = fmaf(a, as_[j], ps);
        pd = fmaf(a, ad_[j], pd);
    }
    *(float4*)&h[(size_t)w * HID + lane * 4] = make_float4(hv[0], hv[1], hv[2], hv[3]);
#pragma unroll
    for (int o = 16; o > 0; o >>= 1) {
        ps += __shfl_xor_sync(0xffffffffu, ps, o);
        pd += __shfl_xor_sync(0xffffffffu, pd, o);
    }
    if (lane == 0) { es[w] = ps; ed[w] = pd; }
}

__global__ void k_lin1_both(const float* xr, const float* Wr, const float* asr, const float* adr,
                            const float* xc, const float* Wc, const float* asc, const float* adc,
                            float* hr, float* hc) {
    int gw = (blockIdx.x * blockDim.x + threadIdx.x) >> 5;
    int lane = threadIdx.x & 31;
    if (blockIdx.x < WGR) {
        if (gw < NRR) lin1_body(gw, lane, xr, Wr, asr, adr, hr, g_es, g_ed);
    } else {
        int w = gw - WGR * 8;
        if (w < NCC) lin1_body(w, lane, xc, Wc, asc, adc, hc, g_es_c, g_ed_c);
    }
}

__device__ __forceinline__ void stats_body(int w, int lane, const int* __restrict__ rp,
                                           const int* __restrict__ col, const float* __restrict__ es,
                                           const float* __restrict__ edv, float* __restrict__ mv,
                                           float* __restrict__ dnv) {
    int beg = rp[w], end = rp[w + 1];
    float ed = edv[w];
    float m = -1e30f, s = 0.f;
    for (int idx = beg + lane; idx < end; idx += 32) {
        float e = es[col[idx]] + ed;
        e = e > 0.f ? e : NEG * e;
        float mn = fmaxf(m, e);
        s = s * __expf(m - mn) + __expf(e - mn);
        m = mn;
    }
#pragma unroll
    for (int o = 16; o > 0; o >>= 1) {
        float m2 = __shfl_xor_sync(0xffffffffu, m, o);
        float s2 = __shfl_xor_sync(0xffffffffu, s, o);
        float mn = fmaxf(m, m2);
        s = s * __expf(m - mn) + s2 * __expf(m2 - mn);
        m = mn;
    }
    if (lane == 0) { mv[w] = m; dnv[w] = s; }
}

__global__ void k_stats_both() {
    int gw = (blockIdx.x * blockDim.x + threadIdx.x) >> 5;
    int lane = threadIdx.x & 31;
    if (blockIdx.x < WGR) {
        if (gw < NRR) stats_body(gw, lane, g_rp_r, g_col_r, g_es, g_ed, g_mm, g_dn);
    } else {
        int w = gw - WGR * 8;
        if (w < NCC) stats_body(w, lane, g_rp_c, g_col_c, g_es_c, g_ed_c, g_mm_c, g_dn_c);
    }
}

__device__ __forceinline__ void agg_body(int w, int lane, const int* __restrict__ rp,
                                         const int* __restrict__ col, const float* __restrict__ hW,
                                         const float* __restrict__ es, const float* __restrict__ edv,
                                         const float* __restrict__ mv, const float* __restrict__ dnv,
                                         const float* __restrict__ bias, float* __restrict__ out) {
    int beg = rp[w], end = rp[w + 1];
    float ed = edv[w], md = mv[w];
    float inv = 1.f / fmaxf(dnv[w], 1e-16f);
    float a0 = 0.f, a1 = 0.f, a2 = 0.f, a3 = 0.f;
    for (int idx = beg; idx < end; idx++) {
        int s = col[idx];
        float e = es[s] + ed;
        e = e > 0.f ? e : NEG * e;
        float wgt = __expf(e - md) * inv;
        const float* hr = &hW[(size_t)s * HID];
        a0 = fmaf(wgt, hr[lane], a0);
        a1 = fmaf(wgt, hr[lane + 32], a1);
        a2 = fmaf(wgt, hr[lane + 64], a2);
        a3 = fmaf(wgt, hr[lane + 96], a3);
    }
    out[(size_t)w * HID + lane]      = fmaxf(a0 + bias[lane], 0.f);
    out[(size_t)w * HID + lane + 32] = fmaxf(a1 + bias[lane + 32], 0.f);
    out[(size_t)w * HID + lane + 64] = fmaxf(a2 + bias[lane + 64], 0.f);
    out[(size_t)w * HID + lane + 96] = fmaxf(a3 + bias[lane + 96], 0.f);
}

__global__ void k_agg_both(const float* hWr, const float* br, float* outr,
                           const float* hWc, const float* bc, float* outc) {
    int gw = (blockIdx.x * blockDim.x + threadIdx.x) >> 5;
    int lane = threadIdx.x & 31;
    if (blockIdx.x < WGR) {
        if (gw < NRR) agg_body(gw, lane, g_rp_r, g_col_r, hWr, g_es, g_ed, g_mm, g_dn, br, outr);
    } else {
        int w = gw - WGR * 8;
        if (w < NCC) agg_body(w, lane, g_rp_c, g_col_c, hWc, g_es_c, g_ed_c, g_mm_c, g_dn_c, bc, outc);
    }
}

__device__ __forceinline__ void gemm_body(int row0, int M, const float* __restrict__ A,
                                          const float* __restrict__ B, float* __restrict__ C) {
    __shared__ float As[16][64];
    __shared__ float Bs[16][128];
    int tid = threadIdx.x;
    int tc = tid & 31, tr = tid >> 5;
    float acc[8][4];
#pragma unroll
    for (int i = 0; i < 8; i++)
#pragma unroll
        for (int j = 0; j < 4; j++) acc[i][j] = 0.f;
    for (int k0 = 0; k0 < HID; k0 += 16) {
        int row_l = tid >> 2, quad = tid & 3;
        int gr = row0 + row_l;
        float4 av = make_float4(0.f, 0.f, 0.f, 0.f);
        if (gr < M) av = *(const float4*)&A[(size_t)gr * HID + k0 + quad * 4];
        As[quad * 4 + 0][row_l] = av.x;
        As[quad * 4 + 1][row_l] = av.y;
        As[quad * 4 + 2][row_l] = av.z;
        As[quad * 4 + 3][row_l] = av.w;
        int kk = tid >> 4, cp = tid & 15;
        float4 bv0 = *(const float4*)&B[(size_t)(k0 + kk) * HID + cp * 8];
        float4 bv1 = *(const float4*)&B[(size_t)(k0 + kk) * HID + cp * 8 + 4];
        *(float4*)&Bs[kk][cp * 8] = bv0;
        *(float4*)&Bs[kk][cp * 8 + 4] = bv1;
        __syncthreads();
#pragma unroll
        for (int k2 = 0; k2 < 16; k2++) {
            float4 a0 = *(float4*)&As[k2][tr * 8];
            float4 a1 = *(float4*)&As[k2][tr * 8 + 4];
            float4 bb = *(float4*)&Bs[k2][tc * 4];
            float a[8] = {a0.x, a0.y, a0.z, a0.w, a1.x, a1.y, a1.z, a1.w};
            float b[4] = {bb.x, bb.y, bb.z, bb.w};
#pragma unroll
            for (int i = 0; i < 8; i++)
#pragma unroll
                for (int j = 0; j < 4; j++) acc[i][j] = fmaf(a[i], b[j], acc[i][j]);
        }
        __syncthreads();
    }
#pragma unroll
    for (int i = 0; i < 8; i++) {
        int r = row0 + tr * 8 + i;
        if (r < M)
            *(float4*)&C[(size_t)r * HID + tc * 4] =
                make_float4(acc[i][0], acc[i][1], acc[i][2], acc[i][3]);
    }
}

__global__ void __launch_bounds__(256) k_gemm_both(const float* Ar, const float* Br, float* Cr,
                                                   const float* Ac, const float* Bc, float* Cc) {
    if (blockIdx.x < GBR) gemm_body(blockIdx.x * 64, NRR, Ar, Br, Cr);
    else gemm_body((blockIdx.x - GBR) * 64, NCC, Ac, Bc, Cc);
}

__device__ __forceinline__ void dots_body(int w, int lane, const float* __restrict__ h,
                                          const float* __restrict__ as_, const float* __restrict__ ad_,
                                          float* __restrict__ es, float* __restrict__ ed) {
    const float* hr = &h[(size_t)w * HID];
    float ps = 0.f, pd = 0.f;
#pragma unroll
    for (int t = 0; t < 4; t++) {
        int j = lane + 32 * t;
        float v = hr[j];
        ps = fmaf(v, as_[j], ps);
        pd = fmaf(v, ad_[j], pd);
    }
#pragma unroll
    for (int o = 16; o > 0; o >>= 1) {
        ps += __shfl_xor_sync(0xffffffffu, ps, o);
        pd += __shfl_xor_sync(0xffffffffu, pd, o);
    }
    if (lane == 0) { es[w] = ps; ed[w] = pd; }
}

__global__ void k_dots_both(const float* hr, const float* asr, const float* adr,
                            const float* hc, const float* asc, const float* adc) {
    int gw = (blockIdx.x * blockDim.x + threadIdx.x) >> 5;
    int lane = threadIdx.x & 31;
    if (blockIdx.x < WGR) {
        if (gw < NRR) dots_body(gw, lane, hr, asr, adr, g_es, g_ed);
    } else {
        int w = gw - WGR * 8;
        if (w < NCC) dots_body(w, lane, hc, asc, adc, g_es_c, g_ed_c);
    }
}

// ---------------- fused prep: norm + fp16 quad split (resting) ----------------
// warp per resting node: nr2 + quad-layout hi/lo fp16.
// 16B group g=(node*8+ks)*4+kcg holds [Hi(kb,kb+1) Hi(kb+8,kb+9) Lo(kb,kb+1) Lo(kb+8,kb+9)]
__global__ void k_prep_r(const float* __restrict__ h) {
    int w = (blockIdx.x * blockDim.x + threadIdx.x) >> 5;
    int lane = threadIdx.x & 31;
    if (w >= NRR) return;
    const float* hr = &h[(size_t)w * HID];
    float s = 0.f;
#pragma unroll
    for (int t = 0; t < 4; t++) {
        int k = lane + 32 * t;
        float x = hr[k];
        s = fmaf(x, x, s);
        __half hi = __float2half(x);
        __half lo = __float2half(x - __half2float(hi));
        int j = k & 15;
        int g = (w * 8 + (k >> 4)) * 4 + ((j >> 1) & 3);
        int slot = ((j >> 3) << 1) | (j & 1);
        __half* base = (__half*)g_brq + (size_t)g * 8;
        base[slot] = hi;
        base[4 + slot] = lo;
    }
#pragma unroll
    for (int o = 16; o > 0; o >>= 1) s += __shfl_xor_sync(0xffffffffu, s, o);
    if (lane == 0) g_nr2[w] = s;
}

// collider: fp16 hi only (2-term split uses A_hi exclusively)
__global__ void k_prep_c(const float* __restrict__ h) {
    int i = blockIdx.x * blockDim.x + threadIdx.x;
    if (i < NCC * HID) g_ach[i] = __float2half(h[i]);
}

// ---------------- comparators ----------------
__device__ __forceinline__ bool d2_less(float v1, int i1, float v2, int i2) {
    return (v1 < v2) || (v1 == v2 && i1 < i2);
}
__device__ __forceinline__ void top3_upd(float v, int r, float tv[3], int ti[3]) {
    if (d2_less(v, r, tv[2], ti[2])) {
        tv[2] = v; ti[2] = r;
        if (d2_less(tv[2], ti[2], tv[1], ti[1])) {
            float a = tv[1]; int b = ti[1]; tv[1] = tv[2]; ti[1] = ti[2]; tv[2] = a; ti[2] = b;
        }
        if (d2_less(tv[1], ti[1], tv[0], ti[0])) {
            float a = tv[0]; int b = ti[0]; tv[0] = tv[1]; ti[0] = ti[1]; tv[1] = a; ti[1] = b;
        }
    }
}
__device__ __forceinline__ void top4_upd(float v, int r, float tv[4], int ti[4]) {
    if (d2_less(v, r, tv[3], ti[3])) {
        tv[3] = v; ti[3] = r;
#pragma unroll
        for (int k = 3; k > 0; k--) {
            if (d2_less(tv[k], ti[k], tv[k - 1], ti[k - 1])) {
                float a = tv[k - 1]; int b = ti[k - 1];
                tv[k - 1] = tv[k]; ti[k - 1] = ti[k];
                tv[k] = a; ti[k] = b;
            }
        }
    }
}

// ---------------- HMMA KNN candidate kernel (fp16 2-term) ----------------
// grid (CTILES, RSPLIT), 256 threads. dot ≈ Ahi·(Bhi+Blo); error ~2^-11 rel,
// absorbed by the per-thread top-4 margin + exact fp32 rescore.
#define BROW 36   // uint4 per smem row (32 data + 4 pad)
__global__ void __launch_bounds__(256, 2) k_knn_mma(const float* __restrict__ nr2) {
    __shared__ __align__(16) uint4 Bs[64 * BROW];
    __shared__ float NrS[64];

    int tid = threadIdx.x;
    int l = tid & 31, w = tid >> 5;
    int cb = blockIdx.x * 128;
    int rbeg = blockIdx.y * RROWS;
    int rend = rbeg + RROWS;

    // ---- A_hi fragments in registers ----
    int m0 = cb + w * 16 + (l >> 2);
    int aR0 = min(m0, NCC - 1);
    int aR1 = min(m0 + 8, NCC - 1);
    int kc = (l & 3) * 2;
    uint32_t Ah[8][4];
#pragma unroll
    for (int ks = 0; ks < 8; ks++) {
        int k0 = ks * 16 + kc;
        Ah[ks][0] = *(const uint32_t*)&g_ach[(size_t)aR0 * HID + k0];
        Ah[ks][1] = *(const uint32_t*)&g_ach[(size_t)aR1 * HID + k0];
        Ah[ks][2] = *(const uint32_t*)&g_ach[(size_t)aR0 * HID + k0 + 8];
        Ah[ks][3] = *(const uint32_t*)&g_ach[(size_t)aR1 * HID + k0 + 8];
    }

    float tvA[4] = {1e30f, 1e30f, 1e30f, 1e30f};
    float tvB[4] = {1e30f, 1e30f, 1e30f, 1e30f};
    int tiA[4] = {0x7fffffff, 0x7fffffff, 0x7fffffff, 0x7fffffff};
    int tiB[4] = {0x7fffffff, 0x7fffffff, 0x7fffffff, 0x7fffffff};

    int kcg = l & 3;

    for (int rt = rbeg; rt < rend; rt += 64) {
        for (int idx = tid; idx < 2048; idx += 256) {
            int row = idx >> 5, i = idx & 31;
            int gr = rt + row;
            uint4 v = make_uint4(0, 0, 0, 0);
            if (gr < rend) v = g_brq[(size_t)gr * 32 + i];
            Bs[row * BROW + i] = v;
        }
        if (tid < 64) NrS[tid] = (rt + tid < rend) ? nr2[rt + tid] : 1e30f;
        __syncthreads();

#pragma unroll
        for (int np = 0; np < 4; np++) {
            int nA = (np * 2) * 8 + (l >> 2);
            int nB = (np * 2 + 1) * 8 + (l >> 2);
            float acc0[4] = {0.f, 0.f, 0.f, 0.f};
            float acc1[4] = {0.f, 0.f, 0.f, 0.f};
#pragma unroll
            for (int ks = 0; ks < 8; ks++) {
                uint4 va = Bs[nA * BROW + ks * 4 + kcg];
                uint4 vb = Bs[nB * BROW + ks * 4 + kcg];
                MMA16816(acc0, Ah[ks], va.x, va.y);   // A_hi * B_hi
                MMA16816(acc1, Ah[ks], vb.x, vb.y);
                MMA16816(acc0, Ah[ks], va.z, va.w);   // A_hi * B_lo
                MMA16816(acc1, Ah[ks], vb.z, vb.w);
            }
            int c0a = (np * 2) * 8 + (l & 3) * 2;
            int c0b = (np * 2 + 1) * 8 + (l & 3) * 2;
            int ra = rt + c0a, rb2 = rt + c0b;
            float na0 = NrS[c0a], na1 = NrS[c0a + 1];
            float nb0 = NrS[c0b], nb1 = NrS[c0b + 1];
            top4_upd(na0 - 2.f * acc0[0], ra, tvA, tiA);
            top4_upd(na1 - 2.f * acc0[1], ra + 1, tvA, tiA);
            top4_upd(na0 - 2.f * acc0[2], ra, tvB, tiB);
            top4_upd(na1 - 2.f * acc0[3], ra + 1, tvB, tiB);
            top4_upd(nb0 - 2.f * acc1[0], rb2, tvA, tiA);
            top4_upd(nb1 - 2.f * acc1[1], rb2 + 1, tvA, tiA);
            top4_upd(nb0 - 2.f * acc1[2], rb2, tvB, tiB);
            top4_upd(nb1 - 2.f * acc1[3], rb2 + 1, tvB, tiB);
        }
        __syncthreads();
    }

    int cA = cb + w * 16 + (l >> 2);
    int cB = cA + 8;
    if (cA < NCC) {
        size_t base = ((size_t)blockIdx.y * NCC + cA) * NCAND + (l & 3) * 4;
#pragma unroll
        for (int k = 0; k < 4; k++) g_ci[base + k] = tiA[k];
    }
    if (cB < NCC) {
        size_t base = ((size_t)blockIdx.y * NCC + cB) * NCAND + (l & 3) * 4;
#pragma unroll
        for (int k = 0; k < 4; k++) g_ci[base + k] = tiB[k];
    }
}

// ---------------- exact fp32 rescore + fused pooling ----------------
__global__ void k_rescore_pool(const float* __restrict__ hc, const float* __restrict__ hr,
                               const float* __restrict__ nr2) {
    int w = (blockIdx.x * blockDim.x + threadIdx.x) >> 5;
    int lane = threadIdx.x & 31;
    if (w >= NCC) return;
    float c0 = hc[(size_t)w * HID + lane];
    float c1 = hc[(size_t)w * HID + lane + 32];
    float c2 = hc[(size_t)w * HID + lane + 64];
    float c3 = hc[(size_t)w * HID + lane + 96];
    float f[3] = {1e30f, 1e30f, 1e30f};
    int   j[3] = {0x7fffffff, 0x7fffffff, 0x7fffffff};
    for (int s = 0; s < RSPLIT; s++) {
        size_t base = ((size_t)s * NCC + w) * NCAND;
        for (int k = 0; k < NCAND; k++) {
            int r = g_ci[base + k];
            if ((unsigned)r >= (unsigned)NRR) continue;
            const float* hrr = &hr[(size_t)r * HID];
            float p = 0.f;
            p = fmaf(c0, hrr[lane], p);
            p = fmaf(c1, hrr[lane + 32], p);
            p = fmaf(c2, hrr[lane + 64], p);
            p = fmaf(c3, hrr[lane + 96], p);
#pragma unroll
            for (int o = 16; o > 0; o >>= 1) p += __shfl_xor_sync(0xffffffffu, p, o);
            if (lane == 0) {
                float key = nr2[r] - 2.f * p;
                top3_upd(key, r, f, j);
            }
        }
    }
    // broadcast neighbors, write g_nn, then pool in place (hc row in regs)
#pragma unroll
    for (int k = 0; k < KNN; k++) {
        int nn = __shfl_sync(0xffffffffu, j[k], 0);
        if (lane == 0) {
            g_nn[w * 3 + k] = nn;
            atomicAdd(&g_pcnt[nn], 1);
        }
        atomicAdd(&g_pool[(size_t)nn * HID + lane], c0);
        atomicAdd(&g_pool[(size_t)nn * HID + lane + 32], c1);
        atomicAdd(&g_pool[(size_t)nn * HID + lane + 64], c2);
        atomicAdd(&g_pool[(size_t)nn * HID + lane + 96], c3);
    }
}

// ---------------- decoder ----------------
__global__ void k_dec(const float* __restrict__ hr, const float* __restrict__ Wd,
                      const float* __restrict__ bd, float* __restrict__ out) {
    int w = (blockIdx.x * blockDim.x + threadIdx.x) >> 5;
    int lane = threadIdx.x & 31;
    if (w >= NRR) return;
    float inv = 1.f / fmaxf((float)g_pcnt[w], 1.f);
    float a0 = 0.f, a1 = 0.f, a2 = 0.f;
#pragma unroll
    for (int t = 0; t < 4; t++) {
        int j = lane + 32 * t;
        float hv = hr[(size_t)w * HID + j];
        float pv = g_pool[(size_t)w * HID + j] * inv;
        a0 = fmaf(hv, Wd[j * 3 + 0], a0); a0 = fmaf(pv, Wd[(HID + j) * 3 + 0], a0);
        a1 = fmaf(hv, Wd[j * 3 + 1], a1); a1 = fmaf(pv, Wd[(HID + j) * 3 + 1], a1);
        a2 = fmaf(hv, Wd[j * 3 + 2], a2); a2 = fmaf(pv, Wd[(HID + j) * 3 + 2], a2);
    }
#pragma unroll
    for (int o = 16; o > 0; o >>= 1) {
        a0 += __shfl_xor_sync(0xffffffffu, a0, o);
        a1 += __shfl_xor_sync(0xffffffffu, a1, o);
        a2 += __shfl_xor_sync(0xffffffffu, a2, o);
    }
    if (lane == 0) {
        out[w * 3 + 0] = a0 + bd[0];
        out[w * 3 + 1] = a1 + bd[1];
        out[w * 3 + 2] = a2 + bd[2];
    }
}

// ---------------- host launcher ----------------
extern "C" void kernel_launch(void* const* d_in, const int* in_sizes, int n_in,
                              void* d_out, int out_size) {
    const float* x_r  = (const float*)d_in[0];
    const float* x_c  = (const float*)d_in[1];
    const int*   ei_r = (const int*)d_in[2];
    const int*   ei_c = (const int*)d_in[3];
    const float* W_r1  = (const float*)d_in[5];
    const float* as_r1 = (const float*)d_in[6];
    const float* ad_r1 = (const float*)d_in[7];
    const float* b_r1  = (const float*)d_in[8];
    const float* W_r2  = (const float*)d_in[9];
    const float* as_r2 = (const float*)d_in[10];
    const float* ad_r2 = (const float*)d_in[11];
    const float* b_r2  = (const float*)d_in[12];
    const float* W_c1  = (const float*)d_in[13];
    const float* as_c1 = (const float*)d_in[14];
    const float* ad_c1 = (const float*)d_in[15];
    const float* b_c1  = (const float*)d_in[16];
    const float* W_c2  = (const float*)d_in[17];
    const float* as_c2 = (const float*)d_in[18];
    const float* ad_c2 = (const float*)d_in[19];
    const float* b_c2  = (const float*)d_in[20];
    const float* W_dec = (const float*)d_in[21];
    const float* b_dec = (const float*)d_in[22];
    float* out = (float*)d_out;

    float *hw_r, *h1_r, *h2_r, *hw_c, *h1_c, *h2_c, *nr2;
    cudaGetSymbolAddress((void**)&hw_r, g_hw_r);
    cudaGetSymbolAddress((void**)&h1_r, g_h1_r);
    cudaGetSymbolAddress((void**)&h2_r, g_h2_r);
    cudaGetSymbolAddress((void**)&hw_c, g_hw_c);
    cudaGetSymbolAddress((void**)&h1_c, g_h1_c);
    cudaGetSymbolAddress((void**)&h2_c, g_h2_c);
    cudaGetSymbolAddress((void**)&nr2, g_nr2);

    k_init<<<1024, 256>>>();

    // CSR (branch-merged)
    k_count_both<<<(ERR + ECC + 255) / 256, 256>>>(ei_r + ERR, ei_c + ECC);
    k_scan_both<<<2, 1024>>>();
    k_scatter_both<<<(ERR + ECC + 255) / 256, 256>>>(ei_r, ei_c);
    k_selfloop_both<<<(NRR + NCC + 255) / 256, 256>>>();

    const int WB = WGR + WGC;

    // layer 1
    k_lin1_both<<<WB, 256>>>(x_r, W_r1, as_r1, ad_r1, x_c, W_c1, as_c1, ad_c1, hw_r, hw_c);
    k_stats_both<<<WB, 256>>>();
    k_agg_both<<<WB, 256>>>(hw_r, b_r1, h1_r, hw_c, b_c1, h1_c);
    // layer 2
    k_gemm_both<<<GBR + GBC, 256>>>(h1_r, W_r2, hw_r, h1_c, W_c2, hw_c);
    k_dots_both<<<WB, 256>>>(hw_r, as_r2, ad_r2, hw_c, as_c2, ad_c2);
    k_stats_both<<<WB, 256>>>();
    k_agg_both<<<WB, 256>>>(hw_r, b_r2, h2_r, hw_c, b_c2, h2_c);

    // KNN: fp16 2-term HMMA candidates -> exact fp32 rescore + pool
    k_prep_r<<<WGR, 256>>>(h2_r);
    k_prep_c<<<(NCC * HID + 255) / 256, 256>>>(h2_c);
    dim3 kg(CTILES, RSPLIT);
    k_knn_mma<<<kg, 256>>>(nr2);
    k_rescore_pool<<<(NCC * 32 + 255) / 256, 256>>>(h2_c, h2_r, nr2);
    k_dec<<<WGR, 256>>>(h2_r, W_dec, b_dec, out);
}

// round 10
// speedup vs baseline: 4.0129x; 1.1189x over previous
#include <cuda_runtime.h>
#include <cuda_fp16.h>
#include <math.h>
#include <cstdint>

// ---------------- problem constants ----------------
#define NRR 20000
#define NCC 5000
#define ERR 320000
#define ECC 80000
#define DIN 6
#define HID 128
#define KNN 3
#define NEG 0.2f

#define CTILES 40        // ceil(NCC/128)
#define RSPLIT 8
#define RROWS 2500       // NRR / RSPLIT (exact)
#define NCAND 16         // candidates per (split, collider)

#define WGR 2500         // NRR/8 warp-per-node blocks
#define WGC 625          // NCC/8
#define GBR 313          // ceil(NRR/64) gemm blocks
#define GBC 79           // ceil(NCC/64)

// ---------------- mma.sync m16n8k16 fp16 ----------------
#define MMA16816(c, a, b0, b1) \
    asm volatile("mma.sync.aligned.m16n8k16.row.col.f32.f16.f16.f32 " \
        "{%0,%1,%2,%3}, {%4,%5,%6,%7}, {%8,%9}, {%0,%1,%2,%3};" \
        : "+f"((c)[0]), "+f"((c)[1]), "+f"((c)[2]), "+f"((c)[3]) \
        : "r"((a)[0]), "r"((a)[1]), "r"((a)[2]), "r"((a)[3]), "r"(b0), "r"(b1))

// ---------------- static scratch ----------------
__device__ float g_hw_r[NRR * HID];
__device__ float g_h1_r[NRR * HID];
__device__ float g_h2_r[NRR * HID];
__device__ float g_hw_c[NCC * HID];
__device__ float g_h1_c[NCC * HID];
__device__ float g_h2_c[NCC * HID];
__device__ float g_es[NRR];
__device__ float g_ed[NRR];
__device__ float g_es_c[NCC];
__device__ float g_ed_c[NCC];
__device__ int   g_cnt_r[NRR];
__device__ int   g_cur_r[NRR];
__device__ int   g_rp_r[NRR + 1];
__device__ int   g_col_r[ERR + NRR];
__device__ int   g_cnt_c[NCC];
__device__ int   g_cur_c[NCC];
__device__ int   g_rp_c[NCC + 1];
__device__ int   g_col_c[ECC + NCC];
__device__ float g_nr2[NRR];
__device__ __half g_ach[NCC * HID];          // collider hi (A fragments, fp16)
__device__ uint4  g_brq[NRR * 32];           // resting hi/lo fp16 fragment-quad layout
__device__ int   g_ci[RSPLIT * NCC * NCAND];
__device__ int   g_nn[NCC * KNN];
__device__ float g_pool[NRR * HID];
__device__ int   g_pcnt[NRR];

// ---------------- init ----------------
__global__ void k_init() {
    int i = blockIdx.x * blockDim.x + threadIdx.x;
    int st = gridDim.x * blockDim.x;
    for (int t = i; t < NRR * HID; t += st) g_pool[t] = 0.f;
    for (int t = i; t < NRR; t += st) { g_cnt_r[t] = 1; g_cur_r[t] = 0; g_pcnt[t] = 0; }
    for (int t = i; t < NCC; t += st) { g_cnt_c[t] = 1; g_cur_c[t] = 0; }
}

// ---------------- CSR build (branch-merged) ----------------
__global__ void k_count_both(const int* __restrict__ dst_r, const int* __restrict__ dst_c) {
    int i = blockIdx.x * blockDim.x + threadIdx.x;
    if (i < ERR) atomicAdd(&g_cnt_r[dst_r[i]], 1);
    else if (i - ERR < ECC) atomicAdd(&g_cnt_c[dst_c[i - ERR]], 1);
}

__device__ __forceinline__ void scan_body(const int* cnt, int* rp, int n) {
    __shared__ int part[1024];
    int t = threadIdx.x;
    int chunk = (n + 1023) / 1024;
    int beg = t * chunk, end = min(n, beg + chunk);
    int s = 0;
    for (int i = beg; i < end; i++) s += cnt[i];
    part[t] = s;
    __syncthreads();
    for (int off = 1; off < 1024; off <<= 1) {
        int v = (t >= off) ? part[t - off] : 0;
        __syncthreads();
        part[t] += v;
        __syncthreads();
    }
    int run = part[t] - s;
    for (int i = beg; i < end; i++) { rp[i] = run; run += cnt[i]; }
    if (t == 1023) rp[n] = part[1023];
}
__global__ void k_scan_both() {
    if (blockIdx.x == 0) scan_body(g_cnt_r, g_rp_r, NRR);
    else scan_body(g_cnt_c, g_rp_c, NCC);
}

__global__ void k_scatter_both(const int* __restrict__ ei_r, const int* __restrict__ ei_c) {
    int i = blockIdx.x * blockDim.x + threadIdx.x;
    if (i < ERR) {
        int d = ei_r[ERR + i];
        int pos = g_rp_r[d] + atomicAdd(&g_cur_r[d], 1);
        g_col_r[pos] = ei_r[i];
    } else if (i - ERR < ECC) {
        int j = i - ERR;
        int d = ei_c[ECC + j];
        int pos = g_rp_c[d] + atomicAdd(&g_cur_c[d], 1);
        g_col_c[pos] = ei_c[j];
    }
}

__global__ void k_selfloop_both() {
    int i = blockIdx.x * blockDim.x + threadIdx.x;
    if (i < NRR) g_col_r[g_rp_r[i + 1] - 1] = i;
    else if (i - NRR < NCC) { int j = i - NRR; g_col_c[g_rp_c[j + 1] - 1] = j; }
}

// ---------------- GAT stage bodies ----------------
__device__ __forceinline__ void lin1_body(int w, int lane, const float* __restrict__ x,
                                          const float* __restrict__ W, const float* __restrict__ as_,
                                          const float* __restrict__ ad_, float* __restrict__ h,
                                          float* __restrict__ es, float* __restrict__ ed) {
    float xv[DIN];
#pragma unroll
    for (int k = 0; k < DIN; k++) xv[k] = x[w * DIN + k];
    float hv[4], ps = 0.f, pd = 0.f;
#pragma unroll
    for (int q = 0; q < 4; q++) {
        int j = lane * 4 + q;
        float a = 0.f;
#pragma unroll
        for (int k = 0; k < DIN; k++) a = fmaf(xv[k], W[k * HID + j], a);
        hv[q] = a;
        ps = fmaf(a, as_[j], ps);
        pd = fmaf(a, ad_[j], pd);
    }
    *(float4*)&h[(size_t)w * HID + lane * 4] = make_float4(hv[0], hv[1], hv[2], hv[3]);
#pragma unroll
    for (int o = 16; o > 0; o >>= 1) {
        ps += __shfl_xor_sync(0xffffffffu, ps, o);
        pd += __shfl_xor_sync(0xffffffffu, pd, o);
    }
    if (lane == 0) { es[w] = ps; ed[w] = pd; }
}

__global__ void k_lin1_both(const float* xr, const float* Wr, const float* asr, const float* adr,
                            const float* xc, const float* Wc, const float* asc, const float* adc,
                            float* hr, float* hc) {
    int gw = (blockIdx.x * blockDim.x + threadIdx.x) >> 5;
    int lane = threadIdx.x & 31;
    if (blockIdx.x < WGR) {
        if (gw < NRR) lin1_body(gw, lane, xr, Wr, asr, adr, hr, g_es, g_ed);
    } else {
        int w = gw - WGR * 8;
        if (w < NCC) lin1_body(w, lane, xc, Wc, asc, adc, hc, g_es_c, g_ed_c);
    }
}

// fused softmax-stats + aggregation (+ optional layer-2 prep epilogue)
// PREP: 0 = none, 1 = resting (nr2 + fp16 quad split), 2 = collider (fp16 cast)
template <int PREP>
__device__ __forceinline__ void gat_fused(int w, int lane, const int* __restrict__ rp,
                                          const int* __restrict__ col, const float* __restrict__ hW,
                                          const float* __restrict__ es, const float* __restrict__ edv,
                                          const float* __restrict__ bias, float* __restrict__ out) {
    int beg = rp[w], end = rp[w + 1];
    float ed = edv[w];
    // pass 1: online max+sum (butterfly leaves result in ALL lanes)
    float m = -1e30f, s = 0.f;
    for (int idx = beg + lane; idx < end; idx += 32) {
        float e = es[col[idx]] + ed;
        e = e > 0.f ? e : NEG * e;
        float mn = fmaxf(m, e);
        s = s * __expf(m - mn) + __expf(e - mn);
        m = mn;
    }
#pragma unroll
    for (int o = 16; o > 0; o >>= 1) {
        float m2 = __shfl_xor_sync(0xffffffffu, m, o);
        float s2 = __shfl_xor_sync(0xffffffffu, s, o);
        float mn = fmaxf(m, m2);
        s = s * __expf(m - mn) + s2 * __expf(m2 - mn);
        m = mn;
    }
    float inv = 1.f / fmaxf(s, 1e-16f);
    // pass 2: weighted aggregation
    float a0 = 0.f, a1 = 0.f, a2 = 0.f, a3 = 0.f;
    for (int idx = beg; idx < end; idx++) {
        int sc = col[idx];
        float e = es[sc] + ed;
        e = e > 0.f ? e : NEG * e;
        float wgt = __expf(e - m) * inv;
        const float* hr = &hW[(size_t)sc * HID];
        a0 = fmaf(wgt, hr[lane], a0);
        a1 = fmaf(wgt, hr[lane + 32], a1);
        a2 = fmaf(wgt, hr[lane + 64], a2);
        a3 = fmaf(wgt, hr[lane + 96], a3);
    }
    float v0 = fmaxf(a0 + bias[lane], 0.f);
    float v1 = fmaxf(a1 + bias[lane + 32], 0.f);
    float v2 = fmaxf(a2 + bias[lane + 64], 0.f);
    float v3 = fmaxf(a3 + bias[lane + 96], 0.f);
    out[(size_t)w * HID + lane]      = v0;
    out[(size_t)w * HID + lane + 32] = v1;
    out[(size_t)w * HID + lane + 64] = v2;
    out[(size_t)w * HID + lane + 96] = v3;

    if (PREP == 1) {
        float vv[4] = {v0, v1, v2, v3};
        float nsum = 0.f;
#pragma unroll
        for (int t = 0; t < 4; t++) {
            int k = lane + 32 * t;
            float x = vv[t];
            nsum = fmaf(x, x, nsum);
            __half hi = __float2half(x);
            __half lo = __float2half(x - __half2float(hi));
            int j = k & 15;
            int g = (w * 8 + (k >> 4)) * 4 + ((j >> 1) & 3);
            int slot = ((j >> 3) << 1) | (j & 1);
            __half* base = (__half*)g_brq + (size_t)g * 8;
            base[slot] = hi;
            base[4 + slot] = lo;
        }
#pragma unroll
        for (int o = 16; o > 0; o >>= 1) nsum += __shfl_xor_sync(0xffffffffu, nsum, o);
        if (lane == 0) g_nr2[w] = nsum;
    } else if (PREP == 2) {
        g_ach[(size_t)w * HID + lane]      = __float2half(v0);
        g_ach[(size_t)w * HID + lane + 32] = __float2half(v1);
        g_ach[(size_t)w * HID + lane + 64] = __float2half(v2);
        g_ach[(size_t)w * HID + lane + 96] = __float2half(v3);
    }
}

__global__ void k_gat1_both(const float* hWr, const float* br, float* outr,
                            const float* hWc, const float* bc, float* outc) {
    int gw = (blockIdx.x * blockDim.x + threadIdx.x) >> 5;
    int lane = threadIdx.x & 31;
    if (blockIdx.x < WGR) {
        if (gw < NRR) gat_fused<0>(gw, lane, g_rp_r, g_col_r, hWr, g_es, g_ed, br, outr);
    } else {
        int w = gw - WGR * 8;
        if (w < NCC) gat_fused<0>(w, lane, g_rp_c, g_col_c, hWc, g_es_c, g_ed_c, bc, outc);
    }
}

__global__ void k_gat2_both(const float* hWr, const float* br, float* outr,
                            const float* hWc, const float* bc, float* outc) {
    int gw = (blockIdx.x * blockDim.x + threadIdx.x) >> 5;
    int lane = threadIdx.x & 31;
    if (blockIdx.x < WGR) {
        if (gw < NRR) gat_fused<1>(gw, lane, g_rp_r, g_col_r, hWr, g_es, g_ed, br, outr);
    } else {
        int w = gw - WGR * 8;
        if (w < NCC) gat_fused<2>(w, lane, g_rp_c, g_col_c, hWc, g_es_c, g_ed_c, bc, outc);
    }
}

__device__ __forceinline__ void gemm_body(int row0, int M, const float* __restrict__ A,
                                          const float* __restrict__ B, float* __restrict__ C) {
    __shared__ float As[16][64];
    __shared__ float Bs[16][128];
    int tid = threadIdx.x;
    int tc = tid & 31, tr = tid >> 5;
    float acc[8][4];
#pragma unroll
    for (int i = 0; i < 8; i++)
#pragma unroll
        for (int j = 0; j < 4; j++) acc[i][j] = 0.f;
    for (int k0 = 0; k0 < HID; k0 += 16) {
        int row_l = tid >> 2, quad = tid & 3;
        int gr = row0 + row_l;
        float4 av = make_float4(0.f, 0.f, 0.f, 0.f);
        if (gr < M) av = *(const float4*)&A[(size_t)gr * HID + k0 + quad * 4];
        As[quad * 4 + 0][row_l] = av.x;
        As[quad * 4 + 1][row_l] = av.y;
        As[quad * 4 + 2][row_l] = av.z;
        As[quad * 4 + 3][row_l] = av.w;
        int kk = tid >> 4, cp = tid & 15;
        float4 bv0 = *(const float4*)&B[(size_t)(k0 + kk) * HID + cp * 8];
        float4 bv1 = *(const float4*)&B[(size_t)(k0 + kk) * HID + cp * 8 + 4];
        *(float4*)&Bs[kk][cp * 8] = bv0;
        *(float4*)&Bs[kk][cp * 8 + 4] = bv1;
        __syncthreads();
#pragma unroll
        for (int k2 = 0; k2 < 16; k2++) {
            float4 a0 = *(float4*)&As[k2][tr * 8];
            float4 a1 = *(float4*)&As[k2][tr * 8 + 4];
            float4 bb = *(float4*)&Bs[k2][tc * 4];
            float a[8] = {a0.x, a0.y, a0.z, a0.w, a1.x, a1.y, a1.z, a1.w};
            float b[4] = {bb.x, bb.y, bb.z, bb.w};
#pragma unroll
            for (int i = 0; i < 8; i++)
#pragma unroll
                for (int j = 0; j < 4; j++) acc[i][j] = fmaf(a[i], b[j], acc[i][j]);
        }
        __syncthreads();
    }
#pragma unroll
    for (int i = 0; i < 8; i++) {
        int r = row0 + tr * 8 + i;
        if (r < M)
            *(float4*)&C[(size_t)r * HID + tc * 4] =
                make_float4(acc[i][0], acc[i][1], acc[i][2], acc[i][3]);
    }
}

__global__ void __launch_bounds__(256) k_gemm_both(const float* Ar, const float* Br, float* Cr,
                                                   const float* Ac, const float* Bc, float* Cc) {
    if (blockIdx.x < GBR) gemm_body(blockIdx.x * 64, NRR, Ar, Br, Cr);
    else gemm_body((blockIdx.x - GBR) * 64, NCC, Ac, Bc, Cc);
}

__device__ __forceinline__ void dots_body(int w, int lane, const float* __restrict__ h,
                                          const float* __restrict__ as_, const float* __restrict__ ad_,
                                          float* __restrict__ es, float* __restrict__ ed) {
    const float* hr = &h[(size_t)w * HID];
    float ps = 0.f, pd = 0.f;
#pragma unroll
    for (int t = 0; t < 4; t++) {
        int j = lane + 32 * t;
        float v = hr[j];
        ps = fmaf(v, as_[j], ps);
        pd = fmaf(v, ad_[j], pd);
    }
#pragma unroll
    for (int o = 16; o > 0; o >>= 1) {
        ps += __shfl_xor_sync(0xffffffffu, ps, o);
        pd += __shfl_xor_sync(0xffffffffu, pd, o);
    }
    if (lane == 0) { es[w] = ps; ed[w] = pd; }
}

__global__ void k_dots_both(const float* hr, const float* asr, const float* adr,
                            const float* hc, const float* asc, const float* adc) {
    int gw = (blockIdx.x * blockDim.x + threadIdx.x) >> 5;
    int lane = threadIdx.x & 31;
    if (blockIdx.x < WGR) {
        if (gw < NRR) dots_body(gw, lane, hr, asr, adr, g_es, g_ed);
    } else {
        int w = gw - WGR * 8;
        if (w < NCC) dots_body(w, lane, hc, asc, adc, g_es_c, g_ed_c);
    }
}

// ---------------- comparators ----------------
__device__ __forceinline__ bool d2_less(float v1, int i1, float v2, int i2) {
    return (v1 < v2) || (v1 == v2 && i1 < i2);
}
__device__ __forceinline__ void top3_upd(float v, int r, float tv[3], int ti[3]) {
    if (d2_less(v, r, tv[2], ti[2])) {
        tv[2] = v; ti[2] = r;
        if (d2_less(tv[2], ti[2], tv[1], ti[1])) {
            float a = tv[1]; int b = ti[1]; tv[1] = tv[2]; ti[1] = ti[2]; tv[2] = a; ti[2] = b;
        }
        if (d2_less(tv[1], ti[1], tv[0], ti[0])) {
            float a = tv[0]; int b = ti[0]; tv[0] = tv[1]; ti[0] = ti[1]; tv[1] = a; ti[1] = b;
        }
    }
}
__device__ __forceinline__ void top4_upd(float v, int r, float tv[4], int ti[4]) {
    if (d2_less(v, r, tv[3], ti[3])) {
        tv[3] = v; ti[3] = r;
#pragma unroll
        for (int k = 3; k > 0; k--) {
            if (d2_less(tv[k], ti[k], tv[k - 1], ti[k - 1])) {
                float a = tv[k - 1]; int b = ti[k - 1];
                tv[k - 1] = tv[k]; ti[k - 1] = ti[k];
                tv[k] = a; ti[k] = b;
            }
        }
    }
}

// ---------------- HMMA KNN candidate kernel (fp16 2-term, occ-3) ----------------
#define BROW 36   // uint4 per smem row (32 data + 4 pad)
__global__ void __launch_bounds__(256, 3) k_knn_mma(const float* __restrict__ nr2) {
    __shared__ __align__(16) uint4 Bs[64 * BROW];
    __shared__ float NrS[64];

    int tid = threadIdx.x;
    int l = tid & 31, w = tid >> 5;
    int cb = blockIdx.x * 128;
    int rbeg = blockIdx.y * RROWS;
    int rend = rbeg + RROWS;

    int m0 = cb + w * 16 + (l >> 2);
    int aR0 = min(m0, NCC - 1);
    int aR1 = min(m0 + 8, NCC - 1);
    int kc = (l & 3) * 2;
    uint32_t Ah[8][4];
#pragma unroll
    for (int ks = 0; ks < 8; ks++) {
        int k0 = ks * 16 + kc;
        Ah[ks][0] = *(const uint32_t*)&g_ach[(size_t)aR0 * HID + k0];
        Ah[ks][1] = *(const uint32_t*)&g_ach[(size_t)aR1 * HID + k0];
        Ah[ks][2] = *(const uint32_t*)&g_ach[(size_t)aR0 * HID + k0 + 8];
        Ah[ks][3] = *(const uint32_t*)&g_ach[(size_t)aR1 * HID + k0 + 8];
    }

    float tvA[4] = {1e30f, 1e30f, 1e30f, 1e30f};
    float tvB[4] = {1e30f, 1e30f, 1e30f, 1e30f};
    int tiA[4] = {0x7fffffff, 0x7fffffff, 0x7fffffff, 0x7fffffff};
    int tiB[4] = {0x7fffffff, 0x7fffffff, 0x7fffffff, 0x7fffffff};

    int kcg = l & 3;

    for (int rt = rbeg; rt < rend; rt += 64) {
        for (int idx = tid; idx < 2048; idx += 256) {
            int row = idx >> 5, i = idx & 31;
            int gr = rt + row;
            uint4 v = make_uint4(0, 0, 0, 0);
            if (gr < rend) v = g_brq[(size_t)gr * 32 + i];
            Bs[row * BROW + i] = v;
        }
        if (tid < 64) NrS[tid] = (rt + tid < rend) ? nr2[rt + tid] : 1e30f;
        __syncthreads();

#pragma unroll
        for (int np = 0; np < 4; np++) {
            int nA = (np * 2) * 8 + (l >> 2);
            int nB = (np * 2 + 1) * 8 + (l >> 2);
            float acc0[4] = {0.f, 0.f, 0.f, 0.f};
            float acc1[4] = {0.f, 0.f, 0.f, 0.f};
#pragma unroll
            for (int ks = 0; ks < 8; ks++) {
                uint4 va = Bs[nA * BROW + ks * 4 + kcg];
                uint4 vb = Bs[nB * BROW + ks * 4 + kcg];
                MMA16816(acc0, Ah[ks], va.x, va.y);
                MMA16816(acc1, Ah[ks], vb.x, vb.y);
                MMA16816(acc0, Ah[ks], va.z, va.w);
                MMA16816(acc1, Ah[ks], vb.z, vb.w);
            }
            int c0a = (np * 2) * 8 + (l & 3) * 2;
            int c0b = (np * 2 + 1) * 8 + (l & 3) * 2;
            int ra = rt + c0a, rb2 = rt + c0b;
            float na0 = NrS[c0a], na1 = NrS[c0a + 1];
            float nb0 = NrS[c0b], nb1 = NrS[c0b + 1];
            top4_upd(na0 - 2.f * acc0[0], ra, tvA, tiA);
            top4_upd(na1 - 2.f * acc0[1], ra + 1, tvA, tiA);
            top4_upd(na0 - 2.f * acc0[2], ra, tvB, tiB);
            top4_upd(na1 - 2.f * acc0[3], ra + 1, tvB, tiB);
            top4_upd(nb0 - 2.f * acc1[0], rb2, tvA, tiA);
            top4_upd(nb1 - 2.f * acc1[1], rb2 + 1, tvA, tiA);
            top4_upd(nb0 - 2.f * acc1[2], rb2, tvB, tiB);
            top4_upd(nb1 - 2.f * acc1[3], rb2 + 1, tvB, tiB);
        }
        __syncthreads();
    }

    int cA = cb + w * 16 + (l >> 2);
    int cB = cA + 8;
    if (cA < NCC) {
        size_t base = ((size_t)blockIdx.y * NCC + cA) * NCAND + (l & 3) * 4;
#pragma unroll
        for (int k = 0; k < 4; k++) g_ci[base + k] = tiA[k];
    }
    if (cB < NCC) {
        size_t base = ((size_t)blockIdx.y * NCC + cB) * NCAND + (l & 3) * 4;
#pragma unroll
        for (int k = 0; k < 4; k++) g_ci[base + k] = tiB[k];
    }
}

// ---------------- exact fp32 rescore + fused pooling ----------------
__global__ void k_rescore_pool(const float* __restrict__ hc, const float* __restrict__ hr,
                               const float* __restrict__ nr2) {
    int w = (blockIdx.x * blockDim.x + threadIdx.x) >> 5;
    int lane = threadIdx.x & 31;
    if (w >= NCC) return;
    float c0 = hc[(size_t)w * HID + lane];
    float c1 = hc[(size_t)w * HID + lane + 32];
    float c2 = hc[(size_t)w * HID + lane + 64];
    float c3 = hc[(size_t)w * HID + lane + 96];
    float f[3] = {1e30f, 1e30f, 1e30f};
    int   j[3] = {0x7fffffff, 0x7fffffff, 0x7fffffff};
    for (int s = 0; s < RSPLIT; s++) {
        size_t base = ((size_t)s * NCC + w) * NCAND;
        for (int k = 0; k < NCAND; k++) {
            int r = g_ci[base + k];
            if ((unsigned)r >= (unsigned)NRR) continue;
            const float* hrr = &hr[(size_t)r * HID];
            float p = 0.f;
            p = fmaf(c0, hrr[lane], p);
            p = fmaf(c1, hrr[lane + 32], p);
            p = fmaf(c2, hrr[lane + 64], p);
            p = fmaf(c3, hrr[lane + 96], p);
#pragma unroll
            for (int o = 16; o > 0; o >>= 1) p += __shfl_xor_sync(0xffffffffu, p, o);
            if (lane == 0) {
                float key = nr2[r] - 2.f * p;
                top3_upd(key, r, f, j);
            }
        }
    }
#pragma unroll
    for (int k = 0; k < KNN; k++) {
        int nn = __shfl_sync(0xffffffffu, j[k], 0);
        if (lane == 0) {
            g_nn[w * 3 + k] = nn;
            atomicAdd(&g_pcnt[nn], 1);
        }
        atomicAdd(&g_pool[(size_t)nn * HID + lane], c0);
        atomicAdd(&g_pool[(size_t)nn * HID + lane + 32], c1);
        atomicAdd(&g_pool[(size_t)nn * HID + lane + 64], c2);
        atomicAdd(&g_pool[(size_t)nn * HID + lane + 96], c3);
    }
}

// ---------------- decoder ----------------
__global__ void k_dec(const float* __restrict__ hr, const float* __restrict__ Wd,
                      const float* __restrict__ bd, float* __restrict__ out) {
    int w = (blockIdx.x * blockDim.x + threadIdx.x) >> 5;
    int lane = threadIdx.x & 31;
    if (w >= NRR) return;
    float inv = 1.f / fmaxf((float)g_pcnt[w], 1.f);
    float a0 = 0.f, a1 = 0.f, a2 = 0.f;
#pragma unroll
    for (int t = 0; t < 4; t++) {
        int j = lane + 32 * t;
        float hv = hr[(size_t)w * HID + j];
        float pv = g_pool[(size_t)w * HID + j] * inv;
        a0 = fmaf(hv, Wd[j * 3 + 0], a0); a0 = fmaf(pv, Wd[(HID + j) * 3 + 0], a0);
        a1 = fmaf(hv, Wd[j * 3 + 1], a1); a1 = fmaf(pv, Wd[(HID + j) * 3 + 1], a1);
        a2 = fmaf(hv, Wd[j * 3 + 2], a2); a2 = fmaf(pv, Wd[(HID + j) * 3 + 2], a2);
    }
#pragma unroll
    for (int o = 16; o > 0; o >>= 1) {
        a0 += __shfl_xor_sync(0xffffffffu, a0, o);
        a1 += __shfl_xor_sync(0xffffffffu, a1, o);
        a2 += __shfl_xor_sync(0xffffffffu, a2, o);
    }
    if (lane == 0) {
        out[w * 3 + 0] = a0 + bd[0];
        out[w * 3 + 1] = a1 + bd[1];
        out[w * 3 + 2] = a2 + bd[2];
    }
}

// ---------------- host launcher ----------------
extern "C" void kernel_launch(void* const* d_in, const int* in_sizes, int n_in,
                              void* d_out, int out_size) {
    const float* x_r  = (const float*)d_in[0];
    const float* x_c  = (const float*)d_in[1];
    const int*   ei_r = (const int*)d_in[2];
    const int*   ei_c = (const int*)d_in[3];
    const float* W_r1  = (const float*)d_in[5];
    const float* as_r1 = (const float*)d_in[6];
    const float* ad_r1 = (const float*)d_in[7];
    const float* b_r1  = (const float*)d_in[8];
    const float* W_r2  = (const float*)d_in[9];
    const float* as_r2 = (const float*)d_in[10];
    const float* ad_r2 = (const float*)d_in[11];
    const float* b_r2  = (const float*)d_in[12];
    const float* W_c1  = (const float*)d_in[13];
    const float* as_c1 = (const float*)d_in[14];
    const float* ad_c1 = (const float*)d_in[15];
    const float* b_c1  = (const float*)d_in[16];
    const float* W_c2  = (const float*)d_in[17];
    const float* as_c2 = (const float*)d_in[18];
    const float* ad_c2 = (const float*)d_in[19];
    const float* b_c2  = (const float*)d_in[20];
    const float* W_dec = (const float*)d_in[21];
    const float* b_dec = (const float*)d_in[22];
    float* out = (float*)d_out;

    float *hw_r, *h1_r, *h2_r, *hw_c, *h1_c, *h2_c, *nr2;
    cudaGetSymbolAddress((void**)&hw_r, g_hw_r);
    cudaGetSymbolAddress((void**)&h1_r, g_h1_r);
    cudaGetSymbolAddress((void**)&h2_r, g_h2_r);
    cudaGetSymbolAddress((void**)&hw_c, g_hw_c);
    cudaGetSymbolAddress((void**)&h1_c, g_h1_c);
    cudaGetSymbolAddress((void**)&h2_c, g_h2_c);
    cudaGetSymbolAddress((void**)&nr2, g_nr2);

    k_init<<<1024, 256>>>();

    // CSR (branch-merged)
    k_count_both<<<(ERR + ECC + 255) / 256, 256>>>(ei_r + ERR, ei_c + ECC);
    k_scan_both<<<2, 1024>>>();
    k_scatter_both<<<(ERR + ECC + 255) / 256, 256>>>(ei_r, ei_c);
    k_selfloop_both<<<(NRR + NCC + 255) / 256, 256>>>();

    const int WB = WGR + WGC;

    // layer 1 (lin + fused stats/agg)
    k_lin1_both<<<WB, 256>>>(x_r, W_r1, as_r1, ad_r1, x_c, W_c1, as_c1, ad_c1, hw_r, hw_c);
    k_gat1_both<<<WB, 256>>>(hw_r, b_r1, h1_r, hw_c, b_c1, h1_c);
    // layer 2 (gemm + dots + fused stats/agg + knn-prep epilogue)
    k_gemm_both<<<GBR + GBC, 256>>>(h1_r, W_r2, hw_r, h1_c, W_c2, hw_c);
    k_dots_both<<<WB, 256>>>(hw_r, as_r2, ad_r2, hw_c, as_c2, ad_c2);
    k_gat2_both<<<WB, 256>>>(hw_r, b_r2, h2_r, hw_c, b_c2, h2_c);

    // KNN: fp16 2-term HMMA candidates -> exact fp32 rescore + pool
    dim3 kg(CTILES, RSPLIT);
    k_knn_mma<<<kg, 256>>>(nr2);
    k_rescore_pool<<<(NCC * 32 + 255) / 256, 256>>>(h2_c, h2_r, nr2);
    k_dec<<<WGR, 256>>>(h2_r, W_dec, b_dec, out);
}